// round 12
// baseline (speedup 1.0000x reference)
#include <cuda_runtime.h>
#include <cuda_fp16.h>
#include <math.h>
#include <stdint.h>

// Problem constants
#define BN  32768
#define DIM 256
#define NK  32
#define NH  8
#define NFF 1024
#define NDK 32

// ---------------- scratch (device globals: allocation-guard-safe) ----------------
__device__ __align__(128) __half g_lnx[BN * DIM];       // LN1(x_anc), half
__device__ __align__(128) __half g_qh[BN * DIM];        // Q, half
__device__ __align__(128) __half g_qt[BN * NH * DIM];   // q~ [B, H, 256], half
__device__ __align__(128) __half g_ctx[BN * NH * DIM];  // ctx [B, H, 256], half
__device__ __align__(128) __half g_att[BN * DIM];       // attention out (pre-W_o), half
__device__ __align__(128) float  g_x[BN * DIM];         // x = x_anc + att @ W_o
__device__ __align__(128) __half g_h[BN * DIM];         // LN2(x), half
__device__ __align__(128) __half g_ff[BN * NFF];        // gelu(h@ff1+b1), half
// half weights
__device__ __align__(128) __half g_wkh[DIM * DIM];      // Wk as half (same layout)
__device__ __align__(128) __half g_wtq[DIM * DIM];
__device__ __align__(128) __half g_wto[DIM * DIM];
__device__ __align__(128) __half g_wt1[DIM * NFF];
__device__ __align__(128) __half g_wt2[NFF * DIM];

// ---------------- LayerNorm: one warp per row, half output ----------------
__global__ void ln_kernel(const float* __restrict__ x, const float* __restrict__ g,
                          const float* __restrict__ b, __half* __restrict__ out) {
    int row  = blockIdx.x * 8 + threadIdx.y;
    int lane = threadIdx.x;
    const float4* xr = reinterpret_cast<const float4*>(x + (size_t)row * DIM);
    float4 v0 = xr[lane];
    float4 v1 = xr[lane + 32];
    float s  = v0.x + v0.y + v0.z + v0.w + v1.x + v1.y + v1.z + v1.w;
    float ss = v0.x*v0.x + v0.y*v0.y + v0.z*v0.z + v0.w*v0.w
             + v1.x*v1.x + v1.y*v1.y + v1.z*v1.z + v1.w*v1.w;
    #pragma unroll
    for (int o = 16; o; o >>= 1) {
        s  += __shfl_xor_sync(0xFFFFFFFFu, s,  o);
        ss += __shfl_xor_sync(0xFFFFFFFFu, ss, o);
    }
    float mu  = s * (1.0f / 256.0f);
    float var = ss * (1.0f / 256.0f) - mu * mu;
    float rs  = rsqrtf(var + 1e-5f);
    const float4* g4 = reinterpret_cast<const float4*>(g);
    const float4* b4 = reinterpret_cast<const float4*>(b);
    __half* orow = out + (size_t)row * DIM;
    #pragma unroll
    for (int p = 0; p < 2; p++) {
        int idx = lane + p * 32;
        float4 v = (p == 0) ? v0 : v1;
        float4 gg = g4[idx], bb = b4[idx];
        float o0 = (v.x - mu) * rs * gg.x + bb.x;
        float o1 = (v.y - mu) * rs * gg.y + bb.y;
        float o2 = (v.z - mu) * rs * gg.z + bb.z;
        float o3 = (v.w - mu) * rs * gg.w + bb.w;
        __half2 ha = __floats2half2_rn(o0, o1);
        __half2 hb = __floats2half2_rn(o2, o3);
        uint2 u;
        u.x = *reinterpret_cast<uint32_t*>(&ha);
        u.y = *reinterpret_cast<uint32_t*>(&hb);
        *reinterpret_cast<uint2*>(orow + idx * 4) = u;
    }
}

__device__ __forceinline__ float gelu_exact(float v) {
    return 0.5f * v * (1.0f + erff(v * 0.70710678118654752f));
}

// ---------------- weight transpose+convert: out[C][R] = (half)in[R][C] ----------------
__global__ void transpose_kernel(const float* __restrict__ in, __half* __restrict__ out,
                                 int R, int C) {
    __shared__ float t[32][33];
    int c0 = blockIdx.x * 32, r0 = blockIdx.y * 32;
    int tx = threadIdx.x, ty = threadIdx.y;   // (32, 8)
    #pragma unroll
    for (int j = 0; j < 4; j++)
        t[ty + j * 8][tx] = in[(size_t)(r0 + ty + j * 8) * C + c0 + tx];
    __syncthreads();
    #pragma unroll
    for (int j = 0; j < 4; j++)
        out[(size_t)(c0 + ty + j * 8) * R + r0 + tx] = __float2half_rn(t[tx][ty + j * 8]);
}

// ---------------- plain fp32 -> half convert ----------------
__global__ void tohalf_kernel(const float* __restrict__ in, __half* __restrict__ out) {
    int i = (blockIdx.x * 256 + threadIdx.x) * 4;
    float4 v = *reinterpret_cast<const float4*>(in + i);
    __half2 h0 = __floats2half2_rn(v.x, v.y);
    __half2 h1 = __floats2half2_rn(v.z, v.w);
    uint2 u;
    u.x = *reinterpret_cast<uint32_t*>(&h0);
    u.y = *reinterpret_cast<uint32_t*>(&h1);
    *reinterpret_cast<uint2*>(out + i) = u;
}

// ---------------- shared helpers ----------------
__device__ __forceinline__ uint32_t smem_u32(const void* p) {
    uint32_t a;
    asm("{ .reg .u64 t; cvta.to.shared.u64 t, %1; cvt.u32.u64 %0, t; }" : "=r"(a) : "l"(p));
    return a;
}
__device__ __forceinline__ void ldsm_x4(uint32_t r[4], uint32_t addr) {
    asm volatile("ldmatrix.sync.aligned.m8n8.x4.shared.b16 {%0,%1,%2,%3}, [%4];"
                 : "=r"(r[0]), "=r"(r[1]), "=r"(r[2]), "=r"(r[3]) : "r"(addr));
}
__device__ __forceinline__ void ldsm_x4_trans(uint32_t r[4], uint32_t addr) {
    asm volatile("ldmatrix.sync.aligned.m8n8.x4.trans.shared.b16 {%0,%1,%2,%3}, [%4];"
                 : "=r"(r[0]), "=r"(r[1]), "=r"(r[2]), "=r"(r[3]) : "r"(addr));
}
__device__ __forceinline__ void ldsm_x2(uint32_t r[2], uint32_t addr) {
    asm volatile("ldmatrix.sync.aligned.m8n8.x2.shared.b16 {%0,%1}, [%2];"
                 : "=r"(r[0]), "=r"(r[1]) : "r"(addr));
}
__device__ __forceinline__ void mma_f16(float c[4], const uint32_t a[4],
                                        uint32_t b0, uint32_t b1) {
    asm volatile(
        "mma.sync.aligned.m16n8k16.row.col.f32.f16.f16.f32 "
        "{%0,%1,%2,%3}, {%4,%5,%6,%7}, {%8,%9}, {%0,%1,%2,%3};\n"
        : "+f"(c[0]), "+f"(c[1]), "+f"(c[2]), "+f"(c[3])
        : "r"(a[0]), "r"(a[1]), "r"(a[2]), "r"(a[3]), "r"(b0), "r"(b1));
}

// ================= fp16 tensor-core GEMM: 64x128 tile, 8 warps of 32x32 =================
#define HS 40
#define ABUF (64 * HS * 2)    // bytes per A buffer
#define BBUF (128 * HS * 2)   // bytes per B buffer

// MODE 0: C=A@B (f32)  1: gelu(A@B+bias) (half out)  2: A@B+bias+resid (f32)
// MODE 3: A@B+resid (f32)  4: A@B (half out)
template <int MODE>
__global__ __launch_bounds__(256, 3)
void hgemm(const __half* __restrict__ A, const __half* __restrict__ BT,
           void* __restrict__ Cout, int M, int N, int Kd,
           const float* __restrict__ bias, const float* __restrict__ resid) {
    __shared__ __half As[2][64][HS];
    __shared__ __half Bs[2][128][HS];

    const int tid  = threadIdx.x;
    const int lane = tid & 31;
    const int wid  = tid >> 5;
    const int m0 = blockIdx.y * 64;
    const int n0 = blockIdx.x * 128;
    const int warp_m = (wid & 1) * 32;
    const int warp_n = (wid >> 1) * 32;

    // loaders: A 64x32 (1 uint4/thread), B 128x32 (2 uint4/thread)
    const int aRow = tid >> 2;            // 0..63
    const int aCol = (tid & 3) * 8;       // 0,8,16,24
    const int bRow = tid >> 1;            // 0..127
    const int bCol = (tid & 1) * 16;      // 0,16
    const __half* Ag = A  + (size_t)(m0 + aRow) * Kd + aCol;
    const __half* Bg = BT + (size_t)(n0 + bRow) * Kd + bCol;

    float c[2][4][4];
    #pragma unroll
    for (int mt = 0; mt < 2; mt++)
        #pragma unroll
        for (int nt = 0; nt < 4; nt++)
            #pragma unroll
            for (int i = 0; i < 4; i++) c[mt][nt][i] = 0.0f;

    const uint32_t as_base = smem_u32(&As[0][0][0]);
    const uint32_t bs_base = smem_u32(&Bs[0][0][0]);
    const int a_row = warp_m + (lane & 7) + ((lane >> 3) & 1) * 8;
    const int a_k   = (lane >> 4) * 8;
    const int b_row = warp_n + (lane & 7) + ((lane >> 4) & 1) * 8;
    const int b_k   = ((lane >> 3) & 1) * 8;
    const uint32_t aAddr0 = as_base + (uint32_t)(a_row * HS + a_k) * 2;
    const uint32_t bAddr0 = bs_base + (uint32_t)(b_row * HS + b_k) * 2;

    // prologue: chunk 0 -> buf 0
    uint4 av  = *reinterpret_cast<const uint4*>(Ag);
    uint4 bv0 = *reinterpret_cast<const uint4*>(Bg);
    uint4 bv1 = *reinterpret_cast<const uint4*>(Bg + 8);
    *reinterpret_cast<uint4*>(&As[0][aRow][aCol])       = av;
    *reinterpret_cast<uint4*>(&Bs[0][bRow][bCol])       = bv0;
    *reinterpret_cast<uint4*>(&Bs[0][bRow][bCol + 8])   = bv1;
    __syncthreads();

    const int KT = Kd >> 5;
    int buf = 0;
    for (int kt = 0; kt < KT; kt++) {
        if (kt + 1 < KT) {
            const __half* Ap = Ag + (kt + 1) * 32;
            const __half* Bp = Bg + (kt + 1) * 32;
            av  = *reinterpret_cast<const uint4*>(Ap);
            bv0 = *reinterpret_cast<const uint4*>(Bp);
            bv1 = *reinterpret_cast<const uint4*>(Bp + 8);
        }
        const uint32_t aBo = (uint32_t)buf * ABUF;
        const uint32_t bBo = (uint32_t)buf * BBUF;
        #pragma unroll
        for (int ks = 0; ks < 2; ks++) {
            uint32_t af[2][4];
            uint32_t bf[2][4];
            #pragma unroll
            for (int mt = 0; mt < 2; mt++)
                ldsm_x4(af[mt], aAddr0 + aBo + (uint32_t)(mt * 16 * HS + ks * 16) * 2);
            #pragma unroll
            for (int ntp = 0; ntp < 2; ntp++)
                ldsm_x4(bf[ntp], bAddr0 + bBo + (uint32_t)(ntp * 16 * HS + ks * 16) * 2);
            #pragma unroll
            for (int mt = 0; mt < 2; mt++) {
                #pragma unroll
                for (int nt = 0; nt < 4; nt++) {
                    uint32_t b0 = (nt & 1) ? bf[nt >> 1][2] : bf[nt >> 1][0];
                    uint32_t b1 = (nt & 1) ? bf[nt >> 1][3] : bf[nt >> 1][1];
                    mma_f16(c[mt][nt], af[mt], b0, b1);
                }
            }
        }
        if (kt + 1 < KT) {
            buf ^= 1;
            *reinterpret_cast<uint4*>(&As[buf][aRow][aCol])     = av;
            *reinterpret_cast<uint4*>(&Bs[buf][bRow][bCol])     = bv0;
            *reinterpret_cast<uint4*>(&Bs[buf][bRow][bCol + 8]) = bv1;
        }
        __syncthreads();
    }

    const int fr = lane >> 2;
    const int fc = lane & 3;
    #pragma unroll
    for (int mt = 0; mt < 2; mt++) {
        #pragma unroll
        for (int nt = 0; nt < 4; nt++) {
            int row0 = m0 + warp_m + mt * 16 + fr;
            int col  = n0 + warp_n + nt * 8 + fc * 2;
            float v0 = c[mt][nt][0], v1 = c[mt][nt][1];
            float v2 = c[mt][nt][2], v3 = c[mt][nt][3];
            if (MODE == 1 || MODE == 2) {
                float2 bv = *reinterpret_cast<const float2*>(bias + col);
                v0 += bv.x; v1 += bv.y; v2 += bv.x; v3 += bv.y;
            }
            if (MODE == 1) {
                v0 = gelu_exact(v0); v1 = gelu_exact(v1);
                v2 = gelu_exact(v2); v3 = gelu_exact(v3);
            }
            if (MODE == 2 || MODE == 3) {
                float2 r0 = *reinterpret_cast<const float2*>(resid + (size_t)row0 * N + col);
                float2 r1 = *reinterpret_cast<const float2*>(resid + (size_t)(row0 + 8) * N + col);
                v0 += r0.x; v1 += r0.y; v2 += r1.x; v3 += r1.y;
            }
            if (MODE == 1 || MODE == 4) {
                __half* Ch = reinterpret_cast<__half*>(Cout);
                __half2 h0 = __floats2half2_rn(v0, v1);
                __half2 h1 = __floats2half2_rn(v2, v3);
                *reinterpret_cast<__half2*>(Ch + (size_t)row0 * N + col)       = h0;
                *reinterpret_cast<__half2*>(Ch + (size_t)(row0 + 8) * N + col) = h1;
            } else {
                float* Cf = reinterpret_cast<float*>(Cout);
                *reinterpret_cast<float2*>(Cf + (size_t)row0 * N + col)       = make_float2(v0, v1);
                *reinterpret_cast<float2*>(Cf + (size_t)(row0 + 8) * N + col) = make_float2(v2, v3);
            }
        }
    }
}

// ---------------- qtilde via tensor cores (R11) ----------------
__global__ __launch_bounds__(256)
void qtilde_tc(const __half* __restrict__ Q, const __half* __restrict__ Wkh,
               __half* __restrict__ qt) {
    __shared__ __half As[128][HS];
    __shared__ __half Bs[128][HS];

    const int tid  = threadIdx.x;
    const int lane = tid & 31;
    const int wid  = tid >> 5;
    const int m0   = blockIdx.x * 128;
    const int head = blockIdx.y >> 1;
    const int n0   = (blockIdx.y & 1) * 128;
    const int warp_m = (wid & 1) * 64;
    const int warp_n = (wid >> 1) * 32;

    const int ldRow = tid >> 1;
    const int ldCol = (tid & 1) * 16;
    {
        const __half* Ag = Q   + (size_t)(m0 + ldRow) * 256 + head * 32 + ldCol;
        const __half* Bg = Wkh + (size_t)(n0 + ldRow) * 256 + head * 32 + ldCol;
        *reinterpret_cast<uint4*>(&As[ldRow][ldCol])     = *reinterpret_cast<const uint4*>(Ag);
        *reinterpret_cast<uint4*>(&As[ldRow][ldCol + 8]) = *reinterpret_cast<const uint4*>(Ag + 8);
        *reinterpret_cast<uint4*>(&Bs[ldRow][ldCol])     = *reinterpret_cast<const uint4*>(Bg);
        *reinterpret_cast<uint4*>(&Bs[ldRow][ldCol + 8]) = *reinterpret_cast<const uint4*>(Bg + 8);
    }
    __syncthreads();

    float c[4][4][4];
    #pragma unroll
    for (int mt = 0; mt < 4; mt++)
        #pragma unroll
        for (int nt = 0; nt < 4; nt++)
            #pragma unroll
            for (int i = 0; i < 4; i++) c[mt][nt][i] = 0.0f;

    const uint32_t as_base = smem_u32(&As[0][0]);
    const uint32_t bs_base = smem_u32(&Bs[0][0]);
    const int a_row = warp_m + (lane & 7) + ((lane >> 3) & 1) * 8;
    const int a_k   = (lane >> 4) * 8;
    const int b_row = warp_n + (lane & 7) + ((lane >> 4) & 1) * 8;
    const int b_k   = ((lane >> 3) & 1) * 8;
    const uint32_t aAddr0 = as_base + (uint32_t)(a_row * HS + a_k) * 2;
    const uint32_t bAddr0 = bs_base + (uint32_t)(b_row * HS + b_k) * 2;

    #pragma unroll
    for (int ks = 0; ks < 2; ks++) {
        uint32_t af[4][4];
        uint32_t bf[2][4];
        #pragma unroll
        for (int mt = 0; mt < 4; mt++)
            ldsm_x4(af[mt], aAddr0 + (uint32_t)(mt * 16 * HS + ks * 16) * 2);
        #pragma unroll
        for (int ntp = 0; ntp < 2; ntp++)
            ldsm_x4(bf[ntp], bAddr0 + (uint32_t)(ntp * 16 * HS + ks * 16) * 2);
        #pragma unroll
        for (int mt = 0; mt < 4; mt++) {
            #pragma unroll
            for (int nt = 0; nt < 4; nt++) {
                uint32_t b0 = (nt & 1) ? bf[nt >> 1][2] : bf[nt >> 1][0];
                uint32_t b1 = (nt & 1) ? bf[nt >> 1][3] : bf[nt >> 1][1];
                mma_f16(c[mt][nt], af[mt], b0, b1);
            }
        }
    }

    const int fr = lane >> 2;
    const int fc = lane & 3;
    #pragma unroll
    for (int mt = 0; mt < 4; mt++) {
        #pragma unroll
        for (int nt = 0; nt < 4; nt++) {
            int row0 = m0 + warp_m + mt * 16 + fr;
            int col  = head * 256 + n0 + warp_n + nt * 8 + fc * 2;
            __half2 h0 = __floats2half2_rn(c[mt][nt][0], c[mt][nt][1]);
            __half2 h1 = __floats2half2_rn(c[mt][nt][2], c[mt][nt][3]);
            *reinterpret_cast<__half2*>(qt + (size_t)row0 * 2048 + col)       = h0;
            *reinterpret_cast<__half2*>(qt + (size_t)(row0 + 8) * 2048 + col) = h1;
        }
    }
}

// ---------------- attention core v6 (R10): tensor-core phases ----------------
#define XS_S 264
#define QS_S 264
#define AT_S 40
#define CT_S 264
__global__ __launch_bounds__(256)
void attn_kernel(const float* __restrict__ xnei, const __half* __restrict__ qt,
                 __half* __restrict__ ctx) {
    __shared__ __half xs[32 * XS_S];
    __shared__ __half qts[8 * QS_S];
    __shared__ float  sred[8 * 256];
    __shared__ __half attns_h[8 * AT_S];
    __shared__ __half ctx_t[8 * CT_S];
    int b    = blockIdx.x;
    int tid  = threadIdx.x;
    int lane = tid & 31;
    int w    = tid >> 5;

    const float4* xb4 = reinterpret_cast<const float4*>(xnei + (size_t)b * 8192);
    #pragma unroll
    for (int j = 0; j < 8; j++) {
        int i  = tid + j * 256;
        int k  = i >> 6;
        int c4 = i & 63;
        float4 v = xb4[i];
        __half2 h0 = __floats2half2_rn(v.x, v.y);
        __half2 h1 = __floats2half2_rn(v.z, v.w);
        uint2 u;
        u.x = *reinterpret_cast<uint32_t*>(&h0);
        u.y = *reinterpret_cast<uint32_t*>(&h1);
        *reinterpret_cast<uint2*>(xs + k * XS_S + c4 * 4) = u;
    }
    {
        const uint4* qp = reinterpret_cast<const uint4*>(qt + (size_t)b * 2048);
        int h  = tid >> 5;
        int c8 = tid & 31;
        *reinterpret_cast<uint4*>(qts + h * QS_S + c8 * 8) = qp[tid];
    }
    __syncthreads();

    const uint32_t xs_base = smem_u32(xs);
    const uint32_t qs_base = smem_u32(qts);
    const uint32_t at_base = smem_u32(attns_h);
    const int fr = lane >> 2;
    const int fc = lane & 3;

    {
        float sacc[2][4];
        #pragma unroll
        for (int mt = 0; mt < 2; mt++)
            #pragma unroll
            for (int i = 0; i < 4; i++) sacc[mt][i] = 0.0f;
        const int a_row = (lane & 7) + ((lane >> 3) & 1) * 8;
        const int a_kof = (lane >> 4) * 8;
        const int b_row = lane & 7;
        const int b_kof = ((lane >> 3) & 1) * 8;
        #pragma unroll
        for (int ks = 0; ks < 2; ks++) {
            uint32_t bq[2];
            ldsm_x2(bq, qs_base + (uint32_t)(b_row * QS_S + w * 32 + ks * 16 + b_kof) * 2);
            #pragma unroll
            for (int mt = 0; mt < 2; mt++) {
                uint32_t af[4];
                ldsm_x4(af, xs_base + (uint32_t)((mt * 16 + a_row) * XS_S + w * 32 + ks * 16 + a_kof) * 2);
                mma_f16(sacc[mt], af, bq[0], bq[1]);
            }
        }
        #pragma unroll
        for (int mt = 0; mt < 2; mt++) {
            int krow = mt * 16 + fr;
            *reinterpret_cast<float2*>(&sred[w * 256 + krow * 8 + fc * 2]) =
                make_float2(sacc[mt][0], sacc[mt][1]);
            *reinterpret_cast<float2*>(&sred[w * 256 + (krow + 8) * 8 + fc * 2]) =
                make_float2(sacc[mt][2], sacc[mt][3]);
        }
    }
    __syncthreads();

    {
        float sc = 0.0f;
        #pragma unroll
        for (int ww = 0; ww < 8; ww++)
            sc += sred[ww * 256 + lane * 8 + w];
        sc *= 0.17677669529663687f;
        float m = sc;
        #pragma unroll
        for (int o = 16; o; o >>= 1) m = fmaxf(m, __shfl_xor_sync(0xFFFFFFFFu, m, o));
        float e = expf(sc - m);
        float s = e;
        #pragma unroll
        for (int o = 16; o; o >>= 1) s += __shfl_xor_sync(0xFFFFFFFFu, s, o);
        attns_h[w * AT_S + lane] = __float2half_rn(e / s);
    }
    __syncthreads();

    {
        float cacc[2][4];
        #pragma unroll
        for (int mt = 0; mt < 2; mt++)
            #pragma unroll
            for (int i = 0; i < 4; i++) cacc[mt][i] = 0.0f;
        const int t_krow = ((lane >> 4) & 1) * 8 + (lane & 7);
        const int t_dof  = ((lane >> 3) & 1) * 8;
        const int b_row = lane & 7;
        const int b_kof = ((lane >> 3) & 1) * 8;
        #pragma unroll
        for (int ks = 0; ks < 2; ks++) {
            uint32_t bp[2];
            ldsm_x2(bp, at_base + (uint32_t)(b_row * AT_S + ks * 16 + b_kof) * 2);
            #pragma unroll
            for (int mt = 0; mt < 2; mt++) {
                int d0 = w * 32 + mt * 16;
                uint32_t af[4];
                ldsm_x4_trans(af, xs_base + (uint32_t)((ks * 16 + t_krow) * XS_S + d0 + t_dof) * 2);
                mma_f16(cacc[mt], af, bp[0], bp[1]);
            }
        }
        #pragma unroll
        for (int mt = 0; mt < 2; mt++) {
            int d0 = w * 32 + mt * 16;
            ctx_t[(fc * 2 + 0) * CT_S + d0 + fr]     = __float2half_rn(cacc[mt][0]);
            ctx_t[(fc * 2 + 1) * CT_S + d0 + fr]     = __float2half_rn(cacc[mt][1]);
            ctx_t[(fc * 2 + 0) * CT_S + d0 + fr + 8] = __float2half_rn(cacc[mt][2]);
            ctx_t[(fc * 2 + 1) * CT_S + d0 + fr + 8] = __float2half_rn(cacc[mt][3]);
        }
    }
    __syncthreads();

    {
        uint4 u = *reinterpret_cast<const uint4*>(&ctx_t[w * CT_S + lane * 8]);
        *reinterpret_cast<uint4*>(&ctx[(size_t)b * 2048 + w * 256 + lane * 8]) = u;
    }
}

// ---------------- out[b, h*32+j] = sum_d ctx[b,h,d] * W_v[d, h*32+j] (half in/out) ----------------
#define VPROJ_SMEM (16384 * 4)
__global__ void vproj_kernel(const __half* __restrict__ ctx, const float* __restrict__ Wv,
                             __half* __restrict__ out) {
    extern __shared__ float vsm[];
    float* Wvs = vsm;          // [256][32]
    float* cs  = vsm + 8192;   // [32][256]
    int h  = blockIdx.y;
    int b0 = blockIdx.x * 32;
    int tid = threadIdx.x;
    for (int i = tid * 4; i < 8192; i += 1024) {
        int d = i >> 5, j = i & 31;
        *reinterpret_cast<float4*>(&Wvs[i]) =
            *reinterpret_cast<const float4*>(&Wv[d * 256 + h * 32 + j]);
    }
    for (int i = tid * 8; i < 8192; i += 2048) {
        int r = i >> 8, d2 = i & 255;
        uint4 u = *reinterpret_cast<const uint4*>(&ctx[(size_t)(b0 + r) * 2048 + h * 256 + d2]);
        float2 f0 = __half22float2(*reinterpret_cast<__half2*>(&u.x));
        float2 f1 = __half22float2(*reinterpret_cast<__half2*>(&u.y));
        float2 f2 = __half22float2(*reinterpret_cast<__half2*>(&u.z));
        float2 f3 = __half22float2(*reinterpret_cast<__half2*>(&u.w));
        *reinterpret_cast<float4*>(&cs[i])     = make_float4(f0.x, f0.y, f1.x, f1.y);
        *reinterpret_cast<float4*>(&cs[i + 4]) = make_float4(f2.x, f2.y, f3.x, f3.y);
    }
    __syncthreads();
    int j  = tid & 31;
    int rg = tid >> 5;
    float acc0 = 0.0f, acc1 = 0.0f, acc2 = 0.0f, acc3 = 0.0f;
    #pragma unroll 4
    for (int d4 = 0; d4 < 64; d4++) {
        float w0 = Wvs[(d4 * 4 + 0) * 32 + j];
        float w1 = Wvs[(d4 * 4 + 1) * 32 + j];
        float w2 = Wvs[(d4 * 4 + 2) * 32 + j];
        float w3 = Wvs[(d4 * 4 + 3) * 32 + j];
        float4 c0 = *reinterpret_cast<const float4*>(&cs[(rg +  0) * 256 + d4 * 4]);
        float4 c1 = *reinterpret_cast<const float4*>(&cs[(rg +  8) * 256 + d4 * 4]);
        float4 c2 = *reinterpret_cast<const float4*>(&cs[(rg + 16) * 256 + d4 * 4]);
        float4 c3 = *reinterpret_cast<const float4*>(&cs[(rg + 24) * 256 + d4 * 4]);
        acc0 += c0.x * w0 + c0.y * w1 + c0.z * w2 + c0.w * w3;
        acc1 += c1.x * w0 + c1.y * w1 + c1.z * w2 + c1.w * w3;
        acc2 += c2.x * w0 + c2.y * w1 + c2.z * w2 + c2.w * w3;
        acc3 += c3.x * w0 + c3.y * w1 + c3.z * w2 + c3.w * w3;
    }
    out[(size_t)(b0 + rg +  0) * 256 + h * 32 + j] = __float2half_rn(acc0);
    out[(size_t)(b0 + rg +  8) * 256 + h * 32 + j] = __float2half_rn(acc1);
    out[(size_t)(b0 + rg + 16) * 256 + h * 32 + j] = __float2half_rn(acc2);
    out[(size_t)(b0 + rg + 24) * 256 + h * 32 + j] = __float2half_rn(acc3);
}

// ---------------- launcher ----------------
extern "C" void kernel_launch(void* const* d_in, const int* in_sizes, int n_in,
                              void* d_out, int out_size) {
    const float* x_anc = (const float*)d_in[0];
    const float* x_nei = (const float*)d_in[1];
    const float* W_q   = (const float*)d_in[2];
    const float* W_k   = (const float*)d_in[3];
    const float* W_v   = (const float*)d_in[4];
    const float* W_o   = (const float*)d_in[5];
    const float* ln1_g = (const float*)d_in[6];
    const float* ln1_b = (const float*)d_in[7];
    const float* ln2_g = (const float*)d_in[8];
    const float* ln2_b = (const float*)d_in[9];
    const float* ff1_w = (const float*)d_in[10];
    const float* ff1_b = (const float*)d_in[11];
    const float* ff2_w = (const float*)d_in[12];
    const float* ff2_b = (const float*)d_in[13];
    float* out = (float*)d_out;

    __half *p_lnx, *p_qh, *p_qt, *p_ctx, *p_att, *p_h, *p_ff;
    __half *p_wkh, *p_wtq, *p_wto, *p_wt1, *p_wt2;
    float *p_x;
    cudaGetSymbolAddress((void**)&p_lnx, g_lnx);
    cudaGetSymbolAddress((void**)&p_qh,  g_qh);
    cudaGetSymbolAddress((void**)&p_qt,  g_qt);
    cudaGetSymbolAddress((void**)&p_ctx, g_ctx);
    cudaGetSymbolAddress((void**)&p_att, g_att);
    cudaGetSymbolAddress((void**)&p_x,   g_x);
    cudaGetSymbolAddress((void**)&p_h,   g_h);
    cudaGetSymbolAddress((void**)&p_ff,  g_ff);
    cudaGetSymbolAddress((void**)&p_wkh, g_wkh);
    cudaGetSymbolAddress((void**)&p_wtq, g_wtq);
    cudaGetSymbolAddress((void**)&p_wto, g_wto);
    cudaGetSymbolAddress((void**)&p_wt1, g_wt1);
    cudaGetSymbolAddress((void**)&p_wt2, g_wt2);

    cudaFuncSetAttribute(vproj_kernel, cudaFuncAttributeMaxDynamicSharedMemorySize, VPROJ_SMEM);

    dim3 lnBlock(32, 8);
    dim3 tBlock(32, 8);

    // 0: Wk -> half
    tohalf_kernel<<<64, 256>>>(W_k, p_wkh);
    // 1: transpose W_q
    transpose_kernel<<<dim3(8, 8),  tBlock>>>(W_q,   p_wtq, 256, 256);
    // 2: LN1 -> half
    ln_kernel<<<BN / 8, lnBlock>>>(x_anc, ln1_g, ln1_b, p_lnx);
    // 3: Q = LN1 @ W_q (half out)  [PROFILED SLOT]
    hgemm<4><<<dim3(2, BN / 64), 256>>>(p_lnx, p_wtq, p_qh, BN, DIM, DIM, nullptr, nullptr);
    // 4: q~ via tensor cores
    qtilde_tc<<<dim3(BN / 128, 16), 256>>>(p_qh, p_wkh, p_qt);
    // 5: attention core -> ctx (half)
    attn_kernel<<<BN, 256>>>(x_nei, p_qt, p_ctx);
    // 6: transpose W_o
    transpose_kernel<<<dim3(8, 8),  tBlock>>>(W_o,   p_wto, 256, 256);
    // 7: att = ctx @ W_v
    vproj_kernel<<<dim3(BN / 32, NH), 256, VPROJ_SMEM>>>(p_ctx, W_v, p_att);
    // 8: x = x_anc + att @ W_o
    hgemm<3><<<dim3(2, BN / 64), 256>>>(p_att, p_wto, p_x, BN, DIM, DIM, nullptr, x_anc);
    // 9: LN2 -> half
    ln_kernel<<<BN / 8, lnBlock>>>(p_x, ln2_g, ln2_b, p_h);
    // 10: transpose ff1
    transpose_kernel<<<dim3(32, 8), tBlock>>>(ff1_w, p_wt1, 256, 1024);
    // 11: ff = gelu(h @ ff1 + b1)
    hgemm<1><<<dim3(8, BN / 64), 256>>>(p_h, p_wt1, p_ff, BN, NFF, DIM, ff1_b, nullptr);
    // 12: transpose ff2
    transpose_kernel<<<dim3(8, 32), tBlock>>>(ff2_w, p_wt2, 1024, 256);
    // 13: out = x + ff @ ff2 + b2
    hgemm<2><<<dim3(2, BN / 64), 256>>>(p_ff, p_wt2, out, BN, DIM, NFF, ff2_b, p_x);
}

// round 13
// speedup vs baseline: 1.0635x; 1.0635x over previous
#include <cuda_runtime.h>
#include <cuda_fp16.h>
#include <math.h>
#include <stdint.h>

// Problem constants
#define BN  32768
#define DIM 256
#define NK  32
#define NH  8
#define NFF 1024
#define NDK 32

// ---------------- scratch (device globals: allocation-guard-safe) ----------------
__device__ __align__(128) __half g_lnx[BN * DIM];       // LN1(x_anc), half
__device__ __align__(128) __half g_qh[BN * DIM];        // Q, half
__device__ __align__(128) __half g_qt[BN * NH * DIM];   // q~ [B, H, 256], half
__device__ __align__(128) __half g_ctx[BN * NH * DIM];  // ctx [B, H, 256], half
__device__ __align__(128) __half g_att[BN * DIM];       // attention out (pre-W_o), half
__device__ __align__(128) float  g_x[BN * DIM];         // x = x_anc + att @ W_o
__device__ __align__(128) __half g_h[BN * DIM];         // LN2(x), half
__device__ __align__(128) __half g_ff[BN * NFF];        // gelu(h@ff1+b1), half
// half weights
__device__ __align__(128) __half g_wkh[DIM * DIM];      // Wk as half (same layout)
__device__ __align__(128) __half g_wtq[DIM * DIM];
__device__ __align__(128) __half g_wto[DIM * DIM];
__device__ __align__(128) __half g_wt1[DIM * NFF];
__device__ __align__(128) __half g_wt2[NFF * DIM];

// ---------------- LayerNorm: one warp per row, half output ----------------
__global__ void ln_kernel(const float* __restrict__ x, const float* __restrict__ g,
                          const float* __restrict__ b, __half* __restrict__ out) {
    int row  = blockIdx.x * 8 + threadIdx.y;
    int lane = threadIdx.x;
    const float4* xr = reinterpret_cast<const float4*>(x + (size_t)row * DIM);
    float4 v0 = xr[lane];
    float4 v1 = xr[lane + 32];
    float s  = v0.x + v0.y + v0.z + v0.w + v1.x + v1.y + v1.z + v1.w;
    float ss = v0.x*v0.x + v0.y*v0.y + v0.z*v0.z + v0.w*v0.w
             + v1.x*v1.x + v1.y*v1.y + v1.z*v1.z + v1.w*v1.w;
    #pragma unroll
    for (int o = 16; o; o >>= 1) {
        s  += __shfl_xor_sync(0xFFFFFFFFu, s,  o);
        ss += __shfl_xor_sync(0xFFFFFFFFu, ss, o);
    }
    float mu  = s * (1.0f / 256.0f);
    float var = ss * (1.0f / 256.0f) - mu * mu;
    float rs  = rsqrtf(var + 1e-5f);
    const float4* g4 = reinterpret_cast<const float4*>(g);
    const float4* b4 = reinterpret_cast<const float4*>(b);
    __half* orow = out + (size_t)row * DIM;
    #pragma unroll
    for (int p = 0; p < 2; p++) {
        int idx = lane + p * 32;
        float4 v = (p == 0) ? v0 : v1;
        float4 gg = g4[idx], bb = b4[idx];
        float o0 = (v.x - mu) * rs * gg.x + bb.x;
        float o1 = (v.y - mu) * rs * gg.y + bb.y;
        float o2 = (v.z - mu) * rs * gg.z + bb.z;
        float o3 = (v.w - mu) * rs * gg.w + bb.w;
        __half2 ha = __floats2half2_rn(o0, o1);
        __half2 hb = __floats2half2_rn(o2, o3);
        uint2 u;
        u.x = *reinterpret_cast<uint32_t*>(&ha);
        u.y = *reinterpret_cast<uint32_t*>(&hb);
        *reinterpret_cast<uint2*>(orow + idx * 4) = u;
    }
}

__device__ __forceinline__ float gelu_exact(float v) {
    return 0.5f * v * (1.0f + erff(v * 0.70710678118654752f));
}

// ---------------- weight transpose+convert: out[C][R] = (half)in[R][C] ----------------
__global__ void transpose_kernel(const float* __restrict__ in, __half* __restrict__ out,
                                 int R, int C) {
    __shared__ float t[32][33];
    int c0 = blockIdx.x * 32, r0 = blockIdx.y * 32;
    int tx = threadIdx.x, ty = threadIdx.y;   // (32, 8)
    #pragma unroll
    for (int j = 0; j < 4; j++)
        t[ty + j * 8][tx] = in[(size_t)(r0 + ty + j * 8) * C + c0 + tx];
    __syncthreads();
    #pragma unroll
    for (int j = 0; j < 4; j++)
        out[(size_t)(c0 + ty + j * 8) * R + r0 + tx] = __float2half_rn(t[tx][ty + j * 8]);
}

// ---------------- plain fp32 -> half convert ----------------
__global__ void tohalf_kernel(const float* __restrict__ in, __half* __restrict__ out) {
    int i = (blockIdx.x * 256 + threadIdx.x) * 4;
    float4 v = *reinterpret_cast<const float4*>(in + i);
    __half2 h0 = __floats2half2_rn(v.x, v.y);
    __half2 h1 = __floats2half2_rn(v.z, v.w);
    uint2 u;
    u.x = *reinterpret_cast<uint32_t*>(&h0);
    u.y = *reinterpret_cast<uint32_t*>(&h1);
    *reinterpret_cast<uint2*>(out + i) = u;
}

// ---------------- shared helpers ----------------
__device__ __forceinline__ uint32_t smem_u32(const void* p) {
    uint32_t a;
    asm("{ .reg .u64 t; cvta.to.shared.u64 t, %1; cvt.u32.u64 %0, t; }" : "=r"(a) : "l"(p));
    return a;
}
__device__ __forceinline__ void ldsm_x4(uint32_t r[4], uint32_t addr) {
    asm volatile("ldmatrix.sync.aligned.m8n8.x4.shared.b16 {%0,%1,%2,%3}, [%4];"
                 : "=r"(r[0]), "=r"(r[1]), "=r"(r[2]), "=r"(r[3]) : "r"(addr));
}
__device__ __forceinline__ void ldsm_x4_trans(uint32_t r[4], uint32_t addr) {
    asm volatile("ldmatrix.sync.aligned.m8n8.x4.trans.shared.b16 {%0,%1,%2,%3}, [%4];"
                 : "=r"(r[0]), "=r"(r[1]), "=r"(r[2]), "=r"(r[3]) : "r"(addr));
}
__device__ __forceinline__ void ldsm_x2(uint32_t r[2], uint32_t addr) {
    asm volatile("ldmatrix.sync.aligned.m8n8.x2.shared.b16 {%0,%1}, [%2];"
                 : "=r"(r[0]), "=r"(r[1]) : "r"(addr));
}
__device__ __forceinline__ void mma_f16(float c[4], const uint32_t a[4],
                                        uint32_t b0, uint32_t b1) {
    asm volatile(
        "mma.sync.aligned.m16n8k16.row.col.f32.f16.f16.f32 "
        "{%0,%1,%2,%3}, {%4,%5,%6,%7}, {%8,%9}, {%0,%1,%2,%3};\n"
        : "+f"(c[0]), "+f"(c[1]), "+f"(c[2]), "+f"(c[3])
        : "r"(a[0]), "r"(a[1]), "r"(a[2]), "r"(a[3]), "r"(b0), "r"(b1));
}
__device__ __forceinline__ void cp_async16(uint32_t dst, const void* src) {
    asm volatile("cp.async.cg.shared.global [%0], [%1], 16;\n" :: "r"(dst), "l"(src));
}
__device__ __forceinline__ void cp_commit() {
    asm volatile("cp.async.commit_group;\n" ::: "memory");
}
template <int N>
__device__ __forceinline__ void cp_wait() {
    asm volatile("cp.async.wait_group %0;\n" :: "n"(N) : "memory");
}

// ================= fp16 tensor-core GEMM: 128x128, 3-stage cp.async pipeline =================
#define HS 40
#define STAGE_BYTES (128 * HS * 2)          // one A or B buffer: 10240 B
#define HGEMM_SMEM (6 * STAGE_BYTES)        // 3 stages x (A + B) = 61440 B

// MODE 0: C=A@B (f32)  1: gelu(A@B+bias) (half out)  2: A@B+bias+resid (f32)
// MODE 3: A@B+resid (f32)  4: A@B (half out)
template <int MODE>
__global__ __launch_bounds__(256, 2)
void hgemm(const __half* __restrict__ A, const __half* __restrict__ BT,
           void* __restrict__ Cout, int M, int N, int Kd,
           const float* __restrict__ bias, const float* __restrict__ resid) {
    extern __shared__ __half hsm[];
    // layout: [stage][A(128x40) then B(128x40)]
    const uint32_t sm_base = smem_u32(hsm);

    const int tid  = threadIdx.x;
    const int lane = tid & 31;
    const int wid  = tid >> 5;
    const int m0 = blockIdx.y * 128;
    const int n0 = blockIdx.x * 128;
    const int warp_m = (wid & 1) * 64;
    const int warp_n = (wid >> 1) * 32;

    // tile loaders: thread -> row tid>>1, half-col (tid&1)*16 (2 x cp.async16 per array)
    const int ldRow = tid >> 1;
    const int ldCol = (tid & 1) * 16;
    const __half* Ag = A  + (size_t)(m0 + ldRow) * Kd + ldCol;
    const __half* Bg = BT + (size_t)(n0 + ldRow) * Kd + ldCol;
    const uint32_t ldOffA = (uint32_t)(ldRow * HS + ldCol) * 2;
    const uint32_t ldOffB = ldOffA + STAGE_BYTES;

    float c[4][4][4];
    #pragma unroll
    for (int mt = 0; mt < 4; mt++)
        #pragma unroll
        for (int nt = 0; nt < 4; nt++)
            #pragma unroll
            for (int i = 0; i < 4; i++) c[mt][nt][i] = 0.0f;

    const int a_row = warp_m + (lane & 7) + ((lane >> 3) & 1) * 8;
    const int a_k   = (lane >> 4) * 8;
    const int b_row = warp_n + (lane & 7) + ((lane >> 4) & 1) * 8;
    const int b_k   = ((lane >> 3) & 1) * 8;
    const uint32_t aAddr0 = sm_base + (uint32_t)(a_row * HS + a_k) * 2;
    const uint32_t bAddr0 = sm_base + STAGE_BYTES + (uint32_t)(b_row * HS + b_k) * 2;

    const int KT = Kd >> 5;   // k32 chunks

    // prologue: async-load chunks 0 and 1
    #pragma unroll
    for (int p = 0; p < 2; p++) {
        uint32_t sbase = (uint32_t)p * (2 * STAGE_BYTES);
        const __half* Ap = Ag + p * 32;
        const __half* Bp = Bg + p * 32;
        cp_async16(sm_base + sbase + ldOffA,      Ap);
        cp_async16(sm_base + sbase + ldOffA + 16, Ap + 8);
        cp_async16(sm_base + sbase + ldOffB,      Bp);
        cp_async16(sm_base + sbase + ldOffB + 16, Bp + 8);
        cp_commit();
    }

    for (int kt = 0; kt < KT; kt++) {
        // wait until chunk kt has landed
        if (kt + 1 < KT) cp_wait<1>(); else cp_wait<0>();
        __syncthreads();   // data visible to all; prior compute done before buffer reuse

        // issue chunk kt+2 into stage (kt+2)%3
        if (kt + 2 < KT) {
            uint32_t sbase = (uint32_t)((kt + 2) % 3) * (2 * STAGE_BYTES);
            const __half* Ap = Ag + (kt + 2) * 32;
            const __half* Bp = Bg + (kt + 2) * 32;
            cp_async16(sm_base + sbase + ldOffA,      Ap);
            cp_async16(sm_base + sbase + ldOffA + 16, Ap + 8);
            cp_async16(sm_base + sbase + ldOffB,      Bp);
            cp_async16(sm_base + sbase + ldOffB + 16, Bp + 8);
            cp_commit();
        }

        // compute chunk kt from stage kt%3
        const uint32_t bo = (uint32_t)(kt % 3) * (2 * STAGE_BYTES);
        #pragma unroll
        for (int ks = 0; ks < 2; ks++) {
            uint32_t af[4][4];
            uint32_t bf[2][4];
            #pragma unroll
            for (int mt = 0; mt < 4; mt++)
                ldsm_x4(af[mt], aAddr0 + bo + (uint32_t)(mt * 16 * HS + ks * 16) * 2);
            #pragma unroll
            for (int ntp = 0; ntp < 2; ntp++)
                ldsm_x4(bf[ntp], bAddr0 + bo + (uint32_t)(ntp * 16 * HS + ks * 16) * 2);
            #pragma unroll
            for (int mt = 0; mt < 4; mt++) {
                #pragma unroll
                for (int nt = 0; nt < 4; nt++) {
                    uint32_t b0 = (nt & 1) ? bf[nt >> 1][2] : bf[nt >> 1][0];
                    uint32_t b1 = (nt & 1) ? bf[nt >> 1][3] : bf[nt >> 1][1];
                    mma_f16(c[mt][nt], af[mt], b0, b1);
                }
            }
        }
        __syncthreads();   // all reads of stage kt%3 done before it is rewritten (distance 3)
    }

    const int fr = lane >> 2;
    const int fc = lane & 3;
    #pragma unroll
    for (int mt = 0; mt < 4; mt++) {
        #pragma unroll
        for (int nt = 0; nt < 4; nt++) {
            int row0 = m0 + warp_m + mt * 16 + fr;
            int col  = n0 + warp_n + nt * 8 + fc * 2;
            float v0 = c[mt][nt][0], v1 = c[mt][nt][1];
            float v2 = c[mt][nt][2], v3 = c[mt][nt][3];
            if (MODE == 1 || MODE == 2) {
                float2 bv = *reinterpret_cast<const float2*>(bias + col);
                v0 += bv.x; v1 += bv.y; v2 += bv.x; v3 += bv.y;
            }
            if (MODE == 1) {
                v0 = gelu_exact(v0); v1 = gelu_exact(v1);
                v2 = gelu_exact(v2); v3 = gelu_exact(v3);
            }
            if (MODE == 2 || MODE == 3) {
                float2 r0 = *reinterpret_cast<const float2*>(resid + (size_t)row0 * N + col);
                float2 r1 = *reinterpret_cast<const float2*>(resid + (size_t)(row0 + 8) * N + col);
                v0 += r0.x; v1 += r0.y; v2 += r1.x; v3 += r1.y;
            }
            if (MODE == 1 || MODE == 4) {
                __half* Ch = reinterpret_cast<__half*>(Cout);
                __half2 h0 = __floats2half2_rn(v0, v1);
                __half2 h1 = __floats2half2_rn(v2, v3);
                *reinterpret_cast<__half2*>(Ch + (size_t)row0 * N + col)       = h0;
                *reinterpret_cast<__half2*>(Ch + (size_t)(row0 + 8) * N + col) = h1;
            } else {
                float* Cf = reinterpret_cast<float*>(Cout);
                *reinterpret_cast<float2*>(Cf + (size_t)row0 * N + col)       = make_float2(v0, v1);
                *reinterpret_cast<float2*>(Cf + (size_t)(row0 + 8) * N + col) = make_float2(v2, v3);
            }
        }
    }
}

// ---------------- qtilde via tensor cores (R11) ----------------
__global__ __launch_bounds__(256)
void qtilde_tc(const __half* __restrict__ Q, const __half* __restrict__ Wkh,
               __half* __restrict__ qt) {
    __shared__ __half As[128][HS];
    __shared__ __half Bs[128][HS];

    const int tid  = threadIdx.x;
    const int lane = tid & 31;
    const int wid  = tid >> 5;
    const int m0   = blockIdx.x * 128;
    const int head = blockIdx.y >> 1;
    const int n0   = (blockIdx.y & 1) * 128;
    const int warp_m = (wid & 1) * 64;
    const int warp_n = (wid >> 1) * 32;

    const int ldRow = tid >> 1;
    const int ldCol = (tid & 1) * 16;
    {
        const __half* Ag = Q   + (size_t)(m0 + ldRow) * 256 + head * 32 + ldCol;
        const __half* Bg = Wkh + (size_t)(n0 + ldRow) * 256 + head * 32 + ldCol;
        *reinterpret_cast<uint4*>(&As[ldRow][ldCol])     = *reinterpret_cast<const uint4*>(Ag);
        *reinterpret_cast<uint4*>(&As[ldRow][ldCol + 8]) = *reinterpret_cast<const uint4*>(Ag + 8);
        *reinterpret_cast<uint4*>(&Bs[ldRow][ldCol])     = *reinterpret_cast<const uint4*>(Bg);
        *reinterpret_cast<uint4*>(&Bs[ldRow][ldCol + 8]) = *reinterpret_cast<const uint4*>(Bg + 8);
    }
    __syncthreads();

    float c[4][4][4];
    #pragma unroll
    for (int mt = 0; mt < 4; mt++)
        #pragma unroll
        for (int nt = 0; nt < 4; nt++)
            #pragma unroll
            for (int i = 0; i < 4; i++) c[mt][nt][i] = 0.0f;

    const uint32_t as_base = smem_u32(&As[0][0]);
    const uint32_t bs_base = smem_u32(&Bs[0][0]);
    const int a_row = warp_m + (lane & 7) + ((lane >> 3) & 1) * 8;
    const int a_k   = (lane >> 4) * 8;
    const int b_row = warp_n + (lane & 7) + ((lane >> 4) & 1) * 8;
    const int b_k   = ((lane >> 3) & 1) * 8;
    const uint32_t aAddr0 = as_base + (uint32_t)(a_row * HS + a_k) * 2;
    const uint32_t bAddr0 = bs_base + (uint32_t)(b_row * HS + b_k) * 2;

    #pragma unroll
    for (int ks = 0; ks < 2; ks++) {
        uint32_t af[4][4];
        uint32_t bf[2][4];
        #pragma unroll
        for (int mt = 0; mt < 4; mt++)
            ldsm_x4(af[mt], aAddr0 + (uint32_t)(mt * 16 * HS + ks * 16) * 2);
        #pragma unroll
        for (int ntp = 0; ntp < 2; ntp++)
            ldsm_x4(bf[ntp], bAddr0 + (uint32_t)(ntp * 16 * HS + ks * 16) * 2);
        #pragma unroll
        for (int mt = 0; mt < 4; mt++) {
            #pragma unroll
            for (int nt = 0; nt < 4; nt++) {
                uint32_t b0 = (nt & 1) ? bf[nt >> 1][2] : bf[nt >> 1][0];
                uint32_t b1 = (nt & 1) ? bf[nt >> 1][3] : bf[nt >> 1][1];
                mma_f16(c[mt][nt], af[mt], b0, b1);
            }
        }
    }

    const int fr = lane >> 2;
    const int fc = lane & 3;
    #pragma unroll
    for (int mt = 0; mt < 4; mt++) {
        #pragma unroll
        for (int nt = 0; nt < 4; nt++) {
            int row0 = m0 + warp_m + mt * 16 + fr;
            int col  = head * 256 + n0 + warp_n + nt * 8 + fc * 2;
            __half2 h0 = __floats2half2_rn(c[mt][nt][0], c[mt][nt][1]);
            __half2 h1 = __floats2half2_rn(c[mt][nt][2], c[mt][nt][3]);
            *reinterpret_cast<__half2*>(qt + (size_t)row0 * 2048 + col)       = h0;
            *reinterpret_cast<__half2*>(qt + (size_t)(row0 + 8) * 2048 + col) = h1;
        }
    }
}

// ---------------- attention core v6 (R10): tensor-core phases ----------------
#define XS_S 264
#define QS_S 264
#define AT_S 40
#define CT_S 264
__global__ __launch_bounds__(256)
void attn_kernel(const float* __restrict__ xnei, const __half* __restrict__ qt,
                 __half* __restrict__ ctx) {
    __shared__ __half xs[32 * XS_S];
    __shared__ __half qts[8 * QS_S];
    __shared__ float  sred[8 * 256];
    __shared__ __half attns_h[8 * AT_S];
    __shared__ __half ctx_t[8 * CT_S];
    int b    = blockIdx.x;
    int tid  = threadIdx.x;
    int lane = tid & 31;
    int w    = tid >> 5;

    const float4* xb4 = reinterpret_cast<const float4*>(xnei + (size_t)b * 8192);
    #pragma unroll
    for (int j = 0; j < 8; j++) {
        int i  = tid + j * 256;
        int k  = i >> 6;
        int c4 = i & 63;
        float4 v = xb4[i];
        __half2 h0 = __floats2half2_rn(v.x, v.y);
        __half2 h1 = __floats2half2_rn(v.z, v.w);
        uint2 u;
        u.x = *reinterpret_cast<uint32_t*>(&h0);
        u.y = *reinterpret_cast<uint32_t*>(&h1);
        *reinterpret_cast<uint2*>(xs + k * XS_S + c4 * 4) = u;
    }
    {
        const uint4* qp = reinterpret_cast<const uint4*>(qt + (size_t)b * 2048);
        int h  = tid >> 5;
        int c8 = tid & 31;
        *reinterpret_cast<uint4*>(qts + h * QS_S + c8 * 8) = qp[tid];
    }
    __syncthreads();

    const uint32_t xs_base = smem_u32(xs);
    const uint32_t qs_base = smem_u32(qts);
    const uint32_t at_base = smem_u32(attns_h);
    const int fr = lane >> 2;
    const int fc = lane & 3;

    {
        float sacc[2][4];
        #pragma unroll
        for (int mt = 0; mt < 2; mt++)
            #pragma unroll
            for (int i = 0; i < 4; i++) sacc[mt][i] = 0.0f;
        const int a_row = (lane & 7) + ((lane >> 3) & 1) * 8;
        const int a_kof = (lane >> 4) * 8;
        const int b_row = lane & 7;
        const int b_kof = ((lane >> 3) & 1) * 8;
        #pragma unroll
        for (int ks = 0; ks < 2; ks++) {
            uint32_t bq[2];
            ldsm_x2(bq, qs_base + (uint32_t)(b_row * QS_S + w * 32 + ks * 16 + b_kof) * 2);
            #pragma unroll
            for (int mt = 0; mt < 2; mt++) {
                uint32_t af[4];
                ldsm_x4(af, xs_base + (uint32_t)((mt * 16 + a_row) * XS_S + w * 32 + ks * 16 + a_kof) * 2);
                mma_f16(sacc[mt], af, bq[0], bq[1]);
            }
        }
        #pragma unroll
        for (int mt = 0; mt < 2; mt++) {
            int krow = mt * 16 + fr;
            *reinterpret_cast<float2*>(&sred[w * 256 + krow * 8 + fc * 2]) =
                make_float2(sacc[mt][0], sacc[mt][1]);
            *reinterpret_cast<float2*>(&sred[w * 256 + (krow + 8) * 8 + fc * 2]) =
                make_float2(sacc[mt][2], sacc[mt][3]);
        }
    }
    __syncthreads();

    {
        float sc = 0.0f;
        #pragma unroll
        for (int ww = 0; ww < 8; ww++)
            sc += sred[ww * 256 + lane * 8 + w];
        sc *= 0.17677669529663687f;
        float m = sc;
        #pragma unroll
        for (int o = 16; o; o >>= 1) m = fmaxf(m, __shfl_xor_sync(0xFFFFFFFFu, m, o));
        float e = expf(sc - m);
        float s = e;
        #pragma unroll
        for (int o = 16; o; o >>= 1) s += __shfl_xor_sync(0xFFFFFFFFu, s, o);
        attns_h[w * AT_S + lane] = __float2half_rn(e / s);
    }
    __syncthreads();

    {
        float cacc[2][4];
        #pragma unroll
        for (int mt = 0; mt < 2; mt++)
            #pragma unroll
            for (int i = 0; i < 4; i++) cacc[mt][i] = 0.0f;
        const int t_krow = ((lane >> 4) & 1) * 8 + (lane & 7);
        const int t_dof  = ((lane >> 3) & 1) * 8;
        const int b_row = lane & 7;
        const int b_kof = ((lane >> 3) & 1) * 8;
        #pragma unroll
        for (int ks = 0; ks < 2; ks++) {
            uint32_t bp[2];
            ldsm_x2(bp, at_base + (uint32_t)(b_row * AT_S + ks * 16 + b_kof) * 2);
            #pragma unroll
            for (int mt = 0; mt < 2; mt++) {
                int d0 = w * 32 + mt * 16;
                uint32_t af[4];
                ldsm_x4_trans(af, xs_base + (uint32_t)((ks * 16 + t_krow) * XS_S + d0 + t_dof) * 2);
                mma_f16(cacc[mt], af, bp[0], bp[1]);
            }
        }
        #pragma unroll
        for (int mt = 0; mt < 2; mt++) {
            int d0 = w * 32 + mt * 16;
            ctx_t[(fc * 2 + 0) * CT_S + d0 + fr]     = __float2half_rn(cacc[mt][0]);
            ctx_t[(fc * 2 + 1) * CT_S + d0 + fr]     = __float2half_rn(cacc[mt][1]);
            ctx_t[(fc * 2 + 0) * CT_S + d0 + fr + 8] = __float2half_rn(cacc[mt][2]);
            ctx_t[(fc * 2 + 1) * CT_S + d0 + fr + 8] = __float2half_rn(cacc[mt][3]);
        }
    }
    __syncthreads();

    {
        uint4 u = *reinterpret_cast<const uint4*>(&ctx_t[w * CT_S + lane * 8]);
        *reinterpret_cast<uint4*>(&ctx[(size_t)b * 2048 + w * 256 + lane * 8]) = u;
    }
}

// ---------------- out[b, h*32+j] = sum_d ctx[b,h,d] * W_v[d, h*32+j] (half in/out) ----------------
#define VPROJ_SMEM (16384 * 4)
__global__ void vproj_kernel(const __half* __restrict__ ctx, const float* __restrict__ Wv,
                             __half* __restrict__ out) {
    extern __shared__ float vsm[];
    float* Wvs = vsm;          // [256][32]
    float* cs  = vsm + 8192;   // [32][256]
    int h  = blockIdx.y;
    int b0 = blockIdx.x * 32;
    int tid = threadIdx.x;
    for (int i = tid * 4; i < 8192; i += 1024) {
        int d = i >> 5, j = i & 31;
        *reinterpret_cast<float4*>(&Wvs[i]) =
            *reinterpret_cast<const float4*>(&Wv[d * 256 + h * 32 + j]);
    }
    for (int i = tid * 8; i < 8192; i += 2048) {
        int r = i >> 8, d2 = i & 255;
        uint4 u = *reinterpret_cast<const uint4*>(&ctx[(size_t)(b0 + r) * 2048 + h * 256 + d2]);
        float2 f0 = __half22float2(*reinterpret_cast<__half2*>(&u.x));
        float2 f1 = __half22float2(*reinterpret_cast<__half2*>(&u.y));
        float2 f2 = __half22float2(*reinterpret_cast<__half2*>(&u.z));
        float2 f3 = __half22float2(*reinterpret_cast<__half2*>(&u.w));
        *reinterpret_cast<float4*>(&cs[i])     = make_float4(f0.x, f0.y, f1.x, f1.y);
        *reinterpret_cast<float4*>(&cs[i + 4]) = make_float4(f2.x, f2.y, f3.x, f3.y);
    }
    __syncthreads();
    int j  = tid & 31;
    int rg = tid >> 5;
    float acc0 = 0.0f, acc1 = 0.0f, acc2 = 0.0f, acc3 = 0.0f;
    #pragma unroll 4
    for (int d4 = 0; d4 < 64; d4++) {
        float w0 = Wvs[(d4 * 4 + 0) * 32 + j];
        float w1 = Wvs[(d4 * 4 + 1) * 32 + j];
        float w2 = Wvs[(d4 * 4 + 2) * 32 + j];
        float w3 = Wvs[(d4 * 4 + 3) * 32 + j];
        float4 c0 = *reinterpret_cast<const float4*>(&cs[(rg +  0) * 256 + d4 * 4]);
        float4 c1 = *reinterpret_cast<const float4*>(&cs[(rg +  8) * 256 + d4 * 4]);
        float4 c2 = *reinterpret_cast<const float4*>(&cs[(rg + 16) * 256 + d4 * 4]);
        float4 c3 = *reinterpret_cast<const float4*>(&cs[(rg + 24) * 256 + d4 * 4]);
        acc0 += c0.x * w0 + c0.y * w1 + c0.z * w2 + c0.w * w3;
        acc1 += c1.x * w0 + c1.y * w1 + c1.z * w2 + c1.w * w3;
        acc2 += c2.x * w0 + c2.y * w1 + c2.z * w2 + c2.w * w3;
        acc3 += c3.x * w0 + c3.y * w1 + c3.z * w2 + c3.w * w3;
    }
    out[(size_t)(b0 + rg +  0) * 256 + h * 32 + j] = __float2half_rn(acc0);
    out[(size_t)(b0 + rg +  8) * 256 + h * 32 + j] = __float2half_rn(acc1);
    out[(size_t)(b0 + rg + 16) * 256 + h * 32 + j] = __float2half_rn(acc2);
    out[(size_t)(b0 + rg + 24) * 256 + h * 32 + j] = __float2half_rn(acc3);
}

// ---------------- launcher ----------------
extern "C" void kernel_launch(void* const* d_in, const int* in_sizes, int n_in,
                              void* d_out, int out_size) {
    const float* x_anc = (const float*)d_in[0];
    const float* x_nei = (const float*)d_in[1];
    const float* W_q   = (const float*)d_in[2];
    const float* W_k   = (const float*)d_in[3];
    const float* W_v   = (const float*)d_in[4];
    const float* W_o   = (const float*)d_in[5];
    const float* ln1_g = (const float*)d_in[6];
    const float* ln1_b = (const float*)d_in[7];
    const float* ln2_g = (const float*)d_in[8];
    const float* ln2_b = (const float*)d_in[9];
    const float* ff1_w = (const float*)d_in[10];
    const float* ff1_b = (const float*)d_in[11];
    const float* ff2_w = (const float*)d_in[12];
    const float* ff2_b = (const float*)d_in[13];
    float* out = (float*)d_out;

    __half *p_lnx, *p_qh, *p_qt, *p_ctx, *p_att, *p_h, *p_ff;
    __half *p_wkh, *p_wtq, *p_wto, *p_wt1, *p_wt2;
    float *p_x;
    cudaGetSymbolAddress((void**)&p_lnx, g_lnx);
    cudaGetSymbolAddress((void**)&p_qh,  g_qh);
    cudaGetSymbolAddress((void**)&p_qt,  g_qt);
    cudaGetSymbolAddress((void**)&p_ctx, g_ctx);
    cudaGetSymbolAddress((void**)&p_att, g_att);
    cudaGetSymbolAddress((void**)&p_x,   g_x);
    cudaGetSymbolAddress((void**)&p_h,   g_h);
    cudaGetSymbolAddress((void**)&p_ff,  g_ff);
    cudaGetSymbolAddress((void**)&p_wkh, g_wkh);
    cudaGetSymbolAddress((void**)&p_wtq, g_wtq);
    cudaGetSymbolAddress((void**)&p_wto, g_wto);
    cudaGetSymbolAddress((void**)&p_wt1, g_wt1);
    cudaGetSymbolAddress((void**)&p_wt2, g_wt2);

    cudaFuncSetAttribute(vproj_kernel, cudaFuncAttributeMaxDynamicSharedMemorySize, VPROJ_SMEM);
    cudaFuncSetAttribute(hgemm<0>, cudaFuncAttributeMaxDynamicSharedMemorySize, HGEMM_SMEM);
    cudaFuncSetAttribute(hgemm<1>, cudaFuncAttributeMaxDynamicSharedMemorySize, HGEMM_SMEM);
    cudaFuncSetAttribute(hgemm<2>, cudaFuncAttributeMaxDynamicSharedMemorySize, HGEMM_SMEM);
    cudaFuncSetAttribute(hgemm<3>, cudaFuncAttributeMaxDynamicSharedMemorySize, HGEMM_SMEM);
    cudaFuncSetAttribute(hgemm<4>, cudaFuncAttributeMaxDynamicSharedMemorySize, HGEMM_SMEM);

    dim3 lnBlock(32, 8);
    dim3 tBlock(32, 8);

    // 0: Wk -> half
    tohalf_kernel<<<64, 256>>>(W_k, p_wkh);
    // 1: transpose W_q
    transpose_kernel<<<dim3(8, 8),  tBlock>>>(W_q,   p_wtq, 256, 256);
    // 2: LN1 -> half
    ln_kernel<<<BN / 8, lnBlock>>>(x_anc, ln1_g, ln1_b, p_lnx);
    // 3: Q = LN1 @ W_q (half out)  [PROFILED SLOT]
    hgemm<4><<<dim3(2, BN / 128), 256, HGEMM_SMEM>>>(p_lnx, p_wtq, p_qh, BN, DIM, DIM, nullptr, nullptr);
    // 4: q~ via tensor cores
    qtilde_tc<<<dim3(BN / 128, 16), 256>>>(p_qh, p_wkh, p_qt);
    // 5: attention core -> ctx (half)
    attn_kernel<<<BN, 256>>>(x_nei, p_qt, p_ctx);
    // 6: transpose W_o
    transpose_kernel<<<dim3(8, 8),  tBlock>>>(W_o,   p_wto, 256, 256);
    // 7: att = ctx @ W_v
    vproj_kernel<<<dim3(BN / 32, NH), 256, VPROJ_SMEM>>>(p_ctx, W_v, p_att);
    // 8: x = x_anc + att @ W_o
    hgemm<3><<<dim3(2, BN / 128), 256, HGEMM_SMEM>>>(p_att, p_wto, p_x, BN, DIM, DIM, nullptr, x_anc);
    // 9: LN2 -> half
    ln_kernel<<<BN / 8, lnBlock>>>(p_x, ln2_g, ln2_b, p_h);
    // 10: transpose ff1
    transpose_kernel<<<dim3(32, 8), tBlock>>>(ff1_w, p_wt1, 256, 1024);
    // 11: ff = gelu(h @ ff1 + b1)
    hgemm<1><<<dim3(8, BN / 128), 256, HGEMM_SMEM>>>(p_h, p_wt1, p_ff, BN, NFF, DIM, ff1_b, nullptr);
    // 12: transpose ff2
    transpose_kernel<<<dim3(8, 32), tBlock>>>(ff2_w, p_wt2, 1024, 256);
    // 13: out = x + ff @ ff2 + b2
    hgemm<2><<<dim3(2, BN / 128), 256, HGEMM_SMEM>>>(p_ff, p_wt2, out, BN, DIM, NFF, ff2_b, p_x);
}

// round 14
// speedup vs baseline: 1.3509x; 1.2702x over previous
#include <cuda_runtime.h>
#include <cuda_fp16.h>
#include <math.h>
#include <stdint.h>

// Problem constants
#define BN  32768
#define DIM 256
#define NK  32
#define NH  8
#define NFF 1024
#define NDK 32

// ---------------- scratch (device globals: allocation-guard-safe) ----------------
__device__ __align__(128) __half g_lnx[BN * DIM];       // LN1(x_anc), half
__device__ __align__(128) __half g_qh[BN * DIM];        // Q, half
__device__ __align__(128) __half g_qt[BN * NH * DIM];   // q~ [B, H, 256], half
__device__ __align__(128) __half g_ctx[BN * NH * DIM];  // ctx [B, H, 256], half
__device__ __align__(128) __half g_att[BN * DIM];       // attention out (pre-W_o), half
__device__ __align__(128) __half g_xh[BN * DIM];        // x = x_anc + att @ W_o, half
__device__ __align__(128) __half g_h[BN * DIM];         // LN2(x), half
__device__ __align__(128) __half g_ff[BN * NFF];        // gelu(h@ff1+b1), half
// half weights
__device__ __align__(128) __half g_wkh[DIM * DIM];      // Wk as half (same layout)
__device__ __align__(128) __half g_wtq[DIM * DIM];
__device__ __align__(128) __half g_wto[DIM * DIM];
__device__ __align__(128) __half g_wtv[DIM * DIM];      // Wv^T
__device__ __align__(128) __half g_wt1[DIM * NFF];
__device__ __align__(128) __half g_wt2[NFF * DIM];

// ---------------- LayerNorm (fp32 input): one warp per row, half output ----------------
__global__ void ln_kernel(const float* __restrict__ x, const float* __restrict__ g,
                          const float* __restrict__ b, __half* __restrict__ out) {
    int row  = blockIdx.x * 8 + threadIdx.y;
    int lane = threadIdx.x;
    const float4* xr = reinterpret_cast<const float4*>(x + (size_t)row * DIM);
    float4 v0 = xr[lane];
    float4 v1 = xr[lane + 32];
    float s  = v0.x + v0.y + v0.z + v0.w + v1.x + v1.y + v1.z + v1.w;
    float ss = v0.x*v0.x + v0.y*v0.y + v0.z*v0.z + v0.w*v0.w
             + v1.x*v1.x + v1.y*v1.y + v1.z*v1.z + v1.w*v1.w;
    #pragma unroll
    for (int o = 16; o; o >>= 1) {
        s  += __shfl_xor_sync(0xFFFFFFFFu, s,  o);
        ss += __shfl_xor_sync(0xFFFFFFFFu, ss, o);
    }
    float mu  = s * (1.0f / 256.0f);
    float var = ss * (1.0f / 256.0f) - mu * mu;
    float rs  = rsqrtf(var + 1e-5f);
    const float4* g4 = reinterpret_cast<const float4*>(g);
    const float4* b4 = reinterpret_cast<const float4*>(b);
    __half* orow = out + (size_t)row * DIM;
    #pragma unroll
    for (int p = 0; p < 2; p++) {
        int idx = lane + p * 32;
        float4 v = (p == 0) ? v0 : v1;
        float4 gg = g4[idx], bb = b4[idx];
        float o0 = (v.x - mu) * rs * gg.x + bb.x;
        float o1 = (v.y - mu) * rs * gg.y + bb.y;
        float o2 = (v.z - mu) * rs * gg.z + bb.z;
        float o3 = (v.w - mu) * rs * gg.w + bb.w;
        __half2 ha = __floats2half2_rn(o0, o1);
        __half2 hb = __floats2half2_rn(o2, o3);
        uint2 u;
        u.x = *reinterpret_cast<uint32_t*>(&ha);
        u.y = *reinterpret_cast<uint32_t*>(&hb);
        *reinterpret_cast<uint2*>(orow + idx * 4) = u;
    }
}

// ---------------- LayerNorm (half input): one warp per row, half output ----------------
__global__ void ln_half_kernel(const __half* __restrict__ x, const float* __restrict__ g,
                               const float* __restrict__ b, __half* __restrict__ out) {
    int row  = blockIdx.x * 8 + threadIdx.y;
    int lane = threadIdx.x;
    const uint4* xr = reinterpret_cast<const uint4*>(x + (size_t)row * DIM);
    uint4 u = xr[lane];   // 8 halves
    float v[8];
    {
        float2 f0 = __half22float2(*reinterpret_cast<__half2*>(&u.x));
        float2 f1 = __half22float2(*reinterpret_cast<__half2*>(&u.y));
        float2 f2 = __half22float2(*reinterpret_cast<__half2*>(&u.z));
        float2 f3 = __half22float2(*reinterpret_cast<__half2*>(&u.w));
        v[0]=f0.x; v[1]=f0.y; v[2]=f1.x; v[3]=f1.y;
        v[4]=f2.x; v[5]=f2.y; v[6]=f3.x; v[7]=f3.y;
    }
    float s = 0.f, ss = 0.f;
    #pragma unroll
    for (int i = 0; i < 8; i++) { s += v[i]; ss += v[i] * v[i]; }
    #pragma unroll
    for (int o = 16; o; o >>= 1) {
        s  += __shfl_xor_sync(0xFFFFFFFFu, s,  o);
        ss += __shfl_xor_sync(0xFFFFFFFFu, ss, o);
    }
    float mu  = s * (1.0f / 256.0f);
    float var = ss * (1.0f / 256.0f) - mu * mu;
    float rs  = rsqrtf(var + 1e-5f);
    const float4* g4 = reinterpret_cast<const float4*>(g);
    const float4* b4 = reinterpret_cast<const float4*>(b);
    float4 ga = g4[lane * 2], gb = g4[lane * 2 + 1];
    float4 ba = b4[lane * 2], bb = b4[lane * 2 + 1];
    float o0 = (v[0]-mu)*rs*ga.x + ba.x;
    float o1 = (v[1]-mu)*rs*ga.y + ba.y;
    float o2 = (v[2]-mu)*rs*ga.z + ba.z;
    float o3 = (v[3]-mu)*rs*ga.w + ba.w;
    float o4 = (v[4]-mu)*rs*gb.x + bb.x;
    float o5 = (v[5]-mu)*rs*gb.y + bb.y;
    float o6 = (v[6]-mu)*rs*gb.z + bb.z;
    float o7 = (v[7]-mu)*rs*gb.w + bb.w;
    __half2 h0 = __floats2half2_rn(o0, o1);
    __half2 h1 = __floats2half2_rn(o2, o3);
    __half2 h2 = __floats2half2_rn(o4, o5);
    __half2 h3 = __floats2half2_rn(o6, o7);
    uint4 ou;
    ou.x = *reinterpret_cast<uint32_t*>(&h0);
    ou.y = *reinterpret_cast<uint32_t*>(&h1);
    ou.z = *reinterpret_cast<uint32_t*>(&h2);
    ou.w = *reinterpret_cast<uint32_t*>(&h3);
    *reinterpret_cast<uint4*>(out + (size_t)row * DIM + lane * 8) = ou;
}

__device__ __forceinline__ float gelu_exact(float v) {
    return 0.5f * v * (1.0f + erff(v * 0.70710678118654752f));
}

// ---------------- weight prep: z=0..2 transpose {Wq,Wo,Wv}; z=3 copy-convert Wk ----------------
__global__ void wprep_kernel(const float* __restrict__ Wq, const float* __restrict__ Wo,
                             const float* __restrict__ Wv, const float* __restrict__ Wk,
                             __half* __restrict__ wtq, __half* __restrict__ wto,
                             __half* __restrict__ wtv, __half* __restrict__ wkh) {
    __shared__ float t[32][33];
    int z = blockIdx.z;
    const float* in = (z == 0) ? Wq : (z == 1) ? Wo : (z == 2) ? Wv : Wk;
    __half* out     = (z == 0) ? wtq : (z == 1) ? wto : (z == 2) ? wtv : wkh;
    int c0 = blockIdx.x * 32, r0 = blockIdx.y * 32;
    int tx = threadIdx.x, ty = threadIdx.y;   // (32, 8)
    if (z < 3) {
        #pragma unroll
        for (int j = 0; j < 4; j++)
            t[ty + j * 8][tx] = in[(size_t)(r0 + ty + j * 8) * 256 + c0 + tx];
        __syncthreads();
        #pragma unroll
        for (int j = 0; j < 4; j++)
            out[(size_t)(c0 + ty + j * 8) * 256 + r0 + tx] = __float2half_rn(t[tx][ty + j * 8]);
    } else {
        #pragma unroll
        for (int j = 0; j < 4; j++) {
            size_t idx = (size_t)(r0 + ty + j * 8) * 256 + c0 + tx;
            out[idx] = __float2half_rn(in[idx]);
        }
    }
}

// ---------------- transpose+convert (rectangular weights) ----------------
__global__ void transpose_kernel(const float* __restrict__ in, __half* __restrict__ out,
                                 int R, int C) {
    __shared__ float t[32][33];
    int c0 = blockIdx.x * 32, r0 = blockIdx.y * 32;
    int tx = threadIdx.x, ty = threadIdx.y;   // (32, 8)
    #pragma unroll
    for (int j = 0; j < 4; j++)
        t[ty + j * 8][tx] = in[(size_t)(r0 + ty + j * 8) * C + c0 + tx];
    __syncthreads();
    #pragma unroll
    for (int j = 0; j < 4; j++)
        out[(size_t)(c0 + ty + j * 8) * R + r0 + tx] = __float2half_rn(t[tx][ty + j * 8]);
}

// ---------------- shared helpers ----------------
__device__ __forceinline__ uint32_t smem_u32(const void* p) {
    uint32_t a;
    asm("{ .reg .u64 t; cvta.to.shared.u64 t, %1; cvt.u32.u64 %0, t; }" : "=r"(a) : "l"(p));
    return a;
}
__device__ __forceinline__ void ldsm_x4(uint32_t r[4], uint32_t addr) {
    asm volatile("ldmatrix.sync.aligned.m8n8.x4.shared.b16 {%0,%1,%2,%3}, [%4];"
                 : "=r"(r[0]), "=r"(r[1]), "=r"(r[2]), "=r"(r[3]) : "r"(addr));
}
__device__ __forceinline__ void ldsm_x4_trans(uint32_t r[4], uint32_t addr) {
    asm volatile("ldmatrix.sync.aligned.m8n8.x4.trans.shared.b16 {%0,%1,%2,%3}, [%4];"
                 : "=r"(r[0]), "=r"(r[1]), "=r"(r[2]), "=r"(r[3]) : "r"(addr));
}
__device__ __forceinline__ void ldsm_x2(uint32_t r[2], uint32_t addr) {
    asm volatile("ldmatrix.sync.aligned.m8n8.x2.shared.b16 {%0,%1}, [%2];"
                 : "=r"(r[0]), "=r"(r[1]) : "r"(addr));
}
__device__ __forceinline__ void mma_f16(float c[4], const uint32_t a[4],
                                        uint32_t b0, uint32_t b1) {
    asm volatile(
        "mma.sync.aligned.m16n8k16.row.col.f32.f16.f16.f32 "
        "{%0,%1,%2,%3}, {%4,%5,%6,%7}, {%8,%9}, {%0,%1,%2,%3};\n"
        : "+f"(c[0]), "+f"(c[1]), "+f"(c[2]), "+f"(c[3])
        : "r"(a[0]), "r"(a[1]), "r"(a[2]), "r"(a[3]), "r"(b0), "r"(b1));
}
__device__ __forceinline__ void cp_async16(uint32_t dst, const void* src) {
    asm volatile("cp.async.cg.shared.global [%0], [%1], 16;\n" :: "r"(dst), "l"(src));
}
__device__ __forceinline__ void cp_commit() {
    asm volatile("cp.async.commit_group;\n" ::: "memory");
}
template <int N>
__device__ __forceinline__ void cp_wait() {
    asm volatile("cp.async.wait_group %0;\n" :: "n"(N) : "memory");
}

// ================= fp16 tensor-core GEMM: 128x128, 3-stage cp.async pipeline =================
#define HS 40
#define STAGE_BYTES (128 * HS * 2)          // one A or B buffer: 10240 B
#define HGEMM_SMEM (6 * STAGE_BYTES)        // 3 stages x (A + B) = 61440 B

// MODE 1: gelu(A@B+bias) -> half     MODE 2: A@B + bias + HALF resid -> f32
// MODE 3: A@B + F32 resid -> half    MODE 4: A@B -> half
template <int MODE>
__global__ __launch_bounds__(256, 2)
void hgemm(const __half* __restrict__ A, const __half* __restrict__ BT,
           void* __restrict__ Cout, int M, int N, int Kd,
           const float* __restrict__ bias, const void* __restrict__ resid) {
    extern __shared__ __half hsm[];
    const uint32_t sm_base = smem_u32(hsm);

    const int tid  = threadIdx.x;
    const int lane = tid & 31;
    const int wid  = tid >> 5;
    const int m0 = blockIdx.y * 128;
    const int n0 = blockIdx.x * 128;
    const int warp_m = (wid & 1) * 64;
    const int warp_n = (wid >> 1) * 32;

    const int ldRow = tid >> 1;
    const int ldCol = (tid & 1) * 16;
    const __half* Ag = A  + (size_t)(m0 + ldRow) * Kd + ldCol;
    const __half* Bg = BT + (size_t)(n0 + ldRow) * Kd + ldCol;
    const uint32_t ldOffA = (uint32_t)(ldRow * HS + ldCol) * 2;
    const uint32_t ldOffB = ldOffA + STAGE_BYTES;

    float c[4][4][4];
    #pragma unroll
    for (int mt = 0; mt < 4; mt++)
        #pragma unroll
        for (int nt = 0; nt < 4; nt++)
            #pragma unroll
            for (int i = 0; i < 4; i++) c[mt][nt][i] = 0.0f;

    const int a_row = warp_m + (lane & 7) + ((lane >> 3) & 1) * 8;
    const int a_k   = (lane >> 4) * 8;
    const int b_row = warp_n + (lane & 7) + ((lane >> 4) & 1) * 8;
    const int b_k   = ((lane >> 3) & 1) * 8;
    const uint32_t aAddr0 = sm_base + (uint32_t)(a_row * HS + a_k) * 2;
    const uint32_t bAddr0 = sm_base + STAGE_BYTES + (uint32_t)(b_row * HS + b_k) * 2;

    const int KT = Kd >> 5;

    #pragma unroll
    for (int p = 0; p < 2; p++) {
        uint32_t sbase = (uint32_t)p * (2 * STAGE_BYTES);
        const __half* Ap = Ag + p * 32;
        const __half* Bp = Bg + p * 32;
        cp_async16(sm_base + sbase + ldOffA,      Ap);
        cp_async16(sm_base + sbase + ldOffA + 16, Ap + 8);
        cp_async16(sm_base + sbase + ldOffB,      Bp);
        cp_async16(sm_base + sbase + ldOffB + 16, Bp + 8);
        cp_commit();
    }

    for (int kt = 0; kt < KT; kt++) {
        if (kt + 1 < KT) cp_wait<1>(); else cp_wait<0>();
        __syncthreads();

        if (kt + 2 < KT) {
            uint32_t sbase = (uint32_t)((kt + 2) % 3) * (2 * STAGE_BYTES);
            const __half* Ap = Ag + (kt + 2) * 32;
            const __half* Bp = Bg + (kt + 2) * 32;
            cp_async16(sm_base + sbase + ldOffA,      Ap);
            cp_async16(sm_base + sbase + ldOffA + 16, Ap + 8);
            cp_async16(sm_base + sbase + ldOffB,      Bp);
            cp_async16(sm_base + sbase + ldOffB + 16, Bp + 8);
            cp_commit();
        }

        const uint32_t bo = (uint32_t)(kt % 3) * (2 * STAGE_BYTES);
        #pragma unroll
        for (int ks = 0; ks < 2; ks++) {
            uint32_t af[4][4];
            uint32_t bf[2][4];
            #pragma unroll
            for (int mt = 0; mt < 4; mt++)
                ldsm_x4(af[mt], aAddr0 + bo + (uint32_t)(mt * 16 * HS + ks * 16) * 2);
            #pragma unroll
            for (int ntp = 0; ntp < 2; ntp++)
                ldsm_x4(bf[ntp], bAddr0 + bo + (uint32_t)(ntp * 16 * HS + ks * 16) * 2);
            #pragma unroll
            for (int mt = 0; mt < 4; mt++) {
                #pragma unroll
                for (int nt = 0; nt < 4; nt++) {
                    uint32_t b0 = (nt & 1) ? bf[nt >> 1][2] : bf[nt >> 1][0];
                    uint32_t b1 = (nt & 1) ? bf[nt >> 1][3] : bf[nt >> 1][1];
                    mma_f16(c[mt][nt], af[mt], b0, b1);
                }
            }
        }
        __syncthreads();
    }

    const int fr = lane >> 2;
    const int fc = lane & 3;
    #pragma unroll
    for (int mt = 0; mt < 4; mt++) {
        #pragma unroll
        for (int nt = 0; nt < 4; nt++) {
            int row0 = m0 + warp_m + mt * 16 + fr;
            int col  = n0 + warp_n + nt * 8 + fc * 2;
            float v0 = c[mt][nt][0], v1 = c[mt][nt][1];
            float v2 = c[mt][nt][2], v3 = c[mt][nt][3];
            if (MODE == 1 || MODE == 2) {
                float2 bv = *reinterpret_cast<const float2*>(bias + col);
                v0 += bv.x; v1 += bv.y; v2 += bv.x; v3 += bv.y;
            }
            if (MODE == 1) {
                v0 = gelu_exact(v0); v1 = gelu_exact(v1);
                v2 = gelu_exact(v2); v3 = gelu_exact(v3);
            }
            if (MODE == 2) {   // half resid
                const __half* rh = reinterpret_cast<const __half*>(resid);
                float2 f0 = __half22float2(*reinterpret_cast<const __half2*>(rh + (size_t)row0 * N + col));
                float2 f1 = __half22float2(*reinterpret_cast<const __half2*>(rh + (size_t)(row0 + 8) * N + col));
                v0 += f0.x; v1 += f0.y; v2 += f1.x; v3 += f1.y;
            }
            if (MODE == 3) {   // fp32 resid
                const float* rf = reinterpret_cast<const float*>(resid);
                float2 r0 = *reinterpret_cast<const float2*>(rf + (size_t)row0 * N + col);
                float2 r1 = *reinterpret_cast<const float2*>(rf + (size_t)(row0 + 8) * N + col);
                v0 += r0.x; v1 += r0.y; v2 += r1.x; v3 += r1.y;
            }
            if (MODE == 1 || MODE == 3 || MODE == 4) {
                __half* Ch = reinterpret_cast<__half*>(Cout);
                __half2 h0 = __floats2half2_rn(v0, v1);
                __half2 h1 = __floats2half2_rn(v2, v3);
                *reinterpret_cast<__half2*>(Ch + (size_t)row0 * N + col)       = h0;
                *reinterpret_cast<__half2*>(Ch + (size_t)(row0 + 8) * N + col) = h1;
            } else {
                float* Cf = reinterpret_cast<float*>(Cout);
                *reinterpret_cast<float2*>(Cf + (size_t)row0 * N + col)       = make_float2(v0, v1);
                *reinterpret_cast<float2*>(Cf + (size_t)(row0 + 8) * N + col) = make_float2(v2, v3);
            }
        }
    }
}

// ---------------- qtilde via tensor cores ----------------
__global__ __launch_bounds__(256)
void qtilde_tc(const __half* __restrict__ Q, const __half* __restrict__ Wkh,
               __half* __restrict__ qt) {
    __shared__ __half As[128][HS];
    __shared__ __half Bs[128][HS];

    const int tid  = threadIdx.x;
    const int lane = tid & 31;
    const int wid  = tid >> 5;
    const int m0   = blockIdx.x * 128;
    const int head = blockIdx.y >> 1;
    const int n0   = (blockIdx.y & 1) * 128;
    const int warp_m = (wid & 1) * 64;
    const int warp_n = (wid >> 1) * 32;

    const int ldRow = tid >> 1;
    const int ldCol = (tid & 1) * 16;
    {
        const __half* Ag = Q   + (size_t)(m0 + ldRow) * 256 + head * 32 + ldCol;
        const __half* Bg = Wkh + (size_t)(n0 + ldRow) * 256 + head * 32 + ldCol;
        *reinterpret_cast<uint4*>(&As[ldRow][ldCol])     = *reinterpret_cast<const uint4*>(Ag);
        *reinterpret_cast<uint4*>(&As[ldRow][ldCol + 8]) = *reinterpret_cast<const uint4*>(Ag + 8);
        *reinterpret_cast<uint4*>(&Bs[ldRow][ldCol])     = *reinterpret_cast<const uint4*>(Bg);
        *reinterpret_cast<uint4*>(&Bs[ldRow][ldCol + 8]) = *reinterpret_cast<const uint4*>(Bg + 8);
    }
    __syncthreads();

    float c[4][4][4];
    #pragma unroll
    for (int mt = 0; mt < 4; mt++)
        #pragma unroll
        for (int nt = 0; nt < 4; nt++)
            #pragma unroll
            for (int i = 0; i < 4; i++) c[mt][nt][i] = 0.0f;

    const uint32_t as_base = smem_u32(&As[0][0]);
    const uint32_t bs_base = smem_u32(&Bs[0][0]);
    const int a_row = warp_m + (lane & 7) + ((lane >> 3) & 1) * 8;
    const int a_k   = (lane >> 4) * 8;
    const int b_row = warp_n + (lane & 7) + ((lane >> 4) & 1) * 8;
    const int b_k   = ((lane >> 3) & 1) * 8;
    const uint32_t aAddr0 = as_base + (uint32_t)(a_row * HS + a_k) * 2;
    const uint32_t bAddr0 = bs_base + (uint32_t)(b_row * HS + b_k) * 2;

    #pragma unroll
    for (int ks = 0; ks < 2; ks++) {
        uint32_t af[4][4];
        uint32_t bf[2][4];
        #pragma unroll
        for (int mt = 0; mt < 4; mt++)
            ldsm_x4(af[mt], aAddr0 + (uint32_t)(mt * 16 * HS + ks * 16) * 2);
        #pragma unroll
        for (int ntp = 0; ntp < 2; ntp++)
            ldsm_x4(bf[ntp], bAddr0 + (uint32_t)(ntp * 16 * HS + ks * 16) * 2);
        #pragma unroll
        for (int mt = 0; mt < 4; mt++) {
            #pragma unroll
            for (int nt = 0; nt < 4; nt++) {
                uint32_t b0 = (nt & 1) ? bf[nt >> 1][2] : bf[nt >> 1][0];
                uint32_t b1 = (nt & 1) ? bf[nt >> 1][3] : bf[nt >> 1][1];
                mma_f16(c[mt][nt], af[mt], b0, b1);
            }
        }
    }

    const int fr = lane >> 2;
    const int fc = lane & 3;
    #pragma unroll
    for (int mt = 0; mt < 4; mt++) {
        #pragma unroll
        for (int nt = 0; nt < 4; nt++) {
            int row0 = m0 + warp_m + mt * 16 + fr;
            int col  = head * 256 + n0 + warp_n + nt * 8 + fc * 2;
            __half2 h0 = __floats2half2_rn(c[mt][nt][0], c[mt][nt][1]);
            __half2 h1 = __floats2half2_rn(c[mt][nt][2], c[mt][nt][3]);
            *reinterpret_cast<__half2*>(qt + (size_t)row0 * 2048 + col)       = h0;
            *reinterpret_cast<__half2*>(qt + (size_t)(row0 + 8) * 2048 + col) = h1;
        }
    }
}

// ---------------- attention core (R10): tensor-core phases ----------------
#define XS_S 264
#define QS_S 264
#define AT_S 40
#define CT_S 264
__global__ __launch_bounds__(256)
void attn_kernel(const float* __restrict__ xnei, const __half* __restrict__ qt,
                 __half* __restrict__ ctx) {
    __shared__ __half xs[32 * XS_S];
    __shared__ __half qts[8 * QS_S];
    __shared__ float  sred[8 * 256];
    __shared__ __half attns_h[8 * AT_S];
    __shared__ __half ctx_t[8 * CT_S];
    int b    = blockIdx.x;
    int tid  = threadIdx.x;
    int lane = tid & 31;
    int w    = tid >> 5;

    const float4* xb4 = reinterpret_cast<const float4*>(xnei + (size_t)b * 8192);
    #pragma unroll
    for (int j = 0; j < 8; j++) {
        int i  = tid + j * 256;
        int k  = i >> 6;
        int c4 = i & 63;
        float4 v = xb4[i];
        __half2 h0 = __floats2half2_rn(v.x, v.y);
        __half2 h1 = __floats2half2_rn(v.z, v.w);
        uint2 u;
        u.x = *reinterpret_cast<uint32_t*>(&h0);
        u.y = *reinterpret_cast<uint32_t*>(&h1);
        *reinterpret_cast<uint2*>(xs + k * XS_S + c4 * 4) = u;
    }
    {
        const uint4* qp = reinterpret_cast<const uint4*>(qt + (size_t)b * 2048);
        int h  = tid >> 5;
        int c8 = tid & 31;
        *reinterpret_cast<uint4*>(qts + h * QS_S + c8 * 8) = qp[tid];
    }
    __syncthreads();

    const uint32_t xs_base = smem_u32(xs);
    const uint32_t qs_base = smem_u32(qts);
    const uint32_t at_base = smem_u32(attns_h);
    const int fr = lane >> 2;
    const int fc = lane & 3;

    {
        float sacc[2][4];
        #pragma unroll
        for (int mt = 0; mt < 2; mt++)
            #pragma unroll
            for (int i = 0; i < 4; i++) sacc[mt][i] = 0.0f;
        const int a_row = (lane & 7) + ((lane >> 3) & 1) * 8;
        const int a_kof = (lane >> 4) * 8;
        const int b_row = lane & 7;
        const int b_kof = ((lane >> 3) & 1) * 8;
        #pragma unroll
        for (int ks = 0; ks < 2; ks++) {
            uint32_t bq[2];
            ldsm_x2(bq, qs_base + (uint32_t)(b_row * QS_S + w * 32 + ks * 16 + b_kof) * 2);
            #pragma unroll
            for (int mt = 0; mt < 2; mt++) {
                uint32_t af[4];
                ldsm_x4(af, xs_base + (uint32_t)((mt * 16 + a_row) * XS_S + w * 32 + ks * 16 + a_kof) * 2);
                mma_f16(sacc[mt], af, bq[0], bq[1]);
            }
        }
        #pragma unroll
        for (int mt = 0; mt < 2; mt++) {
            int krow = mt * 16 + fr;
            *reinterpret_cast<float2*>(&sred[w * 256 + krow * 8 + fc * 2]) =
                make_float2(sacc[mt][0], sacc[mt][1]);
            *reinterpret_cast<float2*>(&sred[w * 256 + (krow + 8) * 8 + fc * 2]) =
                make_float2(sacc[mt][2], sacc[mt][3]);
        }
    }
    __syncthreads();

    {
        float sc = 0.0f;
        #pragma unroll
        for (int ww = 0; ww < 8; ww++)
            sc += sred[ww * 256 + lane * 8 + w];
        sc *= 0.17677669529663687f;
        float m = sc;
        #pragma unroll
        for (int o = 16; o; o >>= 1) m = fmaxf(m, __shfl_xor_sync(0xFFFFFFFFu, m, o));
        float e = expf(sc - m);
        float s = e;
        #pragma unroll
        for (int o = 16; o; o >>= 1) s += __shfl_xor_sync(0xFFFFFFFFu, s, o);
        attns_h[w * AT_S + lane] = __float2half_rn(e / s);
    }
    __syncthreads();

    {
        float cacc[2][4];
        #pragma unroll
        for (int mt = 0; mt < 2; mt++)
            #pragma unroll
            for (int i = 0; i < 4; i++) cacc[mt][i] = 0.0f;
        const int t_krow = ((lane >> 4) & 1) * 8 + (lane & 7);
        const int t_dof  = ((lane >> 3) & 1) * 8;
        const int b_row = lane & 7;
        const int b_kof = ((lane >> 3) & 1) * 8;
        #pragma unroll
        for (int ks = 0; ks < 2; ks++) {
            uint32_t bp[2];
            ldsm_x2(bp, at_base + (uint32_t)(b_row * AT_S + ks * 16 + b_kof) * 2);
            #pragma unroll
            for (int mt = 0; mt < 2; mt++) {
                int d0 = w * 32 + mt * 16;
                uint32_t af[4];
                ldsm_x4_trans(af, xs_base + (uint32_t)((ks * 16 + t_krow) * XS_S + d0 + t_dof) * 2);
                mma_f16(cacc[mt], af, bp[0], bp[1]);
            }
        }
        #pragma unroll
        for (int mt = 0; mt < 2; mt++) {
            int d0 = w * 32 + mt * 16;
            ctx_t[(fc * 2 + 0) * CT_S + d0 + fr]     = __float2half_rn(cacc[mt][0]);
            ctx_t[(fc * 2 + 1) * CT_S + d0 + fr]     = __float2half_rn(cacc[mt][1]);
            ctx_t[(fc * 2 + 0) * CT_S + d0 + fr + 8] = __float2half_rn(cacc[mt][2]);
            ctx_t[(fc * 2 + 1) * CT_S + d0 + fr + 8] = __float2half_rn(cacc[mt][3]);
        }
    }
    __syncthreads();

    {
        uint4 u = *reinterpret_cast<const uint4*>(&ctx_t[w * CT_S + lane * 8]);
        *reinterpret_cast<uint4*>(&ctx[(size_t)b * 2048 + w * 256 + lane * 8]) = u;
    }
}

// ---------------- vproj via tensor cores: att[b, h*32+j] = ctx[b,h,:] . WvT[h*32+j,:] ----------------
// per CTA: 128 rows x 32 cols (one head), K=256 (8 k32 chunks), 3-stage cp.async.
#define VST_A (128 * HS * 2)     // 10240
#define VST_B (32 * HS * 2)      // 2560
#define VSTAGE (VST_A + VST_B)
#define VPROJ_SMEM (3 * VSTAGE)  // 38400 (< 48KB: no attribute needed)
__global__ __launch_bounds__(256)
void vproj_tc(const __half* __restrict__ ctx, const __half* __restrict__ WvT,
              __half* __restrict__ out) {
    extern __shared__ __half vsm[];
    const uint32_t sm_base = smem_u32(vsm);
    const int tid  = threadIdx.x;
    const int lane = tid & 31;
    const int wid  = tid >> 5;
    const int m0 = blockIdx.x * 128;
    const int h  = blockIdx.y;

    // A loader: all 256 threads; B loader: threads < 64
    const int aRow = tid >> 1;
    const int aCol = (tid & 1) * 16;
    const __half* Ag = ctx + (size_t)(m0 + aRow) * 2048 + h * 256 + aCol;
    const uint32_t ldOffA = (uint32_t)(aRow * HS + aCol) * 2;
    const __half* Bg = WvT + (size_t)(h * 32 + (tid >> 1)) * 256 + aCol;   // valid for tid<64
    const uint32_t ldOffB = VST_A + (uint32_t)((tid >> 1) * HS + aCol) * 2;

    float c[4][4];
    #pragma unroll
    for (int nt = 0; nt < 4; nt++)
        #pragma unroll
        for (int i = 0; i < 4; i++) c[nt][i] = 0.0f;

    const int a_row = wid * 16 + (lane & 7) + ((lane >> 3) & 1) * 8;
    const int a_k   = (lane >> 4) * 8;
    const int b_row = (lane & 7) + ((lane >> 4) & 1) * 8;
    const int b_k   = ((lane >> 3) & 1) * 8;

    const int KT = 8;   // 256 / 32
    #pragma unroll
    for (int p = 0; p < 2; p++) {
        uint32_t sbase = (uint32_t)p * VSTAGE;
        cp_async16(sm_base + sbase + ldOffA,      Ag + p * 32);
        cp_async16(sm_base + sbase + ldOffA + 16, Ag + p * 32 + 8);
        if (tid < 64) {
            cp_async16(sm_base + sbase + ldOffB,      Bg + p * 32);
            cp_async16(sm_base + sbase + ldOffB + 16, Bg + p * 32 + 8);
        }
        cp_commit();
    }

    for (int kt = 0; kt < KT; kt++) {
        if (kt + 1 < KT) cp_wait<1>(); else cp_wait<0>();
        __syncthreads();

        if (kt + 2 < KT) {
            uint32_t sbase = (uint32_t)((kt + 2) % 3) * VSTAGE;
            cp_async16(sm_base + sbase + ldOffA,      Ag + (kt + 2) * 32);
            cp_async16(sm_base + sbase + ldOffA + 16, Ag + (kt + 2) * 32 + 8);
            if (tid < 64) {
                cp_async16(sm_base + sbase + ldOffB,      Bg + (kt + 2) * 32);
                cp_async16(sm_base + sbase + ldOffB + 16, Bg + (kt + 2) * 32 + 8);
            }
            cp_commit();
        }

        const uint32_t sb = sm_base + (uint32_t)(kt % 3) * VSTAGE;
        #pragma unroll
        for (int ks = 0; ks < 2; ks++) {
            uint32_t af[4];
            uint32_t bf[2][4];
            ldsm_x4(af, sb + (uint32_t)(a_row * HS + ks * 16 + a_k) * 2);
            #pragma unroll
            for (int ntp = 0; ntp < 2; ntp++)
                ldsm_x4(bf[ntp], sb + VST_A + (uint32_t)((ntp * 16 + b_row) * HS + ks * 16 + b_k) * 2);
            #pragma unroll
            for (int nt = 0; nt < 4; nt++) {
                uint32_t b0 = (nt & 1) ? bf[nt >> 1][2] : bf[nt >> 1][0];
                uint32_t b1 = (nt & 1) ? bf[nt >> 1][3] : bf[nt >> 1][1];
                mma_f16(c[nt], af, b0, b1);
            }
        }
        __syncthreads();
    }

    const int fr = lane >> 2;
    const int fc = lane & 3;
    #pragma unroll
    for (int nt = 0; nt < 4; nt++) {
        int row0 = m0 + wid * 16 + fr;
        int col  = h * 32 + nt * 8 + fc * 2;
        __half2 h0 = __floats2half2_rn(c[nt][0], c[nt][1]);
        __half2 h1 = __floats2half2_rn(c[nt][2], c[nt][3]);
        *reinterpret_cast<__half2*>(out + (size_t)row0 * 256 + col)       = h0;
        *reinterpret_cast<__half2*>(out + (size_t)(row0 + 8) * 256 + col) = h1;
    }
}

// ---------------- launcher ----------------
extern "C" void kernel_launch(void* const* d_in, const int* in_sizes, int n_in,
                              void* d_out, int out_size) {
    const float* x_anc = (const float*)d_in[0];
    const float* x_nei = (const float*)d_in[1];
    const float* W_q   = (const float*)d_in[2];
    const float* W_k   = (const float*)d_in[3];
    const float* W_v   = (const float*)d_in[4];
    const float* W_o   = (const float*)d_in[5];
    const float* ln1_g = (const float*)d_in[6];
    const float* ln1_b = (const float*)d_in[7];
    const float* ln2_g = (const float*)d_in[8];
    const float* ln2_b = (const float*)d_in[9];
    const float* ff1_w = (const float*)d_in[10];
    const float* ff1_b = (const float*)d_in[11];
    const float* ff2_w = (const float*)d_in[12];
    const float* ff2_b = (const float*)d_in[13];
    float* out = (float*)d_out;

    __half *p_lnx, *p_qh, *p_qt, *p_ctx, *p_att, *p_xh, *p_h, *p_ff;
    __half *p_wkh, *p_wtq, *p_wto, *p_wtv, *p_wt1, *p_wt2;
    cudaGetSymbolAddress((void**)&p_lnx, g_lnx);
    cudaGetSymbolAddress((void**)&p_qh,  g_qh);
    cudaGetSymbolAddress((void**)&p_qt,  g_qt);
    cudaGetSymbolAddress((void**)&p_ctx, g_ctx);
    cudaGetSymbolAddress((void**)&p_att, g_att);
    cudaGetSymbolAddress((void**)&p_xh,  g_xh);
    cudaGetSymbolAddress((void**)&p_h,   g_h);
    cudaGetSymbolAddress((void**)&p_ff,  g_ff);
    cudaGetSymbolAddress((void**)&p_wkh, g_wkh);
    cudaGetSymbolAddress((void**)&p_wtq, g_wtq);
    cudaGetSymbolAddress((void**)&p_wto, g_wto);
    cudaGetSymbolAddress((void**)&p_wtv, g_wtv);
    cudaGetSymbolAddress((void**)&p_wt1, g_wt1);
    cudaGetSymbolAddress((void**)&p_wt2, g_wt2);

    cudaFuncSetAttribute(hgemm<1>, cudaFuncAttributeMaxDynamicSharedMemorySize, HGEMM_SMEM);
    cudaFuncSetAttribute(hgemm<2>, cudaFuncAttributeMaxDynamicSharedMemorySize, HGEMM_SMEM);
    cudaFuncSetAttribute(hgemm<3>, cudaFuncAttributeMaxDynamicSharedMemorySize, HGEMM_SMEM);
    cudaFuncSetAttribute(hgemm<4>, cudaFuncAttributeMaxDynamicSharedMemorySize, HGEMM_SMEM);

    dim3 lnBlock(32, 8);
    dim3 tBlock(32, 8);

    // 0: weight prep (Wq^T, Wo^T, Wv^T, Wk->half) in one launch
    wprep_kernel<<<dim3(8, 8, 4), tBlock>>>(W_q, W_o, W_v, W_k, p_wtq, p_wto, p_wtv, p_wkh);
    // 1: LN1 -> half
    ln_kernel<<<BN / 8, lnBlock>>>(x_anc, ln1_g, ln1_b, p_lnx);
    // 2: transpose ff1
    transpose_kernel<<<dim3(32, 8), tBlock>>>(ff1_w, p_wt1, 256, 1024);
    // 3: Q = LN1 @ W_q (half out)  [PROFILED SLOT]
    hgemm<4><<<dim3(2, BN / 128), 256, HGEMM_SMEM>>>(p_lnx, p_wtq, p_qh, BN, DIM, DIM, nullptr, nullptr);
    // 4: q~ via tensor cores
    qtilde_tc<<<dim3(BN / 128, 16), 256>>>(p_qh, p_wkh, p_qt);
    // 5: attention core -> ctx (half)
    attn_kernel<<<BN, 256>>>(x_nei, p_qt, p_ctx);
    // 6: att = ctx @ W_v (tensor cores, per head)
    vproj_tc<<<dim3(BN / 128, NH), 256, VPROJ_SMEM>>>(p_ctx, p_wtv, p_att);
    // 7: x = x_anc + att @ W_o (half out)
    hgemm<3><<<dim3(2, BN / 128), 256, HGEMM_SMEM>>>(p_att, p_wto, p_xh, BN, DIM, DIM, nullptr, x_anc);
    // 8: LN2 (half in) -> half
    ln_half_kernel<<<BN / 8, lnBlock>>>(p_xh, ln2_g, ln2_b, p_h);
    // 9: transpose ff2
    transpose_kernel<<<dim3(8, 32), tBlock>>>(ff2_w, p_wt2, 1024, 256);
    // 10: ff = gelu(h @ ff1 + b1)
    hgemm<1><<<dim3(8, BN / 128), 256, HGEMM_SMEM>>>(p_h, p_wt1, p_ff, BN, NFF, DIM, ff1_b, nullptr);
    // 11: out = x + ff @ ff2 + b2 (half resid, f32 out)
    hgemm<2><<<dim3(2, BN / 128), 256, HGEMM_SMEM>>>(p_ff, p_wt2, out, BN, DIM, NFF, ff2_b, p_xh);
}

// round 15
// speedup vs baseline: 1.3681x; 1.0128x over previous
#include <cuda_runtime.h>
#include <cuda_fp16.h>
#include <math.h>
#include <stdint.h>

// Problem constants
#define BN  32768
#define DIM 256
#define NK  32
#define NH  8
#define NFF 1024
#define NDK 32

// ---------------- scratch (device globals: allocation-guard-safe) ----------------
__device__ __align__(128) __half g_lnx[BN * DIM];       // LN1(x_anc), half
__device__ __align__(128) __half g_qh[BN * DIM];        // Q, half
__device__ __align__(128) __half g_qt[BN * NH * DIM];   // q~ [B, H, 256], half
__device__ __align__(128) __half g_ctx[BN * NH * DIM];  // ctx [B, H, 256], half
__device__ __align__(128) __half g_att[BN * DIM];       // attention out (pre-W_o), half
__device__ __align__(128) __half g_xh[BN * DIM];        // x = x_anc + att @ W_o, half
__device__ __align__(128) __half g_h[BN * DIM];         // LN2(x), half
__device__ __align__(128) __half g_ff[BN * NFF];        // gelu(h@ff1+b1), half
// half weights
__device__ __align__(128) __half g_wkh[DIM * DIM];      // Wk as half (same layout)
__device__ __align__(128) __half g_wtq[DIM * DIM];
__device__ __align__(128) __half g_wto[DIM * DIM];
__device__ __align__(128) __half g_wtv[DIM * DIM];      // Wv^T
__device__ __align__(128) __half g_wt1[DIM * NFF];
__device__ __align__(128) __half g_wt2[NFF * DIM];

// ---------------- LayerNorm (fp32 input): one warp per row, half output ----------------
__global__ void ln_kernel(const float* __restrict__ x, const float* __restrict__ g,
                          const float* __restrict__ b, __half* __restrict__ out) {
    int row  = blockIdx.x * 8 + threadIdx.y;
    int lane = threadIdx.x;
    const float4* xr = reinterpret_cast<const float4*>(x + (size_t)row * DIM);
    float4 v0 = xr[lane];
    float4 v1 = xr[lane + 32];
    float s  = v0.x + v0.y + v0.z + v0.w + v1.x + v1.y + v1.z + v1.w;
    float ss = v0.x*v0.x + v0.y*v0.y + v0.z*v0.z + v0.w*v0.w
             + v1.x*v1.x + v1.y*v1.y + v1.z*v1.z + v1.w*v1.w;
    #pragma unroll
    for (int o = 16; o; o >>= 1) {
        s  += __shfl_xor_sync(0xFFFFFFFFu, s,  o);
        ss += __shfl_xor_sync(0xFFFFFFFFu, ss, o);
    }
    float mu  = s * (1.0f / 256.0f);
    float var = ss * (1.0f / 256.0f) - mu * mu;
    float rs  = rsqrtf(var + 1e-5f);
    const float4* g4 = reinterpret_cast<const float4*>(g);
    const float4* b4 = reinterpret_cast<const float4*>(b);
    __half* orow = out + (size_t)row * DIM;
    #pragma unroll
    for (int p = 0; p < 2; p++) {
        int idx = lane + p * 32;
        float4 v = (p == 0) ? v0 : v1;
        float4 gg = g4[idx], bb = b4[idx];
        float o0 = (v.x - mu) * rs * gg.x + bb.x;
        float o1 = (v.y - mu) * rs * gg.y + bb.y;
        float o2 = (v.z - mu) * rs * gg.z + bb.z;
        float o3 = (v.w - mu) * rs * gg.w + bb.w;
        __half2 ha = __floats2half2_rn(o0, o1);
        __half2 hb = __floats2half2_rn(o2, o3);
        uint2 u;
        u.x = *reinterpret_cast<uint32_t*>(&ha);
        u.y = *reinterpret_cast<uint32_t*>(&hb);
        *reinterpret_cast<uint2*>(orow + idx * 4) = u;
    }
}

// ---------------- LayerNorm (half input): one warp per row, half output ----------------
__global__ void ln_half_kernel(const __half* __restrict__ x, const float* __restrict__ g,
                               const float* __restrict__ b, __half* __restrict__ out) {
    int row  = blockIdx.x * 8 + threadIdx.y;
    int lane = threadIdx.x;
    const uint4* xr = reinterpret_cast<const uint4*>(x + (size_t)row * DIM);
    uint4 u = xr[lane];   // 8 halves
    float v[8];
    {
        float2 f0 = __half22float2(*reinterpret_cast<__half2*>(&u.x));
        float2 f1 = __half22float2(*reinterpret_cast<__half2*>(&u.y));
        float2 f2 = __half22float2(*reinterpret_cast<__half2*>(&u.z));
        float2 f3 = __half22float2(*reinterpret_cast<__half2*>(&u.w));
        v[0]=f0.x; v[1]=f0.y; v[2]=f1.x; v[3]=f1.y;
        v[4]=f2.x; v[5]=f2.y; v[6]=f3.x; v[7]=f3.y;
    }
    float s = 0.f, ss = 0.f;
    #pragma unroll
    for (int i = 0; i < 8; i++) { s += v[i]; ss += v[i] * v[i]; }
    #pragma unroll
    for (int o = 16; o; o >>= 1) {
        s  += __shfl_xor_sync(0xFFFFFFFFu, s,  o);
        ss += __shfl_xor_sync(0xFFFFFFFFu, ss, o);
    }
    float mu  = s * (1.0f / 256.0f);
    float var = ss * (1.0f / 256.0f) - mu * mu;
    float rs  = rsqrtf(var + 1e-5f);
    const float4* g4 = reinterpret_cast<const float4*>(g);
    const float4* b4 = reinterpret_cast<const float4*>(b);
    float4 ga = g4[lane * 2], gb = g4[lane * 2 + 1];
    float4 ba = b4[lane * 2], bb = b4[lane * 2 + 1];
    float o0 = (v[0]-mu)*rs*ga.x + ba.x;
    float o1 = (v[1]-mu)*rs*ga.y + ba.y;
    float o2 = (v[2]-mu)*rs*ga.z + ba.z;
    float o3 = (v[3]-mu)*rs*ga.w + ba.w;
    float o4 = (v[4]-mu)*rs*gb.x + bb.x;
    float o5 = (v[5]-mu)*rs*gb.y + bb.y;
    float o6 = (v[6]-mu)*rs*gb.z + bb.z;
    float o7 = (v[7]-mu)*rs*gb.w + bb.w;
    __half2 h0 = __floats2half2_rn(o0, o1);
    __half2 h1 = __floats2half2_rn(o2, o3);
    __half2 h2 = __floats2half2_rn(o4, o5);
    __half2 h3 = __floats2half2_rn(o6, o7);
    uint4 ou;
    ou.x = *reinterpret_cast<uint32_t*>(&h0);
    ou.y = *reinterpret_cast<uint32_t*>(&h1);
    ou.z = *reinterpret_cast<uint32_t*>(&h2);
    ou.w = *reinterpret_cast<uint32_t*>(&h3);
    *reinterpret_cast<uint4*>(out + (size_t)row * DIM + lane * 8) = ou;
}

__device__ __forceinline__ float gelu_exact(float v) {
    return 0.5f * v * (1.0f + erff(v * 0.70710678118654752f));
}

// ---------------- weight prep: z=0..2 transpose {Wq,Wo,Wv}; z=3 copy-convert Wk ----------------
__global__ void wprep_kernel(const float* __restrict__ Wq, const float* __restrict__ Wo,
                             const float* __restrict__ Wv, const float* __restrict__ Wk,
                             __half* __restrict__ wtq, __half* __restrict__ wto,
                             __half* __restrict__ wtv, __half* __restrict__ wkh) {
    __shared__ float t[32][33];
    int z = blockIdx.z;
    const float* in = (z == 0) ? Wq : (z == 1) ? Wo : (z == 2) ? Wv : Wk;
    __half* out     = (z == 0) ? wtq : (z == 1) ? wto : (z == 2) ? wtv : wkh;
    int c0 = blockIdx.x * 32, r0 = blockIdx.y * 32;
    int tx = threadIdx.x, ty = threadIdx.y;   // (32, 8)
    if (z < 3) {
        #pragma unroll
        for (int j = 0; j < 4; j++)
            t[ty + j * 8][tx] = in[(size_t)(r0 + ty + j * 8) * 256 + c0 + tx];
        __syncthreads();
        #pragma unroll
        for (int j = 0; j < 4; j++)
            out[(size_t)(c0 + ty + j * 8) * 256 + r0 + tx] = __float2half_rn(t[tx][ty + j * 8]);
    } else {
        #pragma unroll
        for (int j = 0; j < 4; j++) {
            size_t idx = (size_t)(r0 + ty + j * 8) * 256 + c0 + tx;
            out[idx] = __float2half_rn(in[idx]);
        }
    }
}

// ---------------- transpose+convert (rectangular weights) ----------------
__global__ void transpose_kernel(const float* __restrict__ in, __half* __restrict__ out,
                                 int R, int C) {
    __shared__ float t[32][33];
    int c0 = blockIdx.x * 32, r0 = blockIdx.y * 32;
    int tx = threadIdx.x, ty = threadIdx.y;   // (32, 8)
    #pragma unroll
    for (int j = 0; j < 4; j++)
        t[ty + j * 8][tx] = in[(size_t)(r0 + ty + j * 8) * C + c0 + tx];
    __syncthreads();
    #pragma unroll
    for (int j = 0; j < 4; j++)
        out[(size_t)(c0 + ty + j * 8) * R + r0 + tx] = __float2half_rn(t[tx][ty + j * 8]);
}

// ---------------- shared helpers ----------------
__device__ __forceinline__ uint32_t smem_u32(const void* p) {
    uint32_t a;
    asm("{ .reg .u64 t; cvta.to.shared.u64 t, %1; cvt.u32.u64 %0, t; }" : "=r"(a) : "l"(p));
    return a;
}
__device__ __forceinline__ void ldsm_x4(uint32_t r[4], uint32_t addr) {
    asm volatile("ldmatrix.sync.aligned.m8n8.x4.shared.b16 {%0,%1,%2,%3}, [%4];"
                 : "=r"(r[0]), "=r"(r[1]), "=r"(r[2]), "=r"(r[3]) : "r"(addr));
}
__device__ __forceinline__ void ldsm_x4_trans(uint32_t r[4], uint32_t addr) {
    asm volatile("ldmatrix.sync.aligned.m8n8.x4.trans.shared.b16 {%0,%1,%2,%3}, [%4];"
                 : "=r"(r[0]), "=r"(r[1]), "=r"(r[2]), "=r"(r[3]) : "r"(addr));
}
__device__ __forceinline__ void ldsm_x2(uint32_t r[2], uint32_t addr) {
    asm volatile("ldmatrix.sync.aligned.m8n8.x2.shared.b16 {%0,%1}, [%2];"
                 : "=r"(r[0]), "=r"(r[1]) : "r"(addr));
}
__device__ __forceinline__ void mma_f16(float c[4], const uint32_t a[4],
                                        uint32_t b0, uint32_t b1) {
    asm volatile(
        "mma.sync.aligned.m16n8k16.row.col.f32.f16.f16.f32 "
        "{%0,%1,%2,%3}, {%4,%5,%6,%7}, {%8,%9}, {%0,%1,%2,%3};\n"
        : "+f"(c[0]), "+f"(c[1]), "+f"(c[2]), "+f"(c[3])
        : "r"(a[0]), "r"(a[1]), "r"(a[2]), "r"(a[3]), "r"(b0), "r"(b1));
}
__device__ __forceinline__ void cp_async16(uint32_t dst, const void* src) {
    asm volatile("cp.async.cg.shared.global [%0], [%1], 16;\n" :: "r"(dst), "l"(src));
}
__device__ __forceinline__ void cp_commit() {
    asm volatile("cp.async.commit_group;\n" ::: "memory");
}
template <int N>
__device__ __forceinline__ void cp_wait() {
    asm volatile("cp.async.wait_group %0;\n" :: "n"(N) : "memory");
}

// ================= fp16 tensor-core GEMM: 128x128, 4-stage cp.async pipeline =================
#define HS 40
#define STAGE_BYTES (128 * HS * 2)          // one A or B buffer: 10240 B
#define HGEMM_SMEM (8 * STAGE_BYTES)        // 4 stages x (A + B) = 81920 B

// MODE 1: gelu(A@B+bias) -> half     MODE 2: A@B + bias + HALF resid -> f32
// MODE 3: A@B + F32 resid -> half    MODE 4: A@B -> half
template <int MODE>
__global__ __launch_bounds__(256, 2)
void hgemm(const __half* __restrict__ A, const __half* __restrict__ BT,
           void* __restrict__ Cout, int M, int N, int Kd,
           const float* __restrict__ bias, const void* __restrict__ resid) {
    extern __shared__ __half hsm[];
    const uint32_t sm_base = smem_u32(hsm);

    const int tid  = threadIdx.x;
    const int lane = tid & 31;
    const int wid  = tid >> 5;
    const int m0 = blockIdx.y * 128;
    const int n0 = blockIdx.x * 128;
    const int warp_m = (wid & 1) * 64;
    const int warp_n = (wid >> 1) * 32;

    const int ldRow = tid >> 1;
    const int ldCol = (tid & 1) * 16;
    const __half* Ag = A  + (size_t)(m0 + ldRow) * Kd + ldCol;
    const __half* Bg = BT + (size_t)(n0 + ldRow) * Kd + ldCol;
    const uint32_t ldOffA = (uint32_t)(ldRow * HS + ldCol) * 2;
    const uint32_t ldOffB = ldOffA + STAGE_BYTES;

    float c[4][4][4];
    #pragma unroll
    for (int mt = 0; mt < 4; mt++)
        #pragma unroll
        for (int nt = 0; nt < 4; nt++)
            #pragma unroll
            for (int i = 0; i < 4; i++) c[mt][nt][i] = 0.0f;

    const int a_row = warp_m + (lane & 7) + ((lane >> 3) & 1) * 8;
    const int a_k   = (lane >> 4) * 8;
    const int b_row = warp_n + (lane & 7) + ((lane >> 4) & 1) * 8;
    const int b_k   = ((lane >> 3) & 1) * 8;
    const uint32_t aAddr0 = sm_base + (uint32_t)(a_row * HS + a_k) * 2;
    const uint32_t bAddr0 = sm_base + STAGE_BYTES + (uint32_t)(b_row * HS + b_k) * 2;

    const int KT = Kd >> 5;

    // prologue: async-load chunks 0..2
    #pragma unroll
    for (int p = 0; p < 3; p++) {
        if (p < KT) {
            uint32_t sbase = (uint32_t)p * (2 * STAGE_BYTES);
            const __half* Ap = Ag + p * 32;
            const __half* Bp = Bg + p * 32;
            cp_async16(sm_base + sbase + ldOffA,      Ap);
            cp_async16(sm_base + sbase + ldOffA + 16, Ap + 8);
            cp_async16(sm_base + sbase + ldOffB,      Bp);
            cp_async16(sm_base + sbase + ldOffB + 16, Bp + 8);
        }
        cp_commit();
    }

    for (int kt = 0; kt < KT; kt++) {
        // ensure chunk kt has landed (up to 2 younger groups outstanding)
        if (kt + 3 <= KT - 1)      cp_wait<2>();
        else if (kt + 2 <= KT - 1) cp_wait<1>();
        else                       cp_wait<0>();
        __syncthreads();   // single barrier: orders prior-iter reads before stage overwrite

        if (kt + 3 < KT) {
            uint32_t sbase = (uint32_t)((kt + 3) & 3) * (2 * STAGE_BYTES);
            const __half* Ap = Ag + (kt + 3) * 32;
            const __half* Bp = Bg + (kt + 3) * 32;
            cp_async16(sm_base + sbase + ldOffA,      Ap);
            cp_async16(sm_base + sbase + ldOffA + 16, Ap + 8);
            cp_async16(sm_base + sbase + ldOffB,      Bp);
            cp_async16(sm_base + sbase + ldOffB + 16, Bp + 8);
            cp_commit();
        } else {
            cp_commit();   // keep group count aligned with wait schedule
        }

        const uint32_t bo = (uint32_t)(kt & 3) * (2 * STAGE_BYTES);
        #pragma unroll
        for (int ks = 0; ks < 2; ks++) {
            uint32_t af[4][4];
            uint32_t bf[2][4];
            #pragma unroll
            for (int mt = 0; mt < 4; mt++)
                ldsm_x4(af[mt], aAddr0 + bo + (uint32_t)(mt * 16 * HS + ks * 16) * 2);
            #pragma unroll
            for (int ntp = 0; ntp < 2; ntp++)
                ldsm_x4(bf[ntp], bAddr0 + bo + (uint32_t)(ntp * 16 * HS + ks * 16) * 2);
            #pragma unroll
            for (int mt = 0; mt < 4; mt++) {
                #pragma unroll
                for (int nt = 0; nt < 4; nt++) {
                    uint32_t b0 = (nt & 1) ? bf[nt >> 1][2] : bf[nt >> 1][0];
                    uint32_t b1 = (nt & 1) ? bf[nt >> 1][3] : bf[nt >> 1][1];
                    mma_f16(c[mt][nt], af[mt], b0, b1);
                }
            }
        }
    }

    const int fr = lane >> 2;
    const int fc = lane & 3;
    #pragma unroll
    for (int mt = 0; mt < 4; mt++) {
        #pragma unroll
        for (int nt = 0; nt < 4; nt++) {
            int row0 = m0 + warp_m + mt * 16 + fr;
            int col  = n0 + warp_n + nt * 8 + fc * 2;
            float v0 = c[mt][nt][0], v1 = c[mt][nt][1];
            float v2 = c[mt][nt][2], v3 = c[mt][nt][3];
            if (MODE == 1 || MODE == 2) {
                float2 bv = *reinterpret_cast<const float2*>(bias + col);
                v0 += bv.x; v1 += bv.y; v2 += bv.x; v3 += bv.y;
            }
            if (MODE == 1) {
                v0 = gelu_exact(v0); v1 = gelu_exact(v1);
                v2 = gelu_exact(v2); v3 = gelu_exact(v3);
            }
            if (MODE == 2) {   // half resid
                const __half* rh = reinterpret_cast<const __half*>(resid);
                float2 f0 = __half22float2(*reinterpret_cast<const __half2*>(rh + (size_t)row0 * N + col));
                float2 f1 = __half22float2(*reinterpret_cast<const __half2*>(rh + (size_t)(row0 + 8) * N + col));
                v0 += f0.x; v1 += f0.y; v2 += f1.x; v3 += f1.y;
            }
            if (MODE == 3) {   // fp32 resid
                const float* rf = reinterpret_cast<const float*>(resid);
                float2 r0 = *reinterpret_cast<const float2*>(rf + (size_t)row0 * N + col);
                float2 r1 = *reinterpret_cast<const float2*>(rf + (size_t)(row0 + 8) * N + col);
                v0 += r0.x; v1 += r0.y; v2 += r1.x; v3 += r1.y;
            }
            if (MODE == 1 || MODE == 3 || MODE == 4) {
                __half* Ch = reinterpret_cast<__half*>(Cout);
                __half2 h0 = __floats2half2_rn(v0, v1);
                __half2 h1 = __floats2half2_rn(v2, v3);
                *reinterpret_cast<__half2*>(Ch + (size_t)row0 * N + col)       = h0;
                *reinterpret_cast<__half2*>(Ch + (size_t)(row0 + 8) * N + col) = h1;
            } else {
                float* Cf = reinterpret_cast<float*>(Cout);
                *reinterpret_cast<float2*>(Cf + (size_t)row0 * N + col)       = make_float2(v0, v1);
                *reinterpret_cast<float2*>(Cf + (size_t)(row0 + 8) * N + col) = make_float2(v2, v3);
            }
        }
    }
}

// ---------------- qtilde via tensor cores ----------------
__global__ __launch_bounds__(256)
void qtilde_tc(const __half* __restrict__ Q, const __half* __restrict__ Wkh,
               __half* __restrict__ qt) {
    __shared__ __half As[128][HS];
    __shared__ __half Bs[128][HS];

    const int tid  = threadIdx.x;
    const int lane = tid & 31;
    const int wid  = tid >> 5;
    const int m0   = blockIdx.x * 128;
    const int head = blockIdx.y >> 1;
    const int n0   = (blockIdx.y & 1) * 128;
    const int warp_m = (wid & 1) * 64;
    const int warp_n = (wid >> 1) * 32;

    const int ldRow = tid >> 1;
    const int ldCol = (tid & 1) * 16;
    {
        const __half* Ag = Q   + (size_t)(m0 + ldRow) * 256 + head * 32 + ldCol;
        const __half* Bg = Wkh + (size_t)(n0 + ldRow) * 256 + head * 32 + ldCol;
        *reinterpret_cast<uint4*>(&As[ldRow][ldCol])     = *reinterpret_cast<const uint4*>(Ag);
        *reinterpret_cast<uint4*>(&As[ldRow][ldCol + 8]) = *reinterpret_cast<const uint4*>(Ag + 8);
        *reinterpret_cast<uint4*>(&Bs[ldRow][ldCol])     = *reinterpret_cast<const uint4*>(Bg);
        *reinterpret_cast<uint4*>(&Bs[ldRow][ldCol + 8]) = *reinterpret_cast<const uint4*>(Bg + 8);
    }
    __syncthreads();

    float c[4][4][4];
    #pragma unroll
    for (int mt = 0; mt < 4; mt++)
        #pragma unroll
        for (int nt = 0; nt < 4; nt++)
            #pragma unroll
            for (int i = 0; i < 4; i++) c[mt][nt][i] = 0.0f;

    const uint32_t as_base = smem_u32(&As[0][0]);
    const uint32_t bs_base = smem_u32(&Bs[0][0]);
    const int a_row = warp_m + (lane & 7) + ((lane >> 3) & 1) * 8;
    const int a_k   = (lane >> 4) * 8;
    const int b_row = warp_n + (lane & 7) + ((lane >> 4) & 1) * 8;
    const int b_k   = ((lane >> 3) & 1) * 8;
    const uint32_t aAddr0 = as_base + (uint32_t)(a_row * HS + a_k) * 2;
    const uint32_t bAddr0 = bs_base + (uint32_t)(b_row * HS + b_k) * 2;

    #pragma unroll
    for (int ks = 0; ks < 2; ks++) {
        uint32_t af[4][4];
        uint32_t bf[2][4];
        #pragma unroll
        for (int mt = 0; mt < 4; mt++)
            ldsm_x4(af[mt], aAddr0 + (uint32_t)(mt * 16 * HS + ks * 16) * 2);
        #pragma unroll
        for (int ntp = 0; ntp < 2; ntp++)
            ldsm_x4(bf[ntp], bAddr0 + (uint32_t)(ntp * 16 * HS + ks * 16) * 2);
        #pragma unroll
        for (int mt = 0; mt < 4; mt++) {
            #pragma unroll
            for (int nt = 0; nt < 4; nt++) {
                uint32_t b0 = (nt & 1) ? bf[nt >> 1][2] : bf[nt >> 1][0];
                uint32_t b1 = (nt & 1) ? bf[nt >> 1][3] : bf[nt >> 1][1];
                mma_f16(c[mt][nt], af[mt], b0, b1);
            }
        }
    }

    const int fr = lane >> 2;
    const int fc = lane & 3;
    #pragma unroll
    for (int mt = 0; mt < 4; mt++) {
        #pragma unroll
        for (int nt = 0; nt < 4; nt++) {
            int row0 = m0 + warp_m + mt * 16 + fr;
            int col  = head * 256 + n0 + warp_n + nt * 8 + fc * 2;
            __half2 h0 = __floats2half2_rn(c[mt][nt][0], c[mt][nt][1]);
            __half2 h1 = __floats2half2_rn(c[mt][nt][2], c[mt][nt][3]);
            *reinterpret_cast<__half2*>(qt + (size_t)row0 * 2048 + col)       = h0;
            *reinterpret_cast<__half2*>(qt + (size_t)(row0 + 8) * 2048 + col) = h1;
        }
    }
}

// ---------------- attention core (R10): tensor-core phases ----------------
#define XS_S 264
#define QS_S 264
#define AT_S 40
#define CT_S 264
__global__ __launch_bounds__(256)
void attn_kernel(const float* __restrict__ xnei, const __half* __restrict__ qt,
                 __half* __restrict__ ctx) {
    __shared__ __half xs[32 * XS_S];
    __shared__ __half qts[8 * QS_S];
    __shared__ float  sred[8 * 256];
    __shared__ __half attns_h[8 * AT_S];
    __shared__ __half ctx_t[8 * CT_S];
    int b    = blockIdx.x;
    int tid  = threadIdx.x;
    int lane = tid & 31;
    int w    = tid >> 5;

    const float4* xb4 = reinterpret_cast<const float4*>(xnei + (size_t)b * 8192);
    #pragma unroll
    for (int j = 0; j < 8; j++) {
        int i  = tid + j * 256;
        int k  = i >> 6;
        int c4 = i & 63;
        float4 v = xb4[i];
        __half2 h0 = __floats2half2_rn(v.x, v.y);
        __half2 h1 = __floats2half2_rn(v.z, v.w);
        uint2 u;
        u.x = *reinterpret_cast<uint32_t*>(&h0);
        u.y = *reinterpret_cast<uint32_t*>(&h1);
        *reinterpret_cast<uint2*>(xs + k * XS_S + c4 * 4) = u;
    }
    {
        const uint4* qp = reinterpret_cast<const uint4*>(qt + (size_t)b * 2048);
        int h  = tid >> 5;
        int c8 = tid & 31;
        *reinterpret_cast<uint4*>(qts + h * QS_S + c8 * 8) = qp[tid];
    }
    __syncthreads();

    const uint32_t xs_base = smem_u32(xs);
    const uint32_t qs_base = smem_u32(qts);
    const uint32_t at_base = smem_u32(attns_h);
    const int fr = lane >> 2;
    const int fc = lane & 3;

    {
        float sacc[2][4];
        #pragma unroll
        for (int mt = 0; mt < 2; mt++)
            #pragma unroll
            for (int i = 0; i < 4; i++) sacc[mt][i] = 0.0f;
        const int a_row = (lane & 7) + ((lane >> 3) & 1) * 8;
        const int a_kof = (lane >> 4) * 8;
        const int b_row = lane & 7;
        const int b_kof = ((lane >> 3) & 1) * 8;
        #pragma unroll
        for (int ks = 0; ks < 2; ks++) {
            uint32_t bq[2];
            ldsm_x2(bq, qs_base + (uint32_t)(b_row * QS_S + w * 32 + ks * 16 + b_kof) * 2);
            #pragma unroll
            for (int mt = 0; mt < 2; mt++) {
                uint32_t af[4];
                ldsm_x4(af, xs_base + (uint32_t)((mt * 16 + a_row) * XS_S + w * 32 + ks * 16 + a_kof) * 2);
                mma_f16(sacc[mt], af, bq[0], bq[1]);
            }
        }
        #pragma unroll
        for (int mt = 0; mt < 2; mt++) {
            int krow = mt * 16 + fr;
            *reinterpret_cast<float2*>(&sred[w * 256 + krow * 8 + fc * 2]) =
                make_float2(sacc[mt][0], sacc[mt][1]);
            *reinterpret_cast<float2*>(&sred[w * 256 + (krow + 8) * 8 + fc * 2]) =
                make_float2(sacc[mt][2], sacc[mt][3]);
        }
    }
    __syncthreads();

    {
        float sc = 0.0f;
        #pragma unroll
        for (int ww = 0; ww < 8; ww++)
            sc += sred[ww * 256 + lane * 8 + w];
        sc *= 0.17677669529663687f;
        float m = sc;
        #pragma unroll
        for (int o = 16; o; o >>= 1) m = fmaxf(m, __shfl_xor_sync(0xFFFFFFFFu, m, o));
        float e = expf(sc - m);
        float s = e;
        #pragma unroll
        for (int o = 16; o; o >>= 1) s += __shfl_xor_sync(0xFFFFFFFFu, s, o);
        attns_h[w * AT_S + lane] = __float2half_rn(e / s);
    }
    __syncthreads();

    {
        float cacc[2][4];
        #pragma unroll
        for (int mt = 0; mt < 2; mt++)
            #pragma unroll
            for (int i = 0; i < 4; i++) cacc[mt][i] = 0.0f;
        const int t_krow = ((lane >> 4) & 1) * 8 + (lane & 7);
        const int t_dof  = ((lane >> 3) & 1) * 8;
        const int b_row = lane & 7;
        const int b_kof = ((lane >> 3) & 1) * 8;
        #pragma unroll
        for (int ks = 0; ks < 2; ks++) {
            uint32_t bp[2];
            ldsm_x2(bp, at_base + (uint32_t)(b_row * AT_S + ks * 16 + b_kof) * 2);
            #pragma unroll
            for (int mt = 0; mt < 2; mt++) {
                int d0 = w * 32 + mt * 16;
                uint32_t af[4];
                ldsm_x4_trans(af, xs_base + (uint32_t)((ks * 16 + t_krow) * XS_S + d0 + t_dof) * 2);
                mma_f16(cacc[mt], af, bp[0], bp[1]);
            }
        }
        #pragma unroll
        for (int mt = 0; mt < 2; mt++) {
            int d0 = w * 32 + mt * 16;
            ctx_t[(fc * 2 + 0) * CT_S + d0 + fr]     = __float2half_rn(cacc[mt][0]);
            ctx_t[(fc * 2 + 1) * CT_S + d0 + fr]     = __float2half_rn(cacc[mt][1]);
            ctx_t[(fc * 2 + 0) * CT_S + d0 + fr + 8] = __float2half_rn(cacc[mt][2]);
            ctx_t[(fc * 2 + 1) * CT_S + d0 + fr + 8] = __float2half_rn(cacc[mt][3]);
        }
    }
    __syncthreads();

    {
        uint4 u = *reinterpret_cast<const uint4*>(&ctx_t[w * CT_S + lane * 8]);
        *reinterpret_cast<uint4*>(&ctx[(size_t)b * 2048 + w * 256 + lane * 8]) = u;
    }
}

// ---------------- vproj via tensor cores: 4-stage cp.async pipeline ----------------
#define VST_A (128 * HS * 2)     // 10240
#define VST_B (32 * HS * 2)      // 2560
#define VSTAGE (VST_A + VST_B)
#define VPROJ_SMEM (4 * VSTAGE)  // 51200
__global__ __launch_bounds__(256)
void vproj_tc(const __half* __restrict__ ctx, const __half* __restrict__ WvT,
              __half* __restrict__ out) {
    extern __shared__ __half vsm[];
    const uint32_t sm_base = smem_u32(vsm);
    const int tid  = threadIdx.x;
    const int lane = tid & 31;
    const int wid  = tid >> 5;
    const int m0 = blockIdx.x * 128;
    const int h  = blockIdx.y;

    const int aRow = tid >> 1;
    const int aCol = (tid & 1) * 16;
    const __half* Ag = ctx + (size_t)(m0 + aRow) * 2048 + h * 256 + aCol;
    const uint32_t ldOffA = (uint32_t)(aRow * HS + aCol) * 2;
    const __half* Bg = WvT + (size_t)(h * 32 + (tid >> 1)) * 256 + aCol;   // valid for tid<64
    const uint32_t ldOffB = VST_A + (uint32_t)((tid >> 1) * HS + aCol) * 2;

    float c[4][4];
    #pragma unroll
    for (int nt = 0; nt < 4; nt++)
        #pragma unroll
        for (int i = 0; i < 4; i++) c[nt][i] = 0.0f;

    const int a_row = wid * 16 + (lane & 7) + ((lane >> 3) & 1) * 8;
    const int a_k   = (lane >> 4) * 8;
    const int b_row = (lane & 7) + ((lane >> 4) & 1) * 8;
    const int b_k   = ((lane >> 3) & 1) * 8;

    const int KT = 8;   // 256 / 32
    #pragma unroll
    for (int p = 0; p < 3; p++) {
        uint32_t sbase = (uint32_t)p * VSTAGE;
        cp_async16(sm_base + sbase + ldOffA,      Ag + p * 32);
        cp_async16(sm_base + sbase + ldOffA + 16, Ag + p * 32 + 8);
        if (tid < 64) {
            cp_async16(sm_base + sbase + ldOffB,      Bg + p * 32);
            cp_async16(sm_base + sbase + ldOffB + 16, Bg + p * 32 + 8);
        }
        cp_commit();
    }

    for (int kt = 0; kt < KT; kt++) {
        if (kt + 3 <= KT - 1)      cp_wait<2>();
        else if (kt + 2 <= KT - 1) cp_wait<1>();
        else                       cp_wait<0>();
        __syncthreads();

        if (kt + 3 < KT) {
            uint32_t sbase = (uint32_t)((kt + 3) & 3) * VSTAGE;
            cp_async16(sm_base + sbase + ldOffA,      Ag + (kt + 3) * 32);
            cp_async16(sm_base + sbase + ldOffA + 16, Ag + (kt + 3) * 32 + 8);
            if (tid < 64) {
                cp_async16(sm_base + sbase + ldOffB,      Bg + (kt + 3) * 32);
                cp_async16(sm_base + sbase + ldOffB + 16, Bg + (kt + 3) * 32 + 8);
            }
            cp_commit();
        } else {
            cp_commit();
        }

        const uint32_t sb = sm_base + (uint32_t)(kt & 3) * VSTAGE;
        #pragma unroll
        for (int ks = 0; ks < 2; ks++) {
            uint32_t af[4];
            uint32_t bf[2][4];
            ldsm_x4(af, sb + (uint32_t)(a_row * HS + ks * 16 + a_k) * 2);
            #pragma unroll
            for (int ntp = 0; ntp < 2; ntp++)
                ldsm_x4(bf[ntp], sb + VST_A + (uint32_t)((ntp * 16 + b_row) * HS + ks * 16 + b_k) * 2);
            #pragma unroll
            for (int nt = 0; nt < 4; nt++) {
                uint32_t b0 = (nt & 1) ? bf[nt >> 1][2] : bf[nt >> 1][0];
                uint32_t b1 = (nt & 1) ? bf[nt >> 1][3] : bf[nt >> 1][1];
                mma_f16(c[nt], af, b0, b1);
            }
        }
    }

    const int fr = lane >> 2;
    const int fc = lane & 3;
    #pragma unroll
    for (int nt = 0; nt < 4; nt++) {
        int row0 = m0 + wid * 16 + fr;
        int col  = h * 32 + nt * 8 + fc * 2;
        __half2 h0 = __floats2half2_rn(c[nt][0], c[nt][1]);
        __half2 h1 = __floats2half2_rn(c[nt][2], c[nt][3]);
        *reinterpret_cast<__half2*>(out + (size_t)row0 * 256 + col)       = h0;
        *reinterpret_cast<__half2*>(out + (size_t)(row0 + 8) * 256 + col) = h1;
    }
}

// ---------------- launcher ----------------
extern "C" void kernel_launch(void* const* d_in, const int* in_sizes, int n_in,
                              void* d_out, int out_size) {
    const float* x_anc = (const float*)d_in[0];
    const float* x_nei = (const float*)d_in[1];
    const float* W_q   = (const float*)d_in[2];
    const float* W_k   = (const float*)d_in[3];
    const float* W_v   = (const float*)d_in[4];
    const float* W_o   = (const float*)d_in[5];
    const float* ln1_g = (const float*)d_in[6];
    const float* ln1_b = (const float*)d_in[7];
    const float* ln2_g = (const float*)d_in[8];
    const float* ln2_b = (const float*)d_in[9];
    const float* ff1_w = (const float*)d_in[10];
    const float* ff1_b = (const float*)d_in[11];
    const float* ff2_w = (const float*)d_in[12];
    const float* ff2_b = (const float*)d_in[13];
    float* out = (float*)d_out;

    __half *p_lnx, *p_qh, *p_qt, *p_ctx, *p_att, *p_xh, *p_h, *p_ff;
    __half *p_wkh, *p_wtq, *p_wto, *p_wtv, *p_wt1, *p_wt2;
    cudaGetSymbolAddress((void**)&p_lnx, g_lnx);
    cudaGetSymbolAddress((void**)&p_qh,  g_qh);
    cudaGetSymbolAddress((void**)&p_qt,  g_qt);
    cudaGetSymbolAddress((void**)&p_ctx, g_ctx);
    cudaGetSymbolAddress((void**)&p_att, g_att);
    cudaGetSymbolAddress((void**)&p_xh,  g_xh);
    cudaGetSymbolAddress((void**)&p_h,   g_h);
    cudaGetSymbolAddress((void**)&p_ff,  g_ff);
    cudaGetSymbolAddress((void**)&p_wkh, g_wkh);
    cudaGetSymbolAddress((void**)&p_wtq, g_wtq);
    cudaGetSymbolAddress((void**)&p_wto, g_wto);
    cudaGetSymbolAddress((void**)&p_wtv, g_wtv);
    cudaGetSymbolAddress((void**)&p_wt1, g_wt1);
    cudaGetSymbolAddress((void**)&p_wt2, g_wt2);

    cudaFuncSetAttribute(hgemm<1>, cudaFuncAttributeMaxDynamicSharedMemorySize, HGEMM_SMEM);
    cudaFuncSetAttribute(hgemm<2>, cudaFuncAttributeMaxDynamicSharedMemorySize, HGEMM_SMEM);
    cudaFuncSetAttribute(hgemm<3>, cudaFuncAttributeMaxDynamicSharedMemorySize, HGEMM_SMEM);
    cudaFuncSetAttribute(hgemm<4>, cudaFuncAttributeMaxDynamicSharedMemorySize, HGEMM_SMEM);
    cudaFuncSetAttribute(vproj_tc, cudaFuncAttributeMaxDynamicSharedMemorySize, VPROJ_SMEM);

    dim3 lnBlock(32, 8);
    dim3 tBlock(32, 8);

    // 0: weight prep (Wq^T, Wo^T, Wv^T, Wk->half) in one launch
    wprep_kernel<<<dim3(8, 8, 4), tBlock>>>(W_q, W_o, W_v, W_k, p_wtq, p_wto, p_wtv, p_wkh);
    // 1: LN1 -> half
    ln_kernel<<<BN / 8, lnBlock>>>(x_anc, ln1_g, ln1_b, p_lnx);
    // 2: transpose ff1
    transpose_kernel<<<dim3(32, 8), tBlock>>>(ff1_w, p_wt1, 256, 1024);
    // 3: Q = LN1 @ W_q (half out)  [PROFILED SLOT]
    hgemm<4><<<dim3(2, BN / 128), 256, HGEMM_SMEM>>>(p_lnx, p_wtq, p_qh, BN, DIM, DIM, nullptr, nullptr);
    // 4: q~ via tensor cores
    qtilde_tc<<<dim3(BN / 128, 16), 256>>>(p_qh, p_wkh, p_qt);
    // 5: attention core -> ctx (half)
    attn_kernel<<<BN, 256>>>(x_nei, p_qt, p_ctx);
    // 6: att = ctx @ W_v (tensor cores, per head)
    vproj_tc<<<dim3(BN / 128, NH), 256, VPROJ_SMEM>>>(p_ctx, p_wtv, p_att);
    // 7: x = x_anc + att @ W_o (half out)
    hgemm<3><<<dim3(2, BN / 128), 256, HGEMM_SMEM>>>(p_att, p_wto, p_xh, BN, DIM, DIM, nullptr, x_anc);
    // 8: LN2 (half in) -> half
    ln_half_kernel<<<BN / 8, lnBlock>>>(p_xh, ln2_g, ln2_b, p_h);
    // 9: transpose ff2
    transpose_kernel<<<dim3(8, 32), tBlock>>>(ff2_w, p_wt2, 1024, 256);
    // 10: ff = gelu(h @ ff1 + b1)
    hgemm<1><<<dim3(8, BN / 128), 256, HGEMM_SMEM>>>(p_h, p_wt1, p_ff, BN, NFF, DIM, ff1_b, nullptr);
    // 11: out = x + ff @ ff2 + b2 (half resid, f32 out)
    hgemm<2><<<dim3(2, BN / 128), 256, HGEMM_SMEM>>>(p_ff, p_wt2, out, BN, DIM, NFF, ff2_b, p_xh);
}

// round 16
// speedup vs baseline: 1.4850x; 1.0855x over previous
#include <cuda_runtime.h>
#include <cuda_fp16.h>
#include <math.h>
#include <stdint.h>

// Problem constants
#define BN  32768
#define DIM 256
#define NK  32
#define NH  8
#define NFF 1024
#define NDK 32

// ---------------- scratch (device globals: allocation-guard-safe) ----------------
__device__ __align__(128) __half g_lnx[BN * DIM];       // LN1(x_anc), half
__device__ __align__(128) __half g_qh[BN * DIM];        // Q, half
__device__ __align__(128) __half g_qt[BN * NH * DIM];   // q~ [B, H, 256], half
__device__ __align__(128) __half g_ctx[BN * NH * DIM];  // ctx [B, H, 256], half
__device__ __align__(128) __half g_att[BN * DIM];       // attention out (pre-W_o), half
__device__ __align__(128) __half g_xh[BN * DIM];        // x = x_anc + att @ W_o, half
__device__ __align__(128) __half g_h[BN * DIM];         // LN2(x), half
__device__ __align__(128) __half g_ff[BN * NFF];        // gelu(h@ff1+b1), half
// half weights
__device__ __align__(128) __half g_wkh[DIM * DIM];      // Wk as half (same layout)
__device__ __align__(128) __half g_wtq[DIM * DIM];
__device__ __align__(128) __half g_wto[DIM * DIM];
__device__ __align__(128) __half g_wtv[DIM * DIM];      // Wv^T
__device__ __align__(128) __half g_wt1[DIM * NFF];
__device__ __align__(128) __half g_wt2[NFF * DIM];

// ---------------- LayerNorm (fp32 input): one warp per row, half output ----------------
__global__ void ln_kernel(const float* __restrict__ x, const float* __restrict__ g,
                          const float* __restrict__ b, __half* __restrict__ out) {
    int row  = blockIdx.x * 8 + threadIdx.y;
    int lane = threadIdx.x;
    const float4* xr = reinterpret_cast<const float4*>(x + (size_t)row * DIM);
    float4 v0 = xr[lane];
    float4 v1 = xr[lane + 32];
    float s  = v0.x + v0.y + v0.z + v0.w + v1.x + v1.y + v1.z + v1.w;
    float ss = v0.x*v0.x + v0.y*v0.y + v0.z*v0.z + v0.w*v0.w
             + v1.x*v1.x + v1.y*v1.y + v1.z*v1.z + v1.w*v1.w;
    #pragma unroll
    for (int o = 16; o; o >>= 1) {
        s  += __shfl_xor_sync(0xFFFFFFFFu, s,  o);
        ss += __shfl_xor_sync(0xFFFFFFFFu, ss, o);
    }
    float mu  = s * (1.0f / 256.0f);
    float var = ss * (1.0f / 256.0f) - mu * mu;
    float rs  = rsqrtf(var + 1e-5f);
    const float4* g4 = reinterpret_cast<const float4*>(g);
    const float4* b4 = reinterpret_cast<const float4*>(b);
    __half* orow = out + (size_t)row * DIM;
    #pragma unroll
    for (int p = 0; p < 2; p++) {
        int idx = lane + p * 32;
        float4 v = (p == 0) ? v0 : v1;
        float4 gg = g4[idx], bb = b4[idx];
        float o0 = (v.x - mu) * rs * gg.x + bb.x;
        float o1 = (v.y - mu) * rs * gg.y + bb.y;
        float o2 = (v.z - mu) * rs * gg.z + bb.z;
        float o3 = (v.w - mu) * rs * gg.w + bb.w;
        __half2 ha = __floats2half2_rn(o0, o1);
        __half2 hb = __floats2half2_rn(o2, o3);
        uint2 u;
        u.x = *reinterpret_cast<uint32_t*>(&ha);
        u.y = *reinterpret_cast<uint32_t*>(&hb);
        *reinterpret_cast<uint2*>(orow + idx * 4) = u;
    }
}

// ---------------- LayerNorm (half input): one warp per row, half output ----------------
__global__ void ln_half_kernel(const __half* __restrict__ x, const float* __restrict__ g,
                               const float* __restrict__ b, __half* __restrict__ out) {
    int row  = blockIdx.x * 8 + threadIdx.y;
    int lane = threadIdx.x;
    const uint4* xr = reinterpret_cast<const uint4*>(x + (size_t)row * DIM);
    uint4 u = xr[lane];   // 8 halves
    float v[8];
    {
        float2 f0 = __half22float2(*reinterpret_cast<__half2*>(&u.x));
        float2 f1 = __half22float2(*reinterpret_cast<__half2*>(&u.y));
        float2 f2 = __half22float2(*reinterpret_cast<__half2*>(&u.z));
        float2 f3 = __half22float2(*reinterpret_cast<__half2*>(&u.w));
        v[0]=f0.x; v[1]=f0.y; v[2]=f1.x; v[3]=f1.y;
        v[4]=f2.x; v[5]=f2.y; v[6]=f3.x; v[7]=f3.y;
    }
    float s = 0.f, ss = 0.f;
    #pragma unroll
    for (int i = 0; i < 8; i++) { s += v[i]; ss += v[i] * v[i]; }
    #pragma unroll
    for (int o = 16; o; o >>= 1) {
        s  += __shfl_xor_sync(0xFFFFFFFFu, s,  o);
        ss += __shfl_xor_sync(0xFFFFFFFFu, ss, o);
    }
    float mu  = s * (1.0f / 256.0f);
    float var = ss * (1.0f / 256.0f) - mu * mu;
    float rs  = rsqrtf(var + 1e-5f);
    const float4* g4 = reinterpret_cast<const float4*>(g);
    const float4* b4 = reinterpret_cast<const float4*>(b);
    float4 ga = g4[lane * 2], gb = g4[lane * 2 + 1];
    float4 ba = b4[lane * 2], bb = b4[lane * 2 + 1];
    float o0 = (v[0]-mu)*rs*ga.x + ba.x;
    float o1 = (v[1]-mu)*rs*ga.y + ba.y;
    float o2 = (v[2]-mu)*rs*ga.z + ba.z;
    float o3 = (v[3]-mu)*rs*ga.w + ba.w;
    float o4 = (v[4]-mu)*rs*gb.x + bb.x;
    float o5 = (v[5]-mu)*rs*gb.y + bb.y;
    float o6 = (v[6]-mu)*rs*gb.z + bb.z;
    float o7 = (v[7]-mu)*rs*gb.w + bb.w;
    __half2 h0 = __floats2half2_rn(o0, o1);
    __half2 h1 = __floats2half2_rn(o2, o3);
    __half2 h2 = __floats2half2_rn(o4, o5);
    __half2 h3 = __floats2half2_rn(o6, o7);
    uint4 ou;
    ou.x = *reinterpret_cast<uint32_t*>(&h0);
    ou.y = *reinterpret_cast<uint32_t*>(&h1);
    ou.z = *reinterpret_cast<uint32_t*>(&h2);
    ou.w = *reinterpret_cast<uint32_t*>(&h3);
    *reinterpret_cast<uint4*>(out + (size_t)row * DIM + lane * 8) = ou;
}

__device__ __forceinline__ float gelu_exact(float v) {
    return 0.5f * v * (1.0f + erff(v * 0.70710678118654752f));
}

// ---------------- weight prep: z=0..2 transpose {Wq,Wo,Wv}; z=3 copy-convert Wk ----------------
__global__ void wprep_kernel(const float* __restrict__ Wq, const float* __restrict__ Wo,
                             const float* __restrict__ Wv, const float* __restrict__ Wk,
                             __half* __restrict__ wtq, __half* __restrict__ wto,
                             __half* __restrict__ wtv, __half* __restrict__ wkh) {
    __shared__ float t[32][33];
    int z = blockIdx.z;
    const float* in = (z == 0) ? Wq : (z == 1) ? Wo : (z == 2) ? Wv : Wk;
    __half* out     = (z == 0) ? wtq : (z == 1) ? wto : (z == 2) ? wtv : wkh;
    int c0 = blockIdx.x * 32, r0 = blockIdx.y * 32;
    int tx = threadIdx.x, ty = threadIdx.y;   // (32, 8)
    if (z < 3) {
        #pragma unroll
        for (int j = 0; j < 4; j++)
            t[ty + j * 8][tx] = in[(size_t)(r0 + ty + j * 8) * 256 + c0 + tx];
        __syncthreads();
        #pragma unroll
        for (int j = 0; j < 4; j++)
            out[(size_t)(c0 + ty + j * 8) * 256 + r0 + tx] = __float2half_rn(t[tx][ty + j * 8]);
    } else {
        #pragma unroll
        for (int j = 0; j < 4; j++) {
            size_t idx = (size_t)(r0 + ty + j * 8) * 256 + c0 + tx;
            out[idx] = __float2half_rn(in[idx]);
        }
    }
}

// ---------------- transpose+convert (rectangular weights) ----------------
__global__ void transpose_kernel(const float* __restrict__ in, __half* __restrict__ out,
                                 int R, int C) {
    __shared__ float t[32][33];
    int c0 = blockIdx.x * 32, r0 = blockIdx.y * 32;
    int tx = threadIdx.x, ty = threadIdx.y;   // (32, 8)
    #pragma unroll
    for (int j = 0; j < 4; j++)
        t[ty + j * 8][tx] = in[(size_t)(r0 + ty + j * 8) * C + c0 + tx];
    __syncthreads();
    #pragma unroll
    for (int j = 0; j < 4; j++)
        out[(size_t)(c0 + ty + j * 8) * R + r0 + tx] = __float2half_rn(t[tx][ty + j * 8]);
}

// ---------------- shared helpers ----------------
__device__ __forceinline__ uint32_t smem_u32(const void* p) {
    uint32_t a;
    asm("{ .reg .u64 t; cvta.to.shared.u64 t, %1; cvt.u32.u64 %0, t; }" : "=r"(a) : "l"(p));
    return a;
}
__device__ __forceinline__ void ldsm_x4(uint32_t r[4], uint32_t addr) {
    asm volatile("ldmatrix.sync.aligned.m8n8.x4.shared.b16 {%0,%1,%2,%3}, [%4];"
                 : "=r"(r[0]), "=r"(r[1]), "=r"(r[2]), "=r"(r[3]) : "r"(addr));
}
__device__ __forceinline__ void ldsm_x4_trans(uint32_t r[4], uint32_t addr) {
    asm volatile("ldmatrix.sync.aligned.m8n8.x4.trans.shared.b16 {%0,%1,%2,%3}, [%4];"
                 : "=r"(r[0]), "=r"(r[1]), "=r"(r[2]), "=r"(r[3]) : "r"(addr));
}
__device__ __forceinline__ void ldsm_x2(uint32_t r[2], uint32_t addr) {
    asm volatile("ldmatrix.sync.aligned.m8n8.x2.shared.b16 {%0,%1}, [%2];"
                 : "=r"(r[0]), "=r"(r[1]) : "r"(addr));
}
__device__ __forceinline__ void mma_f16(float c[4], const uint32_t a[4],
                                        uint32_t b0, uint32_t b1) {
    asm volatile(
        "mma.sync.aligned.m16n8k16.row.col.f32.f16.f16.f32 "
        "{%0,%1,%2,%3}, {%4,%5,%6,%7}, {%8,%9}, {%0,%1,%2,%3};\n"
        : "+f"(c[0]), "+f"(c[1]), "+f"(c[2]), "+f"(c[3])
        : "r"(a[0]), "r"(a[1]), "r"(a[2]), "r"(a[3]), "r"(b0), "r"(b1));
}
__device__ __forceinline__ void cp_async16(uint32_t dst, const void* src) {
    asm volatile("cp.async.cg.shared.global [%0], [%1], 16;\n" :: "r"(dst), "l"(src));
}
__device__ __forceinline__ void cp_commit() {
    asm volatile("cp.async.commit_group;\n" ::: "memory");
}
template <int N>
__device__ __forceinline__ void cp_wait() {
    asm volatile("cp.async.wait_group %0;\n" :: "n"(N) : "memory");
}

// ================= fp16 tensor-core GEMM: 128x128, 4-stage cp.async pipeline =================
#define HS 40
#define STAGE_BYTES (128 * HS * 2)          // one A or B buffer: 10240 B
#define HGEMM_SMEM (8 * STAGE_BYTES)        // 4 stages x (A + B) = 81920 B

// MODE 1: gelu(A@B+bias) -> half     MODE 2: A@B + bias + HALF resid -> f32
// MODE 3: A@B + F32 resid -> half    MODE 4: A@B -> half
template <int MODE>
__global__ __launch_bounds__(256, 2)
void hgemm(const __half* __restrict__ A, const __half* __restrict__ BT,
           void* __restrict__ Cout, int M, int N, int Kd,
           const float* __restrict__ bias, const void* __restrict__ resid) {
    extern __shared__ __half hsm[];
    const uint32_t sm_base = smem_u32(hsm);

    const int tid  = threadIdx.x;
    const int lane = tid & 31;
    const int wid  = tid >> 5;
    const int m0 = blockIdx.y * 128;
    const int n0 = blockIdx.x * 128;
    const int warp_m = (wid & 1) * 64;
    const int warp_n = (wid >> 1) * 32;

    const int ldRow = tid >> 1;
    const int ldCol = (tid & 1) * 16;
    const __half* Ag = A  + (size_t)(m0 + ldRow) * Kd + ldCol;
    const __half* Bg = BT + (size_t)(n0 + ldRow) * Kd + ldCol;
    const uint32_t ldOffA = (uint32_t)(ldRow * HS + ldCol) * 2;
    const uint32_t ldOffB = ldOffA + STAGE_BYTES;

    float c[4][4][4];
    #pragma unroll
    for (int mt = 0; mt < 4; mt++)
        #pragma unroll
        for (int nt = 0; nt < 4; nt++)
            #pragma unroll
            for (int i = 0; i < 4; i++) c[mt][nt][i] = 0.0f;

    const int a_row = warp_m + (lane & 7) + ((lane >> 3) & 1) * 8;
    const int a_k   = (lane >> 4) * 8;
    const int b_row = warp_n + (lane & 7) + ((lane >> 4) & 1) * 8;
    const int b_k   = ((lane >> 3) & 1) * 8;
    const uint32_t aAddr0 = sm_base + (uint32_t)(a_row * HS + a_k) * 2;
    const uint32_t bAddr0 = sm_base + STAGE_BYTES + (uint32_t)(b_row * HS + b_k) * 2;

    const int KT = Kd >> 5;

    #pragma unroll
    for (int p = 0; p < 3; p++) {
        if (p < KT) {
            uint32_t sbase = (uint32_t)p * (2 * STAGE_BYTES);
            const __half* Ap = Ag + p * 32;
            const __half* Bp = Bg + p * 32;
            cp_async16(sm_base + sbase + ldOffA,      Ap);
            cp_async16(sm_base + sbase + ldOffA + 16, Ap + 8);
            cp_async16(sm_base + sbase + ldOffB,      Bp);
            cp_async16(sm_base + sbase + ldOffB + 16, Bp + 8);
        }
        cp_commit();
    }

    for (int kt = 0; kt < KT; kt++) {
        if (kt + 3 <= KT - 1)      cp_wait<2>();
        else if (kt + 2 <= KT - 1) cp_wait<1>();
        else                       cp_wait<0>();
        __syncthreads();

        if (kt + 3 < KT) {
            uint32_t sbase = (uint32_t)((kt + 3) & 3) * (2 * STAGE_BYTES);
            const __half* Ap = Ag + (kt + 3) * 32;
            const __half* Bp = Bg + (kt + 3) * 32;
            cp_async16(sm_base + sbase + ldOffA,      Ap);
            cp_async16(sm_base + sbase + ldOffA + 16, Ap + 8);
            cp_async16(sm_base + sbase + ldOffB,      Bp);
            cp_async16(sm_base + sbase + ldOffB + 16, Bp + 8);
            cp_commit();
        } else {
            cp_commit();
        }

        const uint32_t bo = (uint32_t)(kt & 3) * (2 * STAGE_BYTES);
        #pragma unroll
        for (int ks = 0; ks < 2; ks++) {
            uint32_t af[4][4];
            uint32_t bf[2][4];
            #pragma unroll
            for (int mt = 0; mt < 4; mt++)
                ldsm_x4(af[mt], aAddr0 + bo + (uint32_t)(mt * 16 * HS + ks * 16) * 2);
            #pragma unroll
            for (int ntp = 0; ntp < 2; ntp++)
                ldsm_x4(bf[ntp], bAddr0 + bo + (uint32_t)(ntp * 16 * HS + ks * 16) * 2);
            #pragma unroll
            for (int mt = 0; mt < 4; mt++) {
                #pragma unroll
                for (int nt = 0; nt < 4; nt++) {
                    uint32_t b0 = (nt & 1) ? bf[nt >> 1][2] : bf[nt >> 1][0];
                    uint32_t b1 = (nt & 1) ? bf[nt >> 1][3] : bf[nt >> 1][1];
                    mma_f16(c[mt][nt], af[mt], b0, b1);
                }
            }
        }
    }

    const int fr = lane >> 2;
    const int fc = lane & 3;
    #pragma unroll
    for (int mt = 0; mt < 4; mt++) {
        #pragma unroll
        for (int nt = 0; nt < 4; nt++) {
            int row0 = m0 + warp_m + mt * 16 + fr;
            int col  = n0 + warp_n + nt * 8 + fc * 2;
            float v0 = c[mt][nt][0], v1 = c[mt][nt][1];
            float v2 = c[mt][nt][2], v3 = c[mt][nt][3];
            if (MODE == 1 || MODE == 2) {
                float2 bv = *reinterpret_cast<const float2*>(bias + col);
                v0 += bv.x; v1 += bv.y; v2 += bv.x; v3 += bv.y;
            }
            if (MODE == 1) {
                v0 = gelu_exact(v0); v1 = gelu_exact(v1);
                v2 = gelu_exact(v2); v3 = gelu_exact(v3);
            }
            if (MODE == 2) {   // half resid
                const __half* rh = reinterpret_cast<const __half*>(resid);
                float2 f0 = __half22float2(*reinterpret_cast<const __half2*>(rh + (size_t)row0 * N + col));
                float2 f1 = __half22float2(*reinterpret_cast<const __half2*>(rh + (size_t)(row0 + 8) * N + col));
                v0 += f0.x; v1 += f0.y; v2 += f1.x; v3 += f1.y;
            }
            if (MODE == 3) {   // fp32 resid
                const float* rf = reinterpret_cast<const float*>(resid);
                float2 r0 = *reinterpret_cast<const float2*>(rf + (size_t)row0 * N + col);
                float2 r1 = *reinterpret_cast<const float2*>(rf + (size_t)(row0 + 8) * N + col);
                v0 += r0.x; v1 += r0.y; v2 += r1.x; v3 += r1.y;
            }
            if (MODE == 1 || MODE == 3 || MODE == 4) {
                __half* Ch = reinterpret_cast<__half*>(Cout);
                __half2 h0 = __floats2half2_rn(v0, v1);
                __half2 h1 = __floats2half2_rn(v2, v3);
                *reinterpret_cast<__half2*>(Ch + (size_t)row0 * N + col)       = h0;
                *reinterpret_cast<__half2*>(Ch + (size_t)(row0 + 8) * N + col) = h1;
            } else {
                float* Cf = reinterpret_cast<float*>(Cout);
                *reinterpret_cast<float2*>(Cf + (size_t)row0 * N + col)       = make_float2(v0, v1);
                *reinterpret_cast<float2*>(Cf + (size_t)(row0 + 8) * N + col) = make_float2(v2, v3);
            }
        }
    }
}

// ---------------- qtilde via tensor cores ----------------
__global__ __launch_bounds__(256)
void qtilde_tc(const __half* __restrict__ Q, const __half* __restrict__ Wkh,
               __half* __restrict__ qt) {
    __shared__ __half As[128][HS];
    __shared__ __half Bs[128][HS];

    const int tid  = threadIdx.x;
    const int lane = tid & 31;
    const int wid  = tid >> 5;
    const int m0   = blockIdx.x * 128;
    const int head = blockIdx.y >> 1;
    const int n0   = (blockIdx.y & 1) * 128;
    const int warp_m = (wid & 1) * 64;
    const int warp_n = (wid >> 1) * 32;

    const int ldRow = tid >> 1;
    const int ldCol = (tid & 1) * 16;
    {
        const __half* Ag = Q   + (size_t)(m0 + ldRow) * 256 + head * 32 + ldCol;
        const __half* Bg = Wkh + (size_t)(n0 + ldRow) * 256 + head * 32 + ldCol;
        *reinterpret_cast<uint4*>(&As[ldRow][ldCol])     = *reinterpret_cast<const uint4*>(Ag);
        *reinterpret_cast<uint4*>(&As[ldRow][ldCol + 8]) = *reinterpret_cast<const uint4*>(Ag + 8);
        *reinterpret_cast<uint4*>(&Bs[ldRow][ldCol])     = *reinterpret_cast<const uint4*>(Bg);
        *reinterpret_cast<uint4*>(&Bs[ldRow][ldCol + 8]) = *reinterpret_cast<const uint4*>(Bg + 8);
    }
    __syncthreads();

    float c[4][4][4];
    #pragma unroll
    for (int mt = 0; mt < 4; mt++)
        #pragma unroll
        for (int nt = 0; nt < 4; nt++)
            #pragma unroll
            for (int i = 0; i < 4; i++) c[mt][nt][i] = 0.0f;

    const uint32_t as_base = smem_u32(&As[0][0]);
    const uint32_t bs_base = smem_u32(&Bs[0][0]);
    const int a_row = warp_m + (lane & 7) + ((lane >> 3) & 1) * 8;
    const int a_k   = (lane >> 4) * 8;
    const int b_row = warp_n + (lane & 7) + ((lane >> 4) & 1) * 8;
    const int b_k   = ((lane >> 3) & 1) * 8;
    const uint32_t aAddr0 = as_base + (uint32_t)(a_row * HS + a_k) * 2;
    const uint32_t bAddr0 = bs_base + (uint32_t)(b_row * HS + b_k) * 2;

    #pragma unroll
    for (int ks = 0; ks < 2; ks++) {
        uint32_t af[4][4];
        uint32_t bf[2][4];
        #pragma unroll
        for (int mt = 0; mt < 4; mt++)
            ldsm_x4(af[mt], aAddr0 + (uint32_t)(mt * 16 * HS + ks * 16) * 2);
        #pragma unroll
        for (int ntp = 0; ntp < 2; ntp++)
            ldsm_x4(bf[ntp], bAddr0 + (uint32_t)(ntp * 16 * HS + ks * 16) * 2);
        #pragma unroll
        for (int mt = 0; mt < 4; mt++) {
            #pragma unroll
            for (int nt = 0; nt < 4; nt++) {
                uint32_t b0 = (nt & 1) ? bf[nt >> 1][2] : bf[nt >> 1][0];
                uint32_t b1 = (nt & 1) ? bf[nt >> 1][3] : bf[nt >> 1][1];
                mma_f16(c[mt][nt], af[mt], b0, b1);
            }
        }
    }

    const int fr = lane >> 2;
    const int fc = lane & 3;
    #pragma unroll
    for (int mt = 0; mt < 4; mt++) {
        #pragma unroll
        for (int nt = 0; nt < 4; nt++) {
            int row0 = m0 + warp_m + mt * 16 + fr;
            int col  = head * 256 + n0 + warp_n + nt * 8 + fc * 2;
            __half2 h0 = __floats2half2_rn(c[mt][nt][0], c[mt][nt][1]);
            __half2 h1 = __floats2half2_rn(c[mt][nt][2], c[mt][nt][3]);
            *reinterpret_cast<__half2*>(qt + (size_t)row0 * 2048 + col)       = h0;
            *reinterpret_cast<__half2*>(qt + (size_t)(row0 + 8) * 2048 + col) = h1;
        }
    }
}

// ---------------- attention core v7: 4 anchors per CTA, register prefetch ----------------
#define XS_S 264
#define QS_S 264
#define AT_S 40
#define CT_S 264
#define ANC  4
__global__ __launch_bounds__(256)
void attn_kernel(const float* __restrict__ xnei, const __half* __restrict__ qt,
                 __half* __restrict__ ctx) {
    __shared__ __half xs[32 * XS_S];
    __shared__ __half qts[8 * QS_S];
    __shared__ float  sred[8 * 256];
    __shared__ __half attns_h[8 * AT_S];
    __shared__ __half ctx_t[8 * CT_S];
    int b0   = blockIdx.x * ANC;
    int tid  = threadIdx.x;
    int lane = tid & 31;
    int w    = tid >> 5;

    const uint32_t xs_base = smem_u32(xs);
    const uint32_t qs_base = smem_u32(qts);
    const uint32_t at_base = smem_u32(attns_h);
    const int fr = lane >> 2;
    const int fc = lane & 3;

    // register-prefetch buffers for anchor a
    float4 xv[8];
    uint4  qv;

    // prefetch anchor 0
    {
        const float4* xb4 = reinterpret_cast<const float4*>(xnei + (size_t)b0 * 8192);
        #pragma unroll
        for (int j = 0; j < 8; j++) xv[j] = xb4[tid + j * 256];
        qv = reinterpret_cast<const uint4*>(qt + (size_t)b0 * 2048)[tid];
    }

    for (int a = 0; a < ANC; a++) {
        int b = b0 + a;

        // stage prefetched x (fp32 regs -> half smem) and qt
        #pragma unroll
        for (int j = 0; j < 8; j++) {
            int i  = tid + j * 256;
            int k  = i >> 6;
            int c4 = i & 63;
            __half2 h0 = __floats2half2_rn(xv[j].x, xv[j].y);
            __half2 h1 = __floats2half2_rn(xv[j].z, xv[j].w);
            uint2 u;
            u.x = *reinterpret_cast<uint32_t*>(&h0);
            u.y = *reinterpret_cast<uint32_t*>(&h1);
            *reinterpret_cast<uint2*>(xs + k * XS_S + c4 * 4) = u;
        }
        {
            int h  = tid >> 5;
            int c8 = tid & 31;
            *reinterpret_cast<uint4*>(qts + h * QS_S + c8 * 8) = qv;
        }
        __syncthreads();

        // prefetch next anchor (latency hidden behind compute below)
        if (a + 1 < ANC) {
            const float4* xb4 = reinterpret_cast<const float4*>(xnei + (size_t)(b + 1) * 8192);
            #pragma unroll
            for (int j = 0; j < 8; j++) xv[j] = xb4[tid + j * 256];
            qv = reinterpret_cast<const uint4*>(qt + (size_t)(b + 1) * 2048)[tid];
        }

        // ---- phase 1: scores partials ----
        {
            float sacc[2][4];
            #pragma unroll
            for (int mt = 0; mt < 2; mt++)
                #pragma unroll
                for (int i = 0; i < 4; i++) sacc[mt][i] = 0.0f;
            const int a_row = (lane & 7) + ((lane >> 3) & 1) * 8;
            const int a_kof = (lane >> 4) * 8;
            const int b_row = lane & 7;
            const int b_kof = ((lane >> 3) & 1) * 8;
            #pragma unroll
            for (int ks = 0; ks < 2; ks++) {
                uint32_t bq[2];
                ldsm_x2(bq, qs_base + (uint32_t)(b_row * QS_S + w * 32 + ks * 16 + b_kof) * 2);
                #pragma unroll
                for (int mt = 0; mt < 2; mt++) {
                    uint32_t af[4];
                    ldsm_x4(af, xs_base + (uint32_t)((mt * 16 + a_row) * XS_S + w * 32 + ks * 16 + a_kof) * 2);
                    mma_f16(sacc[mt], af, bq[0], bq[1]);
                }
            }
            #pragma unroll
            for (int mt = 0; mt < 2; mt++) {
                int krow = mt * 16 + fr;
                *reinterpret_cast<float2*>(&sred[w * 256 + krow * 8 + fc * 2]) =
                    make_float2(sacc[mt][0], sacc[mt][1]);
                *reinterpret_cast<float2*>(&sred[w * 256 + (krow + 8) * 8 + fc * 2]) =
                    make_float2(sacc[mt][2], sacc[mt][3]);
            }
        }
        __syncthreads();

        // ---- softmax: warp w = head, lane = k ----
        {
            float sc = 0.0f;
            #pragma unroll
            for (int ww = 0; ww < 8; ww++)
                sc += sred[ww * 256 + lane * 8 + w];
            sc *= 0.17677669529663687f;
            float m = sc;
            #pragma unroll
            for (int o = 16; o; o >>= 1) m = fmaxf(m, __shfl_xor_sync(0xFFFFFFFFu, m, o));
            float e = expf(sc - m);
            float s = e;
            #pragma unroll
            for (int o = 16; o; o >>= 1) s += __shfl_xor_sync(0xFFFFFFFFu, s, o);
            attns_h[w * AT_S + lane] = __float2half_rn(e / s);
        }
        __syncthreads();

        // ---- phase 2: ctx^T ----
        {
            float cacc[2][4];
            #pragma unroll
            for (int mt = 0; mt < 2; mt++)
                #pragma unroll
                for (int i = 0; i < 4; i++) cacc[mt][i] = 0.0f;
            const int t_krow = ((lane >> 4) & 1) * 8 + (lane & 7);
            const int t_dof  = ((lane >> 3) & 1) * 8;
            const int b_row = lane & 7;
            const int b_kof = ((lane >> 3) & 1) * 8;
            #pragma unroll
            for (int ks = 0; ks < 2; ks++) {
                uint32_t bp[2];
                ldsm_x2(bp, at_base + (uint32_t)(b_row * AT_S + ks * 16 + b_kof) * 2);
                #pragma unroll
                for (int mt = 0; mt < 2; mt++) {
                    int d0 = w * 32 + mt * 16;
                    uint32_t af[4];
                    ldsm_x4_trans(af, xs_base + (uint32_t)((ks * 16 + t_krow) * XS_S + d0 + t_dof) * 2);
                    mma_f16(cacc[mt], af, bp[0], bp[1]);
                }
            }
            #pragma unroll
            for (int mt = 0; mt < 2; mt++) {
                int d0 = w * 32 + mt * 16;
                ctx_t[(fc * 2 + 0) * CT_S + d0 + fr]     = __float2half_rn(cacc[mt][0]);
                ctx_t[(fc * 2 + 1) * CT_S + d0 + fr]     = __float2half_rn(cacc[mt][1]);
                ctx_t[(fc * 2 + 0) * CT_S + d0 + fr + 8] = __float2half_rn(cacc[mt][2]);
                ctx_t[(fc * 2 + 1) * CT_S + d0 + fr + 8] = __float2half_rn(cacc[mt][3]);
            }
        }
        __syncthreads();

        // coalesced writeout
        {
            uint4 u = *reinterpret_cast<const uint4*>(&ctx_t[w * CT_S + lane * 8]);
            *reinterpret_cast<uint4*>(&ctx[(size_t)b * 2048 + w * 256 + lane * 8]) = u;
        }
        __syncthreads();   // ctx_t read done before next anchor's ph2 rewrites it
    }
}

// ---------------- vproj via tensor cores: 4-stage cp.async pipeline ----------------
#define VST_A (128 * HS * 2)     // 10240
#define VST_B (32 * HS * 2)      // 2560
#define VSTAGE (VST_A + VST_B)
#define VPROJ_SMEM (4 * VSTAGE)  // 51200
__global__ __launch_bounds__(256)
void vproj_tc(const __half* __restrict__ ctx, const __half* __restrict__ WvT,
              __half* __restrict__ out) {
    extern __shared__ __half vsm[];
    const uint32_t sm_base = smem_u32(vsm);
    const int tid  = threadIdx.x;
    const int lane = tid & 31;
    const int wid  = tid >> 5;
    const int m0 = blockIdx.x * 128;
    const int h  = blockIdx.y;

    const int aRow = tid >> 1;
    const int aCol = (tid & 1) * 16;
    const __half* Ag = ctx + (size_t)(m0 + aRow) * 2048 + h * 256 + aCol;
    const uint32_t ldOffA = (uint32_t)(aRow * HS + aCol) * 2;
    const __half* Bg = WvT + (size_t)(h * 32 + (tid >> 1)) * 256 + aCol;   // valid for tid<64
    const uint32_t ldOffB = VST_A + (uint32_t)((tid >> 1) * HS + aCol) * 2;

    float c[4][4];
    #pragma unroll
    for (int nt = 0; nt < 4; nt++)
        #pragma unroll
        for (int i = 0; i < 4; i++) c[nt][i] = 0.0f;

    const int a_row = wid * 16 + (lane & 7) + ((lane >> 3) & 1) * 8;
    const int a_k   = (lane >> 4) * 8;
    const int b_row = (lane & 7) + ((lane >> 4) & 1) * 8;
    const int b_k   = ((lane >> 3) & 1) * 8;

    const int KT = 8;   // 256 / 32
    #pragma unroll
    for (int p = 0; p < 3; p++) {
        uint32_t sbase = (uint32_t)p * VSTAGE;
        cp_async16(sm_base + sbase + ldOffA,      Ag + p * 32);
        cp_async16(sm_base + sbase + ldOffA + 16, Ag + p * 32 + 8);
        if (tid < 64) {
            cp_async16(sm_base + sbase + ldOffB,      Bg + p * 32);
            cp_async16(sm_base + sbase + ldOffB + 16, Bg + p * 32 + 8);
        }
        cp_commit();
    }

    for (int kt = 0; kt < KT; kt++) {
        if (kt + 3 <= KT - 1)      cp_wait<2>();
        else if (kt + 2 <= KT - 1) cp_wait<1>();
        else                       cp_wait<0>();
        __syncthreads();

        if (kt + 3 < KT) {
            uint32_t sbase = (uint32_t)((kt + 3) & 3) * VSTAGE;
            cp_async16(sm_base + sbase + ldOffA,      Ag + (kt + 3) * 32);
            cp_async16(sm_base + sbase + ldOffA + 16, Ag + (kt + 3) * 32 + 8);
            if (tid < 64) {
                cp_async16(sm_base + sbase + ldOffB,      Bg + (kt + 3) * 32);
                cp_async16(sm_base + sbase + ldOffB + 16, Bg + (kt + 3) * 32 + 8);
            }
            cp_commit();
        } else {
            cp_commit();
        }

        const uint32_t sb = sm_base + (uint32_t)(kt & 3) * VSTAGE;
        #pragma unroll
        for (int ks = 0; ks < 2; ks++) {
            uint32_t af[4];
            uint32_t bf[2][4];
            ldsm_x4(af, sb + (uint32_t)(a_row * HS + ks * 16 + a_k) * 2);
            #pragma unroll
            for (int ntp = 0; ntp < 2; ntp++)
                ldsm_x4(bf[ntp], sb + VST_A + (uint32_t)((ntp * 16 + b_row) * HS + ks * 16 + b_k) * 2);
            #pragma unroll
            for (int nt = 0; nt < 4; nt++) {
                uint32_t b0 = (nt & 1) ? bf[nt >> 1][2] : bf[nt >> 1][0];
                uint32_t b1 = (nt & 1) ? bf[nt >> 1][3] : bf[nt >> 1][1];
                mma_f16(c[nt], af, b0, b1);
            }
        }
    }

    const int fr = lane >> 2;
    const int fc = lane & 3;
    #pragma unroll
    for (int nt = 0; nt < 4; nt++) {
        int row0 = m0 + wid * 16 + fr;
        int col  = h * 32 + nt * 8 + fc * 2;
        __half2 h0 = __floats2half2_rn(c[nt][0], c[nt][1]);
        __half2 h1 = __floats2half2_rn(c[nt][2], c[nt][3]);
        *reinterpret_cast<__half2*>(out + (size_t)row0 * 256 + col)       = h0;
        *reinterpret_cast<__half2*>(out + (size_t)(row0 + 8) * 256 + col) = h1;
    }
}

// ---------------- launcher ----------------
extern "C" void kernel_launch(void* const* d_in, const int* in_sizes, int n_in,
                              void* d_out, int out_size) {
    const float* x_anc = (const float*)d_in[0];
    const float* x_nei = (const float*)d_in[1];
    const float* W_q   = (const float*)d_in[2];
    const float* W_k   = (const float*)d_in[3];
    const float* W_v   = (const float*)d_in[4];
    const float* W_o   = (const float*)d_in[5];
    const float* ln1_g = (const float*)d_in[6];
    const float* ln1_b = (const float*)d_in[7];
    const float* ln2_g = (const float*)d_in[8];
    const float* ln2_b = (const float*)d_in[9];
    const float* ff1_w = (const float*)d_in[10];
    const float* ff1_b = (const float*)d_in[11];
    const float* ff2_w = (const float*)d_in[12];
    const float* ff2_b = (const float*)d_in[13];
    float* out = (float*)d_out;

    __half *p_lnx, *p_qh, *p_qt, *p_ctx, *p_att, *p_xh, *p_h, *p_ff;
    __half *p_wkh, *p_wtq, *p_wto, *p_wtv, *p_wt1, *p_wt2;
    cudaGetSymbolAddress((void**)&p_lnx, g_lnx);
    cudaGetSymbolAddress((void**)&p_qh,  g_qh);
    cudaGetSymbolAddress((void**)&p_qt,  g_qt);
    cudaGetSymbolAddress((void**)&p_ctx, g_ctx);
    cudaGetSymbolAddress((void**)&p_att, g_att);
    cudaGetSymbolAddress((void**)&p_xh,  g_xh);
    cudaGetSymbolAddress((void**)&p_h,   g_h);
    cudaGetSymbolAddress((void**)&p_ff,  g_ff);
    cudaGetSymbolAddress((void**)&p_wkh, g_wkh);
    cudaGetSymbolAddress((void**)&p_wtq, g_wtq);
    cudaGetSymbolAddress((void**)&p_wto, g_wto);
    cudaGetSymbolAddress((void**)&p_wtv, g_wtv);
    cudaGetSymbolAddress((void**)&p_wt1, g_wt1);
    cudaGetSymbolAddress((void**)&p_wt2, g_wt2);

    cudaFuncSetAttribute(hgemm<1>, cudaFuncAttributeMaxDynamicSharedMemorySize, HGEMM_SMEM);
    cudaFuncSetAttribute(hgemm<2>, cudaFuncAttributeMaxDynamicSharedMemorySize, HGEMM_SMEM);
    cudaFuncSetAttribute(hgemm<3>, cudaFuncAttributeMaxDynamicSharedMemorySize, HGEMM_SMEM);
    cudaFuncSetAttribute(hgemm<4>, cudaFuncAttributeMaxDynamicSharedMemorySize, HGEMM_SMEM);
    cudaFuncSetAttribute(vproj_tc, cudaFuncAttributeMaxDynamicSharedMemorySize, VPROJ_SMEM);

    dim3 lnBlock(32, 8);
    dim3 tBlock(32, 8);

    // 0: weight prep (Wq^T, Wo^T, Wv^T, Wk->half) in one launch
    wprep_kernel<<<dim3(8, 8, 4), tBlock>>>(W_q, W_o, W_v, W_k, p_wtq, p_wto, p_wtv, p_wkh);
    // 1: LN1 -> half
    ln_kernel<<<BN / 8, lnBlock>>>(x_anc, ln1_g, ln1_b, p_lnx);
    // 2: transpose ff1
    transpose_kernel<<<dim3(32, 8), tBlock>>>(ff1_w, p_wt1, 256, 1024);
    // 3: Q = LN1 @ W_q (half out)  [PROFILED SLOT]
    hgemm<4><<<dim3(2, BN / 128), 256, HGEMM_SMEM>>>(p_lnx, p_wtq, p_qh, BN, DIM, DIM, nullptr, nullptr);
    // 4: q~ via tensor cores
    qtilde_tc<<<dim3(BN / 128, 16), 256>>>(p_qh, p_wkh, p_qt);
    // 5: attention core (4 anchors/CTA) -> ctx (half)
    attn_kernel<<<BN / ANC, 256>>>(x_nei, p_qt, p_ctx);
    // 6: att = ctx @ W_v (tensor cores, per head)
    vproj_tc<<<dim3(BN / 128, NH), 256, VPROJ_SMEM>>>(p_ctx, p_wtv, p_att);
    // 7: x = x_anc + att @ W_o (half out)
    hgemm<3><<<dim3(2, BN / 128), 256, HGEMM_SMEM>>>(p_att, p_wto, p_xh, BN, DIM, DIM, nullptr, x_anc);
    // 8: LN2 (half in) -> half
    ln_half_kernel<<<BN / 8, lnBlock>>>(p_xh, ln2_g, ln2_b, p_h);
    // 9: transpose ff2
    transpose_kernel<<<dim3(8, 32), tBlock>>>(ff2_w, p_wt2, 1024, 256);
    // 10: ff = gelu(h @ ff1 + b1)
    hgemm<1><<<dim3(8, BN / 128), 256, HGEMM_SMEM>>>(p_h, p_wt1, p_ff, BN, NFF, DIM, ff1_b, nullptr);
    // 11: out = x + ff @ ff2 + b2 (half resid, f32 out)
    hgemm<2><<<dim3(2, BN / 128), 256, HGEMM_SMEM>>>(p_ff, p_wt2, out, BN, DIM, NFF, ff2_b, p_xh);
}

// round 17
// speedup vs baseline: 1.4893x; 1.0028x over previous
#include <cuda_runtime.h>
#include <cuda_fp16.h>
#include <math.h>
#include <stdint.h>

// Problem constants
#define BN  32768
#define DIM 256
#define NK  32
#define NH  8
#define NFF 1024
#define NDK 32

// ---------------- scratch (device globals: allocation-guard-safe) ----------------
__device__ __align__(128) __half g_lnx[BN * DIM];       // LN1(x_anc), half
__device__ __align__(128) __half g_qh[BN * DIM];        // Q, half
__device__ __align__(128) __half g_qt[BN * NH * DIM];   // q~ [B, H, 256], half
__device__ __align__(128) __half g_ctx[BN * NH * DIM];  // ctx [B, H, 256], half
__device__ __align__(128) __half g_att[BN * DIM];       // attention out (pre-W_o), half
__device__ __align__(128) __half g_xh[BN * DIM];        // x = x_anc + att @ W_o, half
__device__ __align__(128) __half g_h[BN * DIM];         // LN2(x), half
__device__ __align__(128) __half g_ff[BN * NFF];        // gelu(h@ff1+b1), half
// half weights
__device__ __align__(128) __half g_wkh[DIM * DIM];      // Wk as half (same layout)
__device__ __align__(128) __half g_wtq[DIM * DIM];
__device__ __align__(128) __half g_wto[DIM * DIM];
__device__ __align__(128) __half g_wtv[DIM * DIM];      // Wv^T
__device__ __align__(128) __half g_wt1[DIM * NFF];
__device__ __align__(128) __half g_wt2[NFF * DIM];

// ---------------- LayerNorm (fp32 input): one warp per row, half output ----------------
__global__ void ln_kernel(const float* __restrict__ x, const float* __restrict__ g,
                          const float* __restrict__ b, __half* __restrict__ out) {
    int row  = blockIdx.x * 8 + threadIdx.y;
    int lane = threadIdx.x;
    const float4* xr = reinterpret_cast<const float4*>(x + (size_t)row * DIM);
    float4 v0 = xr[lane];
    float4 v1 = xr[lane + 32];
    float s  = v0.x + v0.y + v0.z + v0.w + v1.x + v1.y + v1.z + v1.w;
    float ss = v0.x*v0.x + v0.y*v0.y + v0.z*v0.z + v0.w*v0.w
             + v1.x*v1.x + v1.y*v1.y + v1.z*v1.z + v1.w*v1.w;
    #pragma unroll
    for (int o = 16; o; o >>= 1) {
        s  += __shfl_xor_sync(0xFFFFFFFFu, s,  o);
        ss += __shfl_xor_sync(0xFFFFFFFFu, ss, o);
    }
    float mu  = s * (1.0f / 256.0f);
    float var = ss * (1.0f / 256.0f) - mu * mu;
    float rs  = rsqrtf(var + 1e-5f);
    const float4* g4 = reinterpret_cast<const float4*>(g);
    const float4* b4 = reinterpret_cast<const float4*>(b);
    __half* orow = out + (size_t)row * DIM;
    #pragma unroll
    for (int p = 0; p < 2; p++) {
        int idx = lane + p * 32;
        float4 v = (p == 0) ? v0 : v1;
        float4 gg = g4[idx], bb = b4[idx];
        float o0 = (v.x - mu) * rs * gg.x + bb.x;
        float o1 = (v.y - mu) * rs * gg.y + bb.y;
        float o2 = (v.z - mu) * rs * gg.z + bb.z;
        float o3 = (v.w - mu) * rs * gg.w + bb.w;
        __half2 ha = __floats2half2_rn(o0, o1);
        __half2 hb = __floats2half2_rn(o2, o3);
        uint2 u;
        u.x = *reinterpret_cast<uint32_t*>(&ha);
        u.y = *reinterpret_cast<uint32_t*>(&hb);
        *reinterpret_cast<uint2*>(orow + idx * 4) = u;
    }
}

// ---------------- LayerNorm (half input): one warp per row, half output ----------------
__global__ void ln_half_kernel(const __half* __restrict__ x, const float* __restrict__ g,
                               const float* __restrict__ b, __half* __restrict__ out) {
    int row  = blockIdx.x * 8 + threadIdx.y;
    int lane = threadIdx.x;
    const uint4* xr = reinterpret_cast<const uint4*>(x + (size_t)row * DIM);
    uint4 u = xr[lane];   // 8 halves
    float v[8];
    {
        float2 f0 = __half22float2(*reinterpret_cast<__half2*>(&u.x));
        float2 f1 = __half22float2(*reinterpret_cast<__half2*>(&u.y));
        float2 f2 = __half22float2(*reinterpret_cast<__half2*>(&u.z));
        float2 f3 = __half22float2(*reinterpret_cast<__half2*>(&u.w));
        v[0]=f0.x; v[1]=f0.y; v[2]=f1.x; v[3]=f1.y;
        v[4]=f2.x; v[5]=f2.y; v[6]=f3.x; v[7]=f3.y;
    }
    float s = 0.f, ss = 0.f;
    #pragma unroll
    for (int i = 0; i < 8; i++) { s += v[i]; ss += v[i] * v[i]; }
    #pragma unroll
    for (int o = 16; o; o >>= 1) {
        s  += __shfl_xor_sync(0xFFFFFFFFu, s,  o);
        ss += __shfl_xor_sync(0xFFFFFFFFu, ss, o);
    }
    float mu  = s * (1.0f / 256.0f);
    float var = ss * (1.0f / 256.0f) - mu * mu;
    float rs  = rsqrtf(var + 1e-5f);
    const float4* g4 = reinterpret_cast<const float4*>(g);
    const float4* b4 = reinterpret_cast<const float4*>(b);
    float4 ga = g4[lane * 2], gb = g4[lane * 2 + 1];
    float4 ba = b4[lane * 2], bb = b4[lane * 2 + 1];
    float o0 = (v[0]-mu)*rs*ga.x + ba.x;
    float o1 = (v[1]-mu)*rs*ga.y + ba.y;
    float o2 = (v[2]-mu)*rs*ga.z + ba.z;
    float o3 = (v[3]-mu)*rs*ga.w + ba.w;
    float o4 = (v[4]-mu)*rs*gb.x + bb.x;
    float o5 = (v[5]-mu)*rs*gb.y + bb.y;
    float o6 = (v[6]-mu)*rs*gb.z + bb.z;
    float o7 = (v[7]-mu)*rs*gb.w + bb.w;
    __half2 h0 = __floats2half2_rn(o0, o1);
    __half2 h1 = __floats2half2_rn(o2, o3);
    __half2 h2 = __floats2half2_rn(o4, o5);
    __half2 h3 = __floats2half2_rn(o6, o7);
    uint4 ou;
    ou.x = *reinterpret_cast<uint32_t*>(&h0);
    ou.y = *reinterpret_cast<uint32_t*>(&h1);
    ou.z = *reinterpret_cast<uint32_t*>(&h2);
    ou.w = *reinterpret_cast<uint32_t*>(&h3);
    *reinterpret_cast<uint4*>(out + (size_t)row * DIM + lane * 8) = ou;
}

__device__ __forceinline__ float gelu_exact(float v) {
    return 0.5f * v * (1.0f + erff(v * 0.70710678118654752f));
}

// ---------------- weight prep: z=0..2 transpose {Wq,Wo,Wv}; z=3 copy-convert Wk ----------------
__global__ void wprep_kernel(const float* __restrict__ Wq, const float* __restrict__ Wo,
                             const float* __restrict__ Wv, const float* __restrict__ Wk,
                             __half* __restrict__ wtq, __half* __restrict__ wto,
                             __half* __restrict__ wtv, __half* __restrict__ wkh) {
    __shared__ float t[32][33];
    int z = blockIdx.z;
    const float* in = (z == 0) ? Wq : (z == 1) ? Wo : (z == 2) ? Wv : Wk;
    __half* out     = (z == 0) ? wtq : (z == 1) ? wto : (z == 2) ? wtv : wkh;
    int c0 = blockIdx.x * 32, r0 = blockIdx.y * 32;
    int tx = threadIdx.x, ty = threadIdx.y;   // (32, 8)
    if (z < 3) {
        #pragma unroll
        for (int j = 0; j < 4; j++)
            t[ty + j * 8][tx] = in[(size_t)(r0 + ty + j * 8) * 256 + c0 + tx];
        __syncthreads();
        #pragma unroll
        for (int j = 0; j < 4; j++)
            out[(size_t)(c0 + ty + j * 8) * 256 + r0 + tx] = __float2half_rn(t[tx][ty + j * 8]);
    } else {
        #pragma unroll
        for (int j = 0; j < 4; j++) {
            size_t idx = (size_t)(r0 + ty + j * 8) * 256 + c0 + tx;
            out[idx] = __float2half_rn(in[idx]);
        }
    }
}

// ---------------- transpose+convert (rectangular weights) ----------------
__global__ void transpose_kernel(const float* __restrict__ in, __half* __restrict__ out,
                                 int R, int C) {
    __shared__ float t[32][33];
    int c0 = blockIdx.x * 32, r0 = blockIdx.y * 32;
    int tx = threadIdx.x, ty = threadIdx.y;   // (32, 8)
    #pragma unroll
    for (int j = 0; j < 4; j++)
        t[ty + j * 8][tx] = in[(size_t)(r0 + ty + j * 8) * C + c0 + tx];
    __syncthreads();
    #pragma unroll
    for (int j = 0; j < 4; j++)
        out[(size_t)(c0 + ty + j * 8) * R + r0 + tx] = __float2half_rn(t[tx][ty + j * 8]);
}

// ---------------- shared helpers ----------------
__device__ __forceinline__ uint32_t smem_u32(const void* p) {
    uint32_t a;
    asm("{ .reg .u64 t; cvta.to.shared.u64 t, %1; cvt.u32.u64 %0, t; }" : "=r"(a) : "l"(p));
    return a;
}
__device__ __forceinline__ void ldsm_x4(uint32_t r[4], uint32_t addr) {
    asm volatile("ldmatrix.sync.aligned.m8n8.x4.shared.b16 {%0,%1,%2,%3}, [%4];"
                 : "=r"(r[0]), "=r"(r[1]), "=r"(r[2]), "=r"(r[3]) : "r"(addr));
}
__device__ __forceinline__ void ldsm_x4_trans(uint32_t r[4], uint32_t addr) {
    asm volatile("ldmatrix.sync.aligned.m8n8.x4.trans.shared.b16 {%0,%1,%2,%3}, [%4];"
                 : "=r"(r[0]), "=r"(r[1]), "=r"(r[2]), "=r"(r[3]) : "r"(addr));
}
__device__ __forceinline__ void ldsm_x2(uint32_t r[2], uint32_t addr) {
    asm volatile("ldmatrix.sync.aligned.m8n8.x2.shared.b16 {%0,%1}, [%2];"
                 : "=r"(r[0]), "=r"(r[1]) : "r"(addr));
}
__device__ __forceinline__ void mma_f16(float c[4], const uint32_t a[4],
                                        uint32_t b0, uint32_t b1) {
    asm volatile(
        "mma.sync.aligned.m16n8k16.row.col.f32.f16.f16.f32 "
        "{%0,%1,%2,%3}, {%4,%5,%6,%7}, {%8,%9}, {%0,%1,%2,%3};\n"
        : "+f"(c[0]), "+f"(c[1]), "+f"(c[2]), "+f"(c[3])
        : "r"(a[0]), "r"(a[1]), "r"(a[2]), "r"(a[3]), "r"(b0), "r"(b1));
}
__device__ __forceinline__ void cp_async16(uint32_t dst, const void* src) {
    asm volatile("cp.async.cg.shared.global [%0], [%1], 16;\n" :: "r"(dst), "l"(src));
}
__device__ __forceinline__ void cp_commit() {
    asm volatile("cp.async.commit_group;\n" ::: "memory");
}
template <int N>
__device__ __forceinline__ void cp_wait() {
    asm volatile("cp.async.wait_group %0;\n" :: "n"(N) : "memory");
}

// ================= fp16 tensor-core GEMM: 128x128, 4-stage cp.async pipeline =================
#define HS 40
#define STAGE_BYTES (128 * HS * 2)          // one A or B buffer: 10240 B
#define HGEMM_SMEM (8 * STAGE_BYTES)        // 4 stages x (A + B) = 81920 B

// MODE 1: gelu(A@B+bias) -> half     MODE 2: A@B + bias + HALF resid -> f32
// MODE 3: A@B + F32 resid -> half    MODE 4: A@B -> half
template <int MODE>
__global__ __launch_bounds__(256, 2)
void hgemm(const __half* __restrict__ A, const __half* __restrict__ BT,
           void* __restrict__ Cout, int M, int N, int Kd,
           const float* __restrict__ bias, const void* __restrict__ resid) {
    extern __shared__ __half hsm[];
    const uint32_t sm_base = smem_u32(hsm);

    const int tid  = threadIdx.x;
    const int lane = tid & 31;
    const int wid  = tid >> 5;
    const int m0 = blockIdx.y * 128;
    const int n0 = blockIdx.x * 128;
    const int warp_m = (wid & 1) * 64;
    const int warp_n = (wid >> 1) * 32;

    const int ldRow = tid >> 1;
    const int ldCol = (tid & 1) * 16;
    const __half* Ag = A  + (size_t)(m0 + ldRow) * Kd + ldCol;
    const __half* Bg = BT + (size_t)(n0 + ldRow) * Kd + ldCol;
    const uint32_t ldOffA = (uint32_t)(ldRow * HS + ldCol) * 2;
    const uint32_t ldOffB = ldOffA + STAGE_BYTES;

    float c[4][4][4];
    #pragma unroll
    for (int mt = 0; mt < 4; mt++)
        #pragma unroll
        for (int nt = 0; nt < 4; nt++)
            #pragma unroll
            for (int i = 0; i < 4; i++) c[mt][nt][i] = 0.0f;

    const int a_row = warp_m + (lane & 7) + ((lane >> 3) & 1) * 8;
    const int a_k   = (lane >> 4) * 8;
    const int b_row = warp_n + (lane & 7) + ((lane >> 4) & 1) * 8;
    const int b_k   = ((lane >> 3) & 1) * 8;
    const uint32_t aAddr0 = sm_base + (uint32_t)(a_row * HS + a_k) * 2;
    const uint32_t bAddr0 = sm_base + STAGE_BYTES + (uint32_t)(b_row * HS + b_k) * 2;

    const int KT = Kd >> 5;

    #pragma unroll
    for (int p = 0; p < 3; p++) {
        if (p < KT) {
            uint32_t sbase = (uint32_t)p * (2 * STAGE_BYTES);
            const __half* Ap = Ag + p * 32;
            const __half* Bp = Bg + p * 32;
            cp_async16(sm_base + sbase + ldOffA,      Ap);
            cp_async16(sm_base + sbase + ldOffA + 16, Ap + 8);
            cp_async16(sm_base + sbase + ldOffB,      Bp);
            cp_async16(sm_base + sbase + ldOffB + 16, Bp + 8);
        }
        cp_commit();
    }

    for (int kt = 0; kt < KT; kt++) {
        if (kt + 3 <= KT - 1)      cp_wait<2>();
        else if (kt + 2 <= KT - 1) cp_wait<1>();
        else                       cp_wait<0>();
        __syncthreads();

        if (kt + 3 < KT) {
            uint32_t sbase = (uint32_t)((kt + 3) & 3) * (2 * STAGE_BYTES);
            const __half* Ap = Ag + (kt + 3) * 32;
            const __half* Bp = Bg + (kt + 3) * 32;
            cp_async16(sm_base + sbase + ldOffA,      Ap);
            cp_async16(sm_base + sbase + ldOffA + 16, Ap + 8);
            cp_async16(sm_base + sbase + ldOffB,      Bp);
            cp_async16(sm_base + sbase + ldOffB + 16, Bp + 8);
            cp_commit();
        } else {
            cp_commit();
        }

        const uint32_t bo = (uint32_t)(kt & 3) * (2 * STAGE_BYTES);
        #pragma unroll
        for (int ks = 0; ks < 2; ks++) {
            uint32_t af[4][4];
            uint32_t bf[2][4];
            #pragma unroll
            for (int mt = 0; mt < 4; mt++)
                ldsm_x4(af[mt], aAddr0 + bo + (uint32_t)(mt * 16 * HS + ks * 16) * 2);
            #pragma unroll
            for (int ntp = 0; ntp < 2; ntp++)
                ldsm_x4(bf[ntp], bAddr0 + bo + (uint32_t)(ntp * 16 * HS + ks * 16) * 2);
            #pragma unroll
            for (int mt = 0; mt < 4; mt++) {
                #pragma unroll
                for (int nt = 0; nt < 4; nt++) {
                    uint32_t b0 = (nt & 1) ? bf[nt >> 1][2] : bf[nt >> 1][0];
                    uint32_t b1 = (nt & 1) ? bf[nt >> 1][3] : bf[nt >> 1][1];
                    mma_f16(c[mt][nt], af[mt], b0, b1);
                }
            }
        }
    }

    const int fr = lane >> 2;
    const int fc = lane & 3;
    #pragma unroll
    for (int mt = 0; mt < 4; mt++) {
        #pragma unroll
        for (int nt = 0; nt < 4; nt++) {
            int row0 = m0 + warp_m + mt * 16 + fr;
            int col  = n0 + warp_n + nt * 8 + fc * 2;
            float v0 = c[mt][nt][0], v1 = c[mt][nt][1];
            float v2 = c[mt][nt][2], v3 = c[mt][nt][3];
            if (MODE == 1 || MODE == 2) {
                float2 bv = *reinterpret_cast<const float2*>(bias + col);
                v0 += bv.x; v1 += bv.y; v2 += bv.x; v3 += bv.y;
            }
            if (MODE == 1) {
                v0 = gelu_exact(v0); v1 = gelu_exact(v1);
                v2 = gelu_exact(v2); v3 = gelu_exact(v3);
            }
            if (MODE == 2) {   // half resid
                const __half* rh = reinterpret_cast<const __half*>(resid);
                float2 f0 = __half22float2(*reinterpret_cast<const __half2*>(rh + (size_t)row0 * N + col));
                float2 f1 = __half22float2(*reinterpret_cast<const __half2*>(rh + (size_t)(row0 + 8) * N + col));
                v0 += f0.x; v1 += f0.y; v2 += f1.x; v3 += f1.y;
            }
            if (MODE == 3) {   // fp32 resid
                const float* rf = reinterpret_cast<const float*>(resid);
                float2 r0 = *reinterpret_cast<const float2*>(rf + (size_t)row0 * N + col);
                float2 r1 = *reinterpret_cast<const float2*>(rf + (size_t)(row0 + 8) * N + col);
                v0 += r0.x; v1 += r0.y; v2 += r1.x; v3 += r1.y;
            }
            if (MODE == 1 || MODE == 3 || MODE == 4) {
                __half* Ch = reinterpret_cast<__half*>(Cout);
                __half2 h0 = __floats2half2_rn(v0, v1);
                __half2 h1 = __floats2half2_rn(v2, v3);
                *reinterpret_cast<__half2*>(Ch + (size_t)row0 * N + col)       = h0;
                *reinterpret_cast<__half2*>(Ch + (size_t)(row0 + 8) * N + col) = h1;
            } else {
                float* Cf = reinterpret_cast<float*>(Cout);
                *reinterpret_cast<float2*>(Cf + (size_t)row0 * N + col)       = make_float2(v0, v1);
                *reinterpret_cast<float2*>(Cf + (size_t)(row0 + 8) * N + col) = make_float2(v2, v3);
            }
        }
    }
}

// ---------------- qtilde via tensor cores ----------------
__global__ __launch_bounds__(256)
void qtilde_tc(const __half* __restrict__ Q, const __half* __restrict__ Wkh,
               __half* __restrict__ qt) {
    __shared__ __half As[128][HS];
    __shared__ __half Bs[128][HS];

    const int tid  = threadIdx.x;
    const int lane = tid & 31;
    const int wid  = tid >> 5;
    const int m0   = blockIdx.x * 128;
    const int head = blockIdx.y >> 1;
    const int n0   = (blockIdx.y & 1) * 128;
    const int warp_m = (wid & 1) * 64;
    const int warp_n = (wid >> 1) * 32;

    const int ldRow = tid >> 1;
    const int ldCol = (tid & 1) * 16;
    {
        const __half* Ag = Q   + (size_t)(m0 + ldRow) * 256 + head * 32 + ldCol;
        const __half* Bg = Wkh + (size_t)(n0 + ldRow) * 256 + head * 32 + ldCol;
        *reinterpret_cast<uint4*>(&As[ldRow][ldCol])     = *reinterpret_cast<const uint4*>(Ag);
        *reinterpret_cast<uint4*>(&As[ldRow][ldCol + 8]) = *reinterpret_cast<const uint4*>(Ag + 8);
        *reinterpret_cast<uint4*>(&Bs[ldRow][ldCol])     = *reinterpret_cast<const uint4*>(Bg);
        *reinterpret_cast<uint4*>(&Bs[ldRow][ldCol + 8]) = *reinterpret_cast<const uint4*>(Bg + 8);
    }
    __syncthreads();

    float c[4][4][4];
    #pragma unroll
    for (int mt = 0; mt < 4; mt++)
        #pragma unroll
        for (int nt = 0; nt < 4; nt++)
            #pragma unroll
            for (int i = 0; i < 4; i++) c[mt][nt][i] = 0.0f;

    const uint32_t as_base = smem_u32(&As[0][0]);
    const uint32_t bs_base = smem_u32(&Bs[0][0]);
    const int a_row = warp_m + (lane & 7) + ((lane >> 3) & 1) * 8;
    const int a_k   = (lane >> 4) * 8;
    const int b_row = warp_n + (lane & 7) + ((lane >> 4) & 1) * 8;
    const int b_k   = ((lane >> 3) & 1) * 8;
    const uint32_t aAddr0 = as_base + (uint32_t)(a_row * HS + a_k) * 2;
    const uint32_t bAddr0 = bs_base + (uint32_t)(b_row * HS + b_k) * 2;

    #pragma unroll
    for (int ks = 0; ks < 2; ks++) {
        uint32_t af[4][4];
        uint32_t bf[2][4];
        #pragma unroll
        for (int mt = 0; mt < 4; mt++)
            ldsm_x4(af[mt], aAddr0 + (uint32_t)(mt * 16 * HS + ks * 16) * 2);
        #pragma unroll
        for (int ntp = 0; ntp < 2; ntp++)
            ldsm_x4(bf[ntp], bAddr0 + (uint32_t)(ntp * 16 * HS + ks * 16) * 2);
        #pragma unroll
        for (int mt = 0; mt < 4; mt++) {
            #pragma unroll
            for (int nt = 0; nt < 4; nt++) {
                uint32_t b0 = (nt & 1) ? bf[nt >> 1][2] : bf[nt >> 1][0];
                uint32_t b1 = (nt & 1) ? bf[nt >> 1][3] : bf[nt >> 1][1];
                mma_f16(c[mt][nt], af[mt], b0, b1);
            }
        }
    }

    const int fr = lane >> 2;
    const int fc = lane & 3;
    #pragma unroll
    for (int mt = 0; mt < 4; mt++) {
        #pragma unroll
        for (int nt = 0; nt < 4; nt++) {
            int row0 = m0 + warp_m + mt * 16 + fr;
            int col  = head * 256 + n0 + warp_n + nt * 8 + fc * 2;
            __half2 h0 = __floats2half2_rn(c[mt][nt][0], c[mt][nt][1]);
            __half2 h1 = __floats2half2_rn(c[mt][nt][2], c[mt][nt][3]);
            *reinterpret_cast<__half2*>(qt + (size_t)row0 * 2048 + col)       = h0;
            *reinterpret_cast<__half2*>(qt + (size_t)(row0 + 8) * 2048 + col) = h1;
        }
    }
}

// ---------------- attention core v8: 8 anchors per CTA, register prefetch ----------------
#define XS_S 264
#define QS_S 264
#define AT_S 40
#define CT_S 264
#define ANC  8
__global__ __launch_bounds__(256)
void attn_kernel(const float* __restrict__ xnei, const __half* __restrict__ qt,
                 __half* __restrict__ ctx) {
    __shared__ __half xs[32 * XS_S];
    __shared__ __half qts[8 * QS_S];
    __shared__ float  sred[8 * 256];
    __shared__ __half attns_h[8 * AT_S];
    __shared__ __half ctx_t[8 * CT_S];
    int b0   = blockIdx.x * ANC;
    int tid  = threadIdx.x;
    int lane = tid & 31;
    int w    = tid >> 5;

    const uint32_t xs_base = smem_u32(xs);
    const uint32_t qs_base = smem_u32(qts);
    const uint32_t at_base = smem_u32(attns_h);
    const int fr = lane >> 2;
    const int fc = lane & 3;

    // register-prefetch buffers for anchor a
    float4 xv[8];
    uint4  qv;

    // prefetch anchor 0
    {
        const float4* xb4 = reinterpret_cast<const float4*>(xnei + (size_t)b0 * 8192);
        #pragma unroll
        for (int j = 0; j < 8; j++) xv[j] = xb4[tid + j * 256];
        qv = reinterpret_cast<const uint4*>(qt + (size_t)b0 * 2048)[tid];
    }

    for (int a = 0; a < ANC; a++) {
        int b = b0 + a;

        // stage prefetched x (fp32 regs -> half smem) and qt
        #pragma unroll
        for (int j = 0; j < 8; j++) {
            int i  = tid + j * 256;
            int k  = i >> 6;
            int c4 = i & 63;
            __half2 h0 = __floats2half2_rn(xv[j].x, xv[j].y);
            __half2 h1 = __floats2half2_rn(xv[j].z, xv[j].w);
            uint2 u;
            u.x = *reinterpret_cast<uint32_t*>(&h0);
            u.y = *reinterpret_cast<uint32_t*>(&h1);
            *reinterpret_cast<uint2*>(xs + k * XS_S + c4 * 4) = u;
        }
        {
            int h  = tid >> 5;
            int c8 = tid & 31;
            *reinterpret_cast<uint4*>(qts + h * QS_S + c8 * 8) = qv;
        }
        __syncthreads();

        // prefetch next anchor (latency hidden behind compute below)
        if (a + 1 < ANC) {
            const float4* xb4 = reinterpret_cast<const float4*>(xnei + (size_t)(b + 1) * 8192);
            #pragma unroll
            for (int j = 0; j < 8; j++) xv[j] = xb4[tid + j * 256];
            qv = reinterpret_cast<const uint4*>(qt + (size_t)(b + 1) * 2048)[tid];
        }

        // ---- phase 1: scores partials ----
        {
            float sacc[2][4];
            #pragma unroll
            for (int mt = 0; mt < 2; mt++)
                #pragma unroll
                for (int i = 0; i < 4; i++) sacc[mt][i] = 0.0f;
            const int a_row = (lane & 7) + ((lane >> 3) & 1) * 8;
            const int a_kof = (lane >> 4) * 8;
            const int b_row = lane & 7;
            const int b_kof = ((lane >> 3) & 1) * 8;
            #pragma unroll
            for (int ks = 0; ks < 2; ks++) {
                uint32_t bq[2];
                ldsm_x2(bq, qs_base + (uint32_t)(b_row * QS_S + w * 32 + ks * 16 + b_kof) * 2);
                #pragma unroll
                for (int mt = 0; mt < 2; mt++) {
                    uint32_t af[4];
                    ldsm_x4(af, xs_base + (uint32_t)((mt * 16 + a_row) * XS_S + w * 32 + ks * 16 + a_kof) * 2);
                    mma_f16(sacc[mt], af, bq[0], bq[1]);
                }
            }
            #pragma unroll
            for (int mt = 0; mt < 2; mt++) {
                int krow = mt * 16 + fr;
                *reinterpret_cast<float2*>(&sred[w * 256 + krow * 8 + fc * 2]) =
                    make_float2(sacc[mt][0], sacc[mt][1]);
                *reinterpret_cast<float2*>(&sred[w * 256 + (krow + 8) * 8 + fc * 2]) =
                    make_float2(sacc[mt][2], sacc[mt][3]);
            }
        }
        __syncthreads();

        // ---- softmax: warp w = head, lane = k ----
        {
            float sc = 0.0f;
            #pragma unroll
            for (int ww = 0; ww < 8; ww++)
                sc += sred[ww * 256 + lane * 8 + w];
            sc *= 0.17677669529663687f;
            float m = sc;
            #pragma unroll
            for (int o = 16; o; o >>= 1) m = fmaxf(m, __shfl_xor_sync(0xFFFFFFFFu, m, o));
            float e = expf(sc - m);
            float s = e;
            #pragma unroll
            for (int o = 16; o; o >>= 1) s += __shfl_xor_sync(0xFFFFFFFFu, s, o);
            attns_h[w * AT_S + lane] = __float2half_rn(e / s);
        }
        __syncthreads();

        // ---- phase 2: ctx^T ----
        {
            float cacc[2][4];
            #pragma unroll
            for (int mt = 0; mt < 2; mt++)
                #pragma unroll
                for (int i = 0; i < 4; i++) cacc[mt][i] = 0.0f;
            const int t_krow = ((lane >> 4) & 1) * 8 + (lane & 7);
            const int t_dof  = ((lane >> 3) & 1) * 8;
            const int b_row = lane & 7;
            const int b_kof = ((lane >> 3) & 1) * 8;
            #pragma unroll
            for (int ks = 0; ks < 2; ks++) {
                uint32_t bp[2];
                ldsm_x2(bp, at_base + (uint32_t)(b_row * AT_S + ks * 16 + b_kof) * 2);
                #pragma unroll
                for (int mt = 0; mt < 2; mt++) {
                    int d0 = w * 32 + mt * 16;
                    uint32_t af[4];
                    ldsm_x4_trans(af, xs_base + (uint32_t)((ks * 16 + t_krow) * XS_S + d0 + t_dof) * 2);
                    mma_f16(cacc[mt], af, bp[0], bp[1]);
                }
            }
            #pragma unroll
            for (int mt = 0; mt < 2; mt++) {
                int d0 = w * 32 + mt * 16;
                ctx_t[(fc * 2 + 0) * CT_S + d0 + fr]     = __float2half_rn(cacc[mt][0]);
                ctx_t[(fc * 2 + 1) * CT_S + d0 + fr]     = __float2half_rn(cacc[mt][1]);
                ctx_t[(fc * 2 + 0) * CT_S + d0 + fr + 8] = __float2half_rn(cacc[mt][2]);
                ctx_t[(fc * 2 + 1) * CT_S + d0 + fr + 8] = __float2half_rn(cacc[mt][3]);
            }
        }
        __syncthreads();

        // coalesced writeout
        {
            uint4 u = *reinterpret_cast<const uint4*>(&ctx_t[w * CT_S + lane * 8]);
            *reinterpret_cast<uint4*>(&ctx[(size_t)b * 2048 + w * 256 + lane * 8]) = u;
        }
        __syncthreads();   // ctx_t read done before next anchor's ph2 rewrites it
    }
}

// ---------------- vproj via tensor cores: 4-stage cp.async pipeline ----------------
#define VST_A (128 * HS * 2)     // 10240
#define VST_B (32 * HS * 2)      // 2560
#define VSTAGE (VST_A + VST_B)
#define VPROJ_SMEM (4 * VSTAGE)  // 51200
__global__ __launch_bounds__(256)
void vproj_tc(const __half* __restrict__ ctx, const __half* __restrict__ WvT,
              __half* __restrict__ out) {
    extern __shared__ __half vsm[];
    const uint32_t sm_base = smem_u32(vsm);
    const int tid  = threadIdx.x;
    const int lane = tid & 31;
    const int wid  = tid >> 5;
    const int m0 = blockIdx.x * 128;
    const int h  = blockIdx.y;

    const int aRow = tid >> 1;
    const int aCol = (tid & 1) * 16;
    const __half* Ag = ctx + (size_t)(m0 + aRow) * 2048 + h * 256 + aCol;
    const uint32_t ldOffA = (uint32_t)(aRow * HS + aCol) * 2;
    const __half* Bg = WvT + (size_t)(h * 32 + (tid >> 1)) * 256 + aCol;   // valid for tid<64
    const uint32_t ldOffB = VST_A + (uint32_t)((tid >> 1) * HS + aCol) * 2;

    float c[4][4];
    #pragma unroll
    for (int nt = 0; nt < 4; nt++)
        #pragma unroll
        for (int i = 0; i < 4; i++) c[nt][i] = 0.0f;

    const int a_row = wid * 16 + (lane & 7) + ((lane >> 3) & 1) * 8;
    const int a_k   = (lane >> 4) * 8;
    const int b_row = (lane & 7) + ((lane >> 4) & 1) * 8;
    const int b_k   = ((lane >> 3) & 1) * 8;

    const int KT = 8;   // 256 / 32
    #pragma unroll
    for (int p = 0; p < 3; p++) {
        uint32_t sbase = (uint32_t)p * VSTAGE;
        cp_async16(sm_base + sbase + ldOffA,      Ag + p * 32);
        cp_async16(sm_base + sbase + ldOffA + 16, Ag + p * 32 + 8);
        if (tid < 64) {
            cp_async16(sm_base + sbase + ldOffB,      Bg + p * 32);
            cp_async16(sm_base + sbase + ldOffB + 16, Bg + p * 32 + 8);
        }
        cp_commit();
    }

    for (int kt = 0; kt < KT; kt++) {
        if (kt + 3 <= KT - 1)      cp_wait<2>();
        else if (kt + 2 <= KT - 1) cp_wait<1>();
        else                       cp_wait<0>();
        __syncthreads();

        if (kt + 3 < KT) {
            uint32_t sbase = (uint32_t)((kt + 3) & 3) * VSTAGE;
            cp_async16(sm_base + sbase + ldOffA,      Ag + (kt + 3) * 32);
            cp_async16(sm_base + sbase + ldOffA + 16, Ag + (kt + 3) * 32 + 8);
            if (tid < 64) {
                cp_async16(sm_base + sbase + ldOffB,      Bg + (kt + 3) * 32);
                cp_async16(sm_base + sbase + ldOffB + 16, Bg + (kt + 3) * 32 + 8);
            }
            cp_commit();
        } else {
            cp_commit();
        }

        const uint32_t sb = sm_base + (uint32_t)(kt & 3) * VSTAGE;
        #pragma unroll
        for (int ks = 0; ks < 2; ks++) {
            uint32_t af[4];
            uint32_t bf[2][4];
            ldsm_x4(af, sb + (uint32_t)(a_row * HS + ks * 16 + a_k) * 2);
            #pragma unroll
            for (int ntp = 0; ntp < 2; ntp++)
                ldsm_x4(bf[ntp], sb + VST_A + (uint32_t)((ntp * 16 + b_row) * HS + ks * 16 + b_k) * 2);
            #pragma unroll
            for (int nt = 0; nt < 4; nt++) {
                uint32_t b0 = (nt & 1) ? bf[nt >> 1][2] : bf[nt >> 1][0];
                uint32_t b1 = (nt & 1) ? bf[nt >> 1][3] : bf[nt >> 1][1];
                mma_f16(c[nt], af, b0, b1);
            }
        }
    }

    const int fr = lane >> 2;
    const int fc = lane & 3;
    #pragma unroll
    for (int nt = 0; nt < 4; nt++) {
        int row0 = m0 + wid * 16 + fr;
        int col  = h * 32 + nt * 8 + fc * 2;
        __half2 h0 = __floats2half2_rn(c[nt][0], c[nt][1]);
        __half2 h1 = __floats2half2_rn(c[nt][2], c[nt][3]);
        *reinterpret_cast<__half2*>(out + (size_t)row0 * 256 + col)       = h0;
        *reinterpret_cast<__half2*>(out + (size_t)(row0 + 8) * 256 + col) = h1;
    }
}

// ---------------- launcher ----------------
extern "C" void kernel_launch(void* const* d_in, const int* in_sizes, int n_in,
                              void* d_out, int out_size) {
    const float* x_anc = (const float*)d_in[0];
    const float* x_nei = (const float*)d_in[1];
    const float* W_q   = (const float*)d_in[2];
    const float* W_k   = (const float*)d_in[3];
    const float* W_v   = (const float*)d_in[4];
    const float* W_o   = (const float*)d_in[5];
    const float* ln1_g = (const float*)d_in[6];
    const float* ln1_b = (const float*)d_in[7];
    const float* ln2_g = (const float*)d_in[8];
    const float* ln2_b = (const float*)d_in[9];
    const float* ff1_w = (const float*)d_in[10];
    const float* ff1_b = (const float*)d_in[11];
    const float* ff2_w = (const float*)d_in[12];
    const float* ff2_b = (const float*)d_in[13];
    float* out = (float*)d_out;

    __half *p_lnx, *p_qh, *p_qt, *p_ctx, *p_att, *p_xh, *p_h, *p_ff;
    __half *p_wkh, *p_wtq, *p_wto, *p_wtv, *p_wt1, *p_wt2;
    cudaGetSymbolAddress((void**)&p_lnx, g_lnx);
    cudaGetSymbolAddress((void**)&p_qh,  g_qh);
    cudaGetSymbolAddress((void**)&p_qt,  g_qt);
    cudaGetSymbolAddress((void**)&p_ctx, g_ctx);
    cudaGetSymbolAddress((void**)&p_att, g_att);
    cudaGetSymbolAddress((void**)&p_xh,  g_xh);
    cudaGetSymbolAddress((void**)&p_h,   g_h);
    cudaGetSymbolAddress((void**)&p_ff,  g_ff);
    cudaGetSymbolAddress((void**)&p_wkh, g_wkh);
    cudaGetSymbolAddress((void**)&p_wtq, g_wtq);
    cudaGetSymbolAddress((void**)&p_wto, g_wto);
    cudaGetSymbolAddress((void**)&p_wtv, g_wtv);
    cudaGetSymbolAddress((void**)&p_wt1, g_wt1);
    cudaGetSymbolAddress((void**)&p_wt2, g_wt2);

    cudaFuncSetAttribute(hgemm<1>, cudaFuncAttributeMaxDynamicSharedMemorySize, HGEMM_SMEM);
    cudaFuncSetAttribute(hgemm<2>, cudaFuncAttributeMaxDynamicSharedMemorySize, HGEMM_SMEM);
    cudaFuncSetAttribute(hgemm<3>, cudaFuncAttributeMaxDynamicSharedMemorySize, HGEMM_SMEM);
    cudaFuncSetAttribute(hgemm<4>, cudaFuncAttributeMaxDynamicSharedMemorySize, HGEMM_SMEM);
    cudaFuncSetAttribute(vproj_tc, cudaFuncAttributeMaxDynamicSharedMemorySize, VPROJ_SMEM);

    dim3 lnBlock(32, 8);
    dim3 tBlock(32, 8);

    // 0: weight prep (Wq^T, Wo^T, Wv^T, Wk->half) in one launch
    wprep_kernel<<<dim3(8, 8, 4), tBlock>>>(W_q, W_o, W_v, W_k, p_wtq, p_wto, p_wtv, p_wkh);
    // 1: transpose ff1 (independent; overlaps with LN1)
    transpose_kernel<<<dim3(32, 8), tBlock>>>(ff1_w, p_wt1, 256, 1024);
    // 2: LN1 -> half
    ln_kernel<<<BN / 8, lnBlock>>>(x_anc, ln1_g, ln1_b, p_lnx);
    // 3: Q = LN1 @ W_q (half out)  [PROFILED SLOT]
    hgemm<4><<<dim3(2, BN / 128), 256, HGEMM_SMEM>>>(p_lnx, p_wtq, p_qh, BN, DIM, DIM, nullptr, nullptr);
    // 4: q~ via tensor cores
    qtilde_tc<<<dim3(BN / 128, 16), 256>>>(p_qh, p_wkh, p_qt);
    // 5: attention core (8 anchors/CTA) -> ctx (half)
    attn_kernel<<<BN / ANC, 256>>>(x_nei, p_qt, p_ctx);
    // 6: att = ctx @ W_v (tensor cores, per head)
    vproj_tc<<<dim3(BN / 128, NH), 256, VPROJ_SMEM>>>(p_ctx, p_wtv, p_att);
    // 7: x = x_anc + att @ W_o (half out)
    hgemm<3><<<dim3(2, BN / 128), 256, HGEMM_SMEM>>>(p_att, p_wto, p_xh, BN, DIM, DIM, nullptr, x_anc);
    // 8: LN2 (half in) -> half
    ln_half_kernel<<<BN / 8, lnBlock>>>(p_xh, ln2_g, ln2_b, p_h);
    // 9: transpose ff2
    transpose_kernel<<<dim3(8, 32), tBlock>>>(ff2_w, p_wt2, 1024, 256);
    // 10: ff = gelu(h @ ff1 + b1)
    hgemm<1><<<dim3(8, BN / 128), 256, HGEMM_SMEM>>>(p_h, p_wt1, p_ff, BN, NFF, DIM, ff1_b, nullptr);
    // 11: out = x + ff @ ff2 + b2 (half resid, f32 out)
    hgemm<2><<<dim3(2, BN / 128), 256, HGEMM_SMEM>>>(p_ff, p_wt2, out, BN, DIM, NFF, ff2_b, p_xh);
}